// round 5
// baseline (speedup 1.0000x reference)
#include <cuda_runtime.h>
#include <math.h>

#define Bv    2
#define Lv    1024
#define Hv    768
#define NHv   12
#define NEv   24
#define Mv    3
#define NCv   2
#define CWv   8
#define BLK   64
#define NCLSv 97
#define KB    12              /* H / BLK */
#define NPAIR (NEv*NEv)       /* 576 */
#define ROWS  (Bv*NPAIR)      /* 1152 */
#define WCN   (Hv*BLK)        /* 49152 */

// ---------------- scratch (static device memory; no allocations) -------------
__device__ float g_eatt[Bv*NEv*NHv*Lv];
__device__ float g_gate[Bv*NEv*Lv];
__device__ float g_eemb[Bv*NEv*Hv];
__device__ float g_ht[(size_t)Bv*NPAIR*Lv];
__device__ float g_rs[(size_t)ROWS*Hv];
__device__ float g_uh[Bv*NEv*Hv];
__device__ float g_ut[Bv*NEv*Hv];
__device__ float g_vh[(size_t)ROWS*Hv];
__device__ float g_vt[(size_t)ROWS*Hv];
__device__ float g_zh[(size_t)ROWS*Hv];
__device__ float g_zt[(size_t)ROWS*Hv];
__device__ float g_wc[(size_t)NCLSv*WCN];
__device__ float g_lpart[2*(size_t)ROWS*NCLSv];

// ---------------- K1: e_att[b,e,h,l] = mean_m attention[b,h,p_m,l] -----------
__global__ void k_eatt(const float* __restrict__ att, const int* __restrict__ ms)
{
    int bh = blockIdx.x;            // (b*NE + e)*NH + h
    int h  = bh % NHv;
    int be = bh / NHv;
    int b  = be / NEv;
    int p0 = ms[be*Mv + 0] + 1;
    int p1 = ms[be*Mv + 1] + 1;
    int p2 = ms[be*Mv + 2] + 1;
    const float* base = att + (size_t)(b*NHv + h)*Lv*Lv;
    const float* a0 = base + (size_t)p0*Lv;
    const float* a1 = base + (size_t)p1*Lv;
    const float* a2 = base + (size_t)p2*Lv;
    float* o = g_eatt + (size_t)(be*NHv + h)*Lv;
    for (int l = threadIdx.x; l < Lv; l += blockDim.x)
        o[l] = (a0[l] + a1[l] + a2[l]) * (1.0f/3.0f);
}

// ---------------- K2: gate[b,e,l] = (sum_h e_att) / sum_l ---------------------
__global__ void k_gate()
{
    int be = blockIdx.x;
    __shared__ float s[Lv];
    __shared__ float red[256];
    float part = 0.f;
    for (int l = threadIdx.x; l < Lv; l += 256) {
        float v = 0.f;
        #pragma unroll
        for (int h = 0; h < NHv; h++)
            v += g_eatt[((size_t)(be*NHv + h))*Lv + l];
        s[l] = v;
        part += v;
    }
    red[threadIdx.x] = part;
    __syncthreads();
    for (int st = 128; st > 0; st >>= 1) {
        if (threadIdx.x < st) red[threadIdx.x] += red[threadIdx.x + st];
        __syncthreads();
    }
    float inv = 1.0f / red[0];
    for (int l = threadIdx.x; l < Lv; l += 256)
        g_gate[be*Lv + l] = s[l] * inv;
}

// ---------------- K3: e_emb = logsumexp(mentions + coref) --------------------
__global__ void k_eemb(const float* __restrict__ seq, const int* __restrict__ ms,
                       const int* __restrict__ cs)
{
    int be = blockIdx.x;
    int b  = be / NEv;
    int d  = threadIdx.x;   // 768
    __shared__ int   sp[Mv];
    __shared__ int   scs[NCv];
    __shared__ float sg[NCv][CWv];
    if (threadIdx.x < Mv)  sp[threadIdx.x]  = ms[be*Mv + threadIdx.x] + 1;
    if (threadIdx.x < NCv) scs[threadIdx.x] = cs[be*NCv + threadIdx.x];
    __syncthreads();
    if (threadIdx.x < NCv*CWv) {
        int c = threadIdx.x / CWv, w = threadIdx.x % CWv;
        sg[c][w] = g_gate[be*Lv + scs[c] + w];
    }
    __syncthreads();

    float x[Mv + NCv];
    #pragma unroll
    for (int m = 0; m < Mv; m++)
        x[m] = seq[((size_t)b*Lv + sp[m])*Hv + d];
    #pragma unroll
    for (int c = 0; c < NCv; c++) {
        float acc = 0.f;
        int basel = scs[c];
        #pragma unroll
        for (int w = 0; w < CWv; w++)
            acc += sg[c][w] * seq[((size_t)b*Lv + basel + w)*Hv + d];
        x[Mv + c] = acc;
    }
    float mx = x[0];
    #pragma unroll
    for (int i = 1; i < Mv + NCv; i++) mx = fmaxf(mx, x[i]);
    float ssum = 0.f;
    #pragma unroll
    for (int i = 0; i < Mv + NCv; i++) ssum += expf(x[i] - mx);
    g_eemb[be*Hv + d] = mx + logf(ssum);
}

// ---------------- K4: ht[b,e,f,l] (normalized relu inner prod over heads) ----
__global__ void k_ht()
{
    int ef = blockIdx.x;   // 0..575
    int b  = blockIdx.y;
    int e = ef / NEv, f = ef % NEv;
    __shared__ float s[Lv];
    __shared__ float red[256];
    const float* pe = g_eatt + (size_t)((b*NEv + e)*NHv)*Lv;
    const float* pf = g_eatt + (size_t)((b*NEv + f)*NHv)*Lv;
    float part = 0.f;
    for (int l = threadIdx.x; l < Lv; l += 256) {
        float v = 0.f;
        #pragma unroll
        for (int h = 0; h < NHv; h++)
            v += pe[h*Lv + l] * pf[h*Lv + l];
        v = fmaxf(v, 0.f);
        s[l] = v;
        part += v;
    }
    red[threadIdx.x] = part;
    __syncthreads();
    for (int st = 128; st > 0; st >>= 1) {
        if (threadIdx.x < st) red[threadIdx.x] += red[threadIdx.x + st];
        __syncthreads();
    }
    float inv = 1.0f / (red[0] + 1e-10f);
    float* o = g_ht + ((size_t)b*NPAIR + ef)*Lv;
    for (int l = threadIdx.x; l < Lv; l += 256)
        o[l] = s[l] * inv;
}

// ---------------- generic fp32 tiled GEMM: C = A * B (or A * B^T) -------------
// A: M x K row-major (lda). BT=false: B is K x N (ldb). BT=true: B is N x K (ldb).
// Requires K % 16 == 0 and N % 64 == 0. M guarded.
template<bool BT>
__global__ void __launch_bounds__(256) k_gemm(
    const float* __restrict__ A, const float* __restrict__ Bm, float* __restrict__ C,
    int Mr, int Nc, int Kd, int lda, int ldb, int ldc,
    long long sA, long long sB, long long sC)
{
    A  += (long long)blockIdx.z * sA;
    Bm += (long long)blockIdx.z * sB;
    C  += (long long)blockIdx.z * sC;

    __shared__ __align__(16) float As[16][68];
    __shared__ __align__(16) float Bs[16][68];

    const int tid = threadIdx.x;
    const int tx = tid & 15, ty = tid >> 4;
    const int row0 = blockIdx.y * 64;
    const int col0 = blockIdx.x * 64;

    float acc[4][4] = {};

    const int a_k = tid & 15;     // k within tile
    const int a_r = tid >> 4;     // row base (+16*t)
    const int b_n = tid & 63;     // NN: col
    const int b_k = tid >> 6;     // NN: kk base (+4*t)

    for (int k0 = 0; k0 < Kd; k0 += 16) {
        #pragma unroll
        for (int t = 0; t < 4; t++) {
            int r  = a_r + t*16;
            int gr = row0 + r;
            As[a_k][r] = (gr < Mr) ? A[(long long)gr*lda + (k0 + a_k)] : 0.f;
        }
        if (BT) {
            #pragma unroll
            for (int t = 0; t < 4; t++) {
                int n = a_r + t*16;
                Bs[a_k][n] = Bm[(long long)(col0 + n)*ldb + (k0 + a_k)];
            }
        } else {
            #pragma unroll
            for (int t = 0; t < 4; t++) {
                int kk = b_k + t*4;
                Bs[kk][b_n] = Bm[(long long)(k0 + kk)*ldb + (col0 + b_n)];
            }
        }
        __syncthreads();
        #pragma unroll
        for (int kk = 0; kk < 16; kk++) {
            float4 a4 = *reinterpret_cast<const float4*>(&As[kk][ty*4]);
            float4 b4 = *reinterpret_cast<const float4*>(&Bs[kk][tx*4]);
            acc[0][0] += a4.x*b4.x; acc[0][1] += a4.x*b4.y; acc[0][2] += a4.x*b4.z; acc[0][3] += a4.x*b4.w;
            acc[1][0] += a4.y*b4.x; acc[1][1] += a4.y*b4.y; acc[1][2] += a4.y*b4.z; acc[1][3] += a4.y*b4.w;
            acc[2][0] += a4.z*b4.x; acc[2][1] += a4.z*b4.y; acc[2][2] += a4.z*b4.z; acc[2][3] += a4.z*b4.w;
            acc[3][0] += a4.w*b4.x; acc[3][1] += a4.w*b4.y; acc[3][2] += a4.w*b4.z; acc[3][3] += a4.w*b4.w;
        }
        __syncthreads();
    }

    #pragma unroll
    for (int i = 0; i < 4; i++) {
        int gr = row0 + ty*4 + i;
        if (gr < Mr) {
            #pragma unroll
            for (int j = 0; j < 4; j++)
                C[(long long)gr*ldc + col0 + tx*4 + j] = acc[i][j];
        }
    }
}

// ---------------- K6: zh/zt = tanh(U + V + bias) ------------------------------
__global__ void k_tanh(const float* __restrict__ bh, const float* __restrict__ bt)
{
    int idx = blockIdx.x*256 + threadIdx.x;
    if (idx >= ROWS*Hv) return;
    int d  = idx % Hv;
    int r  = idx / Hv;        // b*576 + e*24 + f
    int f  = r % NEv;
    int be = r / NEv;         // b*24 + e
    int b  = be / NEv;
    g_zh[idx] = tanhf(g_uh[be*Hv + d]          + g_vh[idx] + bh[d]);
    g_zt[idx] = tanhf(g_ut[(b*NEv + f)*Hv + d] + g_vt[idx] + bt[d]);
}

// ---------------- K7: logits partials -----------------------------------------
// logits[r,c] = sum_{k,i,j} zh[r,k*64+i] * zt[r,k*64+j] * Wc[c,(k*64+i)*64+j]
// Block: 16 rows x all 97 classes; K split in 2 halves (grid.y). 128 threads:
// rg = tid>>5 (4 row groups of 4), cg = tid&31 (32 col groups of 4).
__global__ void __launch_bounds__(128) k_logits()
{
    const int row0 = blockIdx.x * 16;
    const int ks   = blockIdx.y;           // 0 or 1  (k in [ks*6, ks*6+6))
    const int tid  = threadIdx.x;
    const int rg   = tid >> 5;
    const int cg   = tid & 31;

    __shared__ __align__(16) float zh_s[64*20];     // [i][row], padded stride 20
    __shared__ __align__(16) float zt_s[64*20];     // [j][row]
    __shared__ __align__(16) float wc_s[64*132];    // [j][c],  padded stride 132

    // zero-fill the c in [97,128) pad region once (never rewritten)
    for (int idx = tid; idx < 64*31; idx += 128) {
        int j = idx / 31, c = 97 + idx % 31;
        wc_s[j*132 + c] = 0.f;
    }

    float acc[4][4] = {};

    for (int k = ks*6; k < ks*6 + 6; k++) {
        __syncthreads();   // protect zh_s/zt_s rewrite
        for (int idx = tid; idx < 16*64; idx += 128) {
            int r = idx >> 6, j = idx & 63;
            zh_s[j*20 + r] = g_zh[(size_t)(row0 + r)*Hv + k*64 + j];
            zt_s[j*20 + r] = g_zt[(size_t)(row0 + r)*Hv + k*64 + j];
        }
        for (int i = 0; i < 64; i++) {
            __syncthreads();   // protect wc_s rewrite (also fences zh/zt stores)
            const float* wbase = g_wc + (size_t)(k*64 + i)*64;
            for (int idx = tid; idx < NCLSv*64; idx += 128) {
                int c = idx >> 6, j = idx & 63;
                wc_s[j*132 + c] = wbase[(size_t)c*WCN + j];
            }
            __syncthreads();
            const float4 a4 = *reinterpret_cast<const float4*>(&zh_s[i*20 + rg*4]);
            #pragma unroll 8
            for (int j = 0; j < 64; j++) {
                float4 z4 = *reinterpret_cast<const float4*>(&zt_s[j*20 + rg*4]);
                float4 w4 = *reinterpret_cast<const float4*>(&wc_s[j*132 + cg*4]);
                float p0 = a4.x * z4.x;
                float p1 = a4.y * z4.y;
                float p2 = a4.z * z4.z;
                float p3 = a4.w * z4.w;
                acc[0][0] += p0*w4.x; acc[0][1] += p0*w4.y; acc[0][2] += p0*w4.z; acc[0][3] += p0*w4.w;
                acc[1][0] += p1*w4.x; acc[1][1] += p1*w4.y; acc[1][2] += p1*w4.z; acc[1][3] += p1*w4.w;
                acc[2][0] += p2*w4.x; acc[2][1] += p2*w4.y; acc[2][2] += p2*w4.z; acc[2][3] += p2*w4.w;
                acc[3][0] += p3*w4.x; acc[3][1] += p3*w4.y; acc[3][2] += p3*w4.z; acc[3][3] += p3*w4.w;
            }
        }
    }

    #pragma unroll
    for (int rr = 0; rr < 4; rr++) {
        int row = row0 + rg*4 + rr;
        #pragma unroll
        for (int cc = 0; cc < 4; cc++) {
            int c = cg*4 + cc;
            if (c < NCLSv)
                g_lpart[((size_t)ks*ROWS + row)*NCLSv + c] = acc[rr][cc];
        }
    }
}

// ---------------- K8: combine partials + bias ----------------------------------
__global__ void k_final(const float* __restrict__ bcls, float* __restrict__ out)
{
    int idx = blockIdx.x*256 + threadIdx.x;
    if (idx >= ROWS*NCLSv) return;
    int c = idx % NCLSv;
    out[idx] = g_lpart[idx] + g_lpart[(size_t)ROWS*NCLSv + idx] + bcls[c];
}

// ================================ launch ========================================
extern "C" void kernel_launch(void* const* d_in, const int* in_sizes, int n_in,
                              void* d_out, int out_size)
{
    const float* seq  = (const float*)d_in[0];
    const float* att  = (const float*)d_in[1];
    const int*   ms   = (const int*)  d_in[2];
    const int*   cs   = (const int*)  d_in[3];
    const float* Wh   = (const float*)d_in[4];
    const float* bh   = (const float*)d_in[5];
    const float* Wt   = (const float*)d_in[6];
    const float* bt   = (const float*)d_in[7];
    const float* Wp   = (const float*)d_in[8];
    const float* Wcls = (const float*)d_in[9];
    const float* bcls = (const float*)d_in[10];
    float* out = (float*)d_out;

    float *p_ht, *p_rs, *p_eemb, *p_uh, *p_ut, *p_vh, *p_vt, *p_wc;
    cudaGetSymbolAddress((void**)&p_ht,   g_ht);
    cudaGetSymbolAddress((void**)&p_rs,   g_rs);
    cudaGetSymbolAddress((void**)&p_eemb, g_eemb);
    cudaGetSymbolAddress((void**)&p_uh,   g_uh);
    cudaGetSymbolAddress((void**)&p_ut,   g_ut);
    cudaGetSymbolAddress((void**)&p_vh,   g_vh);
    cudaGetSymbolAddress((void**)&p_vt,   g_vt);
    cudaGetSymbolAddress((void**)&p_wc,   g_wc);

    // Wc = W_cls @ W_proj  (97 x 49152, K=768) — independent, launch first
    k_gemm<false><<<dim3(WCN/64, (NCLSv + 63)/64, 1), 256>>>(
        Wcls, Wp, p_wc, NCLSv, WCN, Hv, Hv, WCN, WCN, 0, 0, 0);

    k_eatt<<<Bv*NEv*NHv, 256>>>(att, ms);
    k_gate<<<Bv*NEv, 256>>>();
    k_eemb<<<Bv*NEv, Hv>>>(seq, ms, cs);
    k_ht<<<dim3(NPAIR, Bv), 256>>>();

    // rs = ht @ seq  (batched over B)
    k_gemm<false><<<dim3(Hv/64, NPAIR/64, Bv), 256>>>(
        p_ht, seq, p_rs, NPAIR, Hv, Lv, Lv, Hv, Hv,
        (long long)NPAIR*Lv, (long long)Lv*Hv, (long long)NPAIR*Hv);

    // U = e_emb @ W[:, :H]^T   (48 x 768, K=768)
    k_gemm<true><<<dim3(Hv/64, 1, 1), 256>>>(
        p_eemb, Wh, p_uh, Bv*NEv, Hv, Hv, Hv, 2*Hv, Hv, 0, 0, 0);
    k_gemm<true><<<dim3(Hv/64, 1, 1), 256>>>(
        p_eemb, Wt, p_ut, Bv*NEv, Hv, Hv, Hv, 2*Hv, Hv, 0, 0, 0);

    // V = rs @ W[:, H:]^T   (1152 x 768, K=768)
    k_gemm<true><<<dim3(Hv/64, ROWS/64, 1), 256>>>(
        p_rs, Wh + Hv, p_vh, ROWS, Hv, Hv, Hv, 2*Hv, Hv, 0, 0, 0);
    k_gemm<true><<<dim3(Hv/64, ROWS/64, 1), 256>>>(
        p_rs, Wt + Hv, p_vt, ROWS, Hv, Hv, Hv, 2*Hv, Hv, 0, 0, 0);

    k_tanh<<<(ROWS*Hv + 255)/256, 256>>>(bh, bt);

    k_logits<<<dim3(ROWS/16, 2), 128>>>();

    k_final<<<(ROWS*NCLSv + 255)/256, 256>>>(bcls, out);
}

// round 6
// speedup vs baseline: 3.9791x; 3.9791x over previous
#include <cuda_runtime.h>
#include <math.h>

#define Bv    2
#define Lv    1024
#define Hv    768
#define NHv   12
#define NEv   24
#define Mv    3
#define NCv   2
#define CWv   8
#define BLK   64
#define NCLSv 97
#define NPAIR (NEv*NEv)       /* 576 */
#define ROWS  (Bv*NPAIR)      /* 1152 */
#define WCN   (Hv*BLK)        /* 49152 */
#define LROWS 32

// ---------------- scratch (static device memory; no allocations) -------------
__device__ float g_eatt[Bv*NEv*NHv*Lv];
__device__ float g_gate[Bv*NEv*Lv];
__device__ float g_eemb[Bv*NEv*Hv];
__device__ float g_ht[(size_t)Bv*NPAIR*Lv];
__device__ float g_rs[(size_t)ROWS*Hv];
__device__ float g_uh[Bv*NEv*Hv];
__device__ float g_ut[Bv*NEv*Hv];
__device__ float g_vh[(size_t)ROWS*Hv];
__device__ float g_vt[(size_t)ROWS*Hv];
__device__ float g_zh[(size_t)ROWS*Hv];
__device__ float g_zt[(size_t)ROWS*Hv];
__device__ float g_wc[(size_t)NCLSv*WCN];
__device__ float g_lpart[12*(size_t)ROWS*NCLSv];

// ---------------- K1: e_att[b,e,h,l] = mean_m attention[b,h,p_m,l] -----------
__global__ void k_eatt(const float* __restrict__ att, const int* __restrict__ ms)
{
    int bh = blockIdx.x;
    int h  = bh % NHv;
    int be = bh / NHv;
    int b  = be / NEv;
    int p0 = ms[be*Mv + 0] + 1;
    int p1 = ms[be*Mv + 1] + 1;
    int p2 = ms[be*Mv + 2] + 1;
    const float* base = att + (size_t)(b*NHv + h)*Lv*Lv;
    const float* a0 = base + (size_t)p0*Lv;
    const float* a1 = base + (size_t)p1*Lv;
    const float* a2 = base + (size_t)p2*Lv;
    float* o = g_eatt + (size_t)(be*NHv + h)*Lv;
    for (int l = threadIdx.x; l < Lv; l += blockDim.x)
        o[l] = (a0[l] + a1[l] + a2[l]) * (1.0f/3.0f);
}

// ---------------- K2: gate[b,e,l] = (sum_h e_att) / sum_l ---------------------
__global__ void k_gate()
{
    int be = blockIdx.x;
    __shared__ float s[Lv];
    __shared__ float red[256];
    float part = 0.f;
    for (int l = threadIdx.x; l < Lv; l += 256) {
        float v = 0.f;
        #pragma unroll
        for (int h = 0; h < NHv; h++)
            v += g_eatt[((size_t)(be*NHv + h))*Lv + l];
        s[l] = v;
        part += v;
    }
    red[threadIdx.x] = part;
    __syncthreads();
    for (int st = 128; st > 0; st >>= 1) {
        if (threadIdx.x < st) red[threadIdx.x] += red[threadIdx.x + st];
        __syncthreads();
    }
    float inv = 1.0f / red[0];
    for (int l = threadIdx.x; l < Lv; l += 256)
        g_gate[be*Lv + l] = s[l] * inv;
}

// ---------------- K3: e_emb = logsumexp(mentions + coref) --------------------
__global__ void k_eemb(const float* __restrict__ seq, const int* __restrict__ ms,
                       const int* __restrict__ cs)
{
    int be = blockIdx.x;
    int b  = be / NEv;
    int d  = threadIdx.x;   // 768
    __shared__ int   sp[Mv];
    __shared__ int   scs[NCv];
    __shared__ float sg[NCv][CWv];
    if (threadIdx.x < Mv)  sp[threadIdx.x]  = ms[be*Mv + threadIdx.x] + 1;
    if (threadIdx.x < NCv) scs[threadIdx.x] = cs[be*NCv + threadIdx.x];
    __syncthreads();
    if (threadIdx.x < NCv*CWv) {
        int c = threadIdx.x / CWv, w = threadIdx.x % CWv;
        sg[c][w] = g_gate[be*Lv + scs[c] + w];
    }
    __syncthreads();

    float x[Mv + NCv];
    #pragma unroll
    for (int m = 0; m < Mv; m++)
        x[m] = seq[((size_t)b*Lv + sp[m])*Hv + d];
    #pragma unroll
    for (int c = 0; c < NCv; c++) {
        float acc = 0.f;
        int basel = scs[c];
        #pragma unroll
        for (int w = 0; w < CWv; w++)
            acc += sg[c][w] * seq[((size_t)b*Lv + basel + w)*Hv + d];
        x[Mv + c] = acc;
    }
    float mx = x[0];
    #pragma unroll
    for (int i = 1; i < Mv + NCv; i++) mx = fmaxf(mx, x[i]);
    float ssum = 0.f;
    #pragma unroll
    for (int i = 0; i < Mv + NCv; i++) ssum += expf(x[i] - mx);
    g_eemb[be*Hv + d] = mx + logf(ssum);
}

// ---------------- K4: ht[b,e,f,l] (normalized relu inner prod over heads) ----
__global__ void k_ht()
{
    int ef = blockIdx.x;   // 0..575
    int b  = blockIdx.y;
    int e = ef / NEv, f = ef % NEv;
    __shared__ float s[Lv];
    __shared__ float red[256];
    const float* pe = g_eatt + (size_t)((b*NEv + e)*NHv)*Lv;
    const float* pf = g_eatt + (size_t)((b*NEv + f)*NHv)*Lv;
    float part = 0.f;
    for (int l = threadIdx.x; l < Lv; l += 256) {
        float v = 0.f;
        #pragma unroll
        for (int h = 0; h < NHv; h++)
            v += pe[h*Lv + l] * pf[h*Lv + l];
        v = fmaxf(v, 0.f);
        s[l] = v;
        part += v;
    }
    red[threadIdx.x] = part;
    __syncthreads();
    for (int st = 128; st > 0; st >>= 1) {
        if (threadIdx.x < st) red[threadIdx.x] += red[threadIdx.x + st];
        __syncthreads();
    }
    float inv = 1.0f / (red[0] + 1e-10f);
    float* o = g_ht + ((size_t)b*NPAIR + ef)*Lv;
    for (int l = threadIdx.x; l < Lv; l += 256)
        o[l] = s[l] * inv;
}

// ---------------- generic fp32 tiled GEMM: C = A * B (or A * B^T) -------------
// Tile: TM rows x 64 cols, K-step 16, 256 threads, thread tile RT x 4 (TM = 16*RT*?).
// Register-prefetch pipelining: next K-tile's global loads issued before compute.
// blockIdx.z applies pointer strides (batch OR dual-matrix trick).
template<int TM, int RT, bool BT>
__global__ void __launch_bounds__(256) k_gemm(
    const float* __restrict__ A, const float* __restrict__ Bm, float* __restrict__ C,
    int Mr, int Kd, int lda, int ldb, int ldc,
    long long sA, long long sB, long long sC)
{
    constexpr int APAD = (TM == 128) ? 136 : 20;
    A  += (long long)blockIdx.z * sA;
    Bm += (long long)blockIdx.z * sB;
    C  += (long long)blockIdx.z * sC;

    __shared__ __align__(16) float As[16*APAD];
    __shared__ __align__(16) float Bs[16*68];

    const int tid = threadIdx.x;
    const int tx = tid & 15;        // col group (4 cols)
    const int ty = tid >> 4;        // row group (RT rows)
    const int row0 = blockIdx.y * TM;
    const int col0 = blockIdx.x * 64;

    const int a_k = tid & 15;
    const int a_r = tid >> 4;

    float acc[RT][4] = {};
    float ra[TM/16], rb[4];

    auto loadA = [&](int k0) {
        #pragma unroll
        for (int t = 0; t < TM/16; t++) {
            int gr = row0 + a_r + t*16;
            ra[t] = (gr < Mr) ? A[(long long)gr*lda + (k0 + a_k)] : 0.f;
        }
    };
    auto loadB = [&](int k0) {
        if (BT) {
            #pragma unroll
            for (int t = 0; t < 4; t++)
                rb[t] = Bm[(long long)(col0 + a_r + t*16)*ldb + (k0 + a_k)];
        } else {
            #pragma unroll
            for (int t = 0; t < 4; t++)
                rb[t] = Bm[(long long)(k0 + (tid>>6) + t*4)*ldb + col0 + (tid&63)];
        }
    };
    auto storeAB = [&]() {
        #pragma unroll
        for (int t = 0; t < TM/16; t++)
            As[a_k*APAD + a_r + t*16] = ra[t];
        if (BT) {
            #pragma unroll
            for (int t = 0; t < 4; t++)
                Bs[a_k*68 + a_r + t*16] = rb[t];
        } else {
            #pragma unroll
            for (int t = 0; t < 4; t++)
                Bs[((tid>>6) + t*4)*68 + (tid&63)] = rb[t];
        }
    };

    loadA(0); loadB(0);
    for (int k0 = 0; k0 < Kd; k0 += 16) {
        storeAB();
        __syncthreads();
        if (k0 + 16 < Kd) { loadA(k0 + 16); loadB(k0 + 16); }
        #pragma unroll
        for (int kk = 0; kk < 16; kk++) {
            float av[RT];
            if constexpr (RT == 8) {
                float4 a0 = *reinterpret_cast<const float4*>(&As[kk*APAD + ty*8]);
                float4 a1 = *reinterpret_cast<const float4*>(&As[kk*APAD + ty*8 + 4]);
                av[0]=a0.x; av[1]=a0.y; av[2]=a0.z; av[3]=a0.w;
                av[4]=a1.x; av[5]=a1.y; av[6]=a1.z; av[7]=a1.w;
            } else {
                av[0] = As[kk*APAD + ty];
            }
            float4 b4 = *reinterpret_cast<const float4*>(&Bs[kk*68 + tx*4]);
            #pragma unroll
            for (int i = 0; i < RT; i++) {
                acc[i][0] += av[i]*b4.x; acc[i][1] += av[i]*b4.y;
                acc[i][2] += av[i]*b4.z; acc[i][3] += av[i]*b4.w;
            }
        }
        __syncthreads();
    }

    #pragma unroll
    for (int i = 0; i < RT; i++) {
        int gr = row0 + ty*RT + i;
        if (gr < Mr) {
            #pragma unroll
            for (int j = 0; j < 4; j++)
                C[(long long)gr*ldc + col0 + tx*4 + j] = acc[i][j];
        }
    }
}

// ---------------- K6: zh/zt = tanh(U + V + bias) ------------------------------
__global__ void k_tanh(const float* __restrict__ bh, const float* __restrict__ bt)
{
    int idx = blockIdx.x*256 + threadIdx.x;
    if (idx >= ROWS*Hv) return;
    int d  = idx % Hv;
    int r  = idx / Hv;        // b*576 + e*24 + f
    int f  = r % NEv;
    int be = r / NEv;         // b*24 + e
    int b  = be / NEv;
    g_zh[idx] = tanhf(g_uh[be*Hv + d]          + g_vh[idx] + bh[d]);
    g_zt[idx] = tanhf(g_ut[(b*NEv + f)*Hv + d] + g_vt[idx] + bt[d]);
}

// ---------------- K7: logits partials (one k-block per blockIdx.y) ------------
// logits_k[r,c] = sum_{i,j} zh[r,k64+i] * zt[r,k64+j] * Wc[c,(k64+i)*64+j]
// 32 rows x 112 cols (97 padded) per block. 224 threads: rg = tid&15 (16 groups
// of 2 rows), cg = tid>>4 (14 groups of 8 cols).
__global__ void __launch_bounds__(224) k_logits()
{
    const int row0 = blockIdx.x * LROWS;
    const int k    = blockIdx.y;           // 0..11
    const int tid  = threadIdx.x;
    const int rg   = tid & 15;
    const int cg   = tid >> 4;             // 0..13

    __shared__ __align__(16) float zh_s[64*34];      // [i][row], stride 34
    __shared__ __align__(16) float zt_s[64*34];      // [j][row]
    __shared__ __align__(16) float wc_s[64*116];     // [j][c], stride 116

    // zero-fill pad cols [97,112) once (never rewritten by slab loads)
    for (int idx = tid; idx < 64*15; idx += 224) {
        int j = idx / 15, c = 97 + idx % 15;
        wc_s[j*116 + c] = 0.f;
    }
    // stage this block's zh/zt k-slab (32 rows x 64)
    for (int idx = tid; idx < LROWS*64; idx += 224) {
        int i = idx & 63, r = idx >> 6;
        zh_s[i*34 + r] = g_zh[(size_t)(row0 + r)*Hv + k*64 + i];
        zt_s[i*34 + r] = g_zt[(size_t)(row0 + r)*Hv + k*64 + i];
    }

    float acc[2][8] = {};
    const float* wck = g_wc + (size_t)k*64*64;   // + c*WCN + i*64 + j

    for (int i = 0; i < 64; i++) {
        __syncthreads();                         // protect wc_s rewrite
        for (int idx = tid; idx < NCLSv*64; idx += 224) {
            int c = idx >> 6, j = idx & 63;
            wc_s[j*116 + c] = wck[(size_t)c*WCN + i*64 + j];
        }
        __syncthreads();
        const float2 a = *reinterpret_cast<const float2*>(&zh_s[i*34 + rg*2]);
        #pragma unroll 8
        for (int j = 0; j < 64; j++) {
            float2 z = *reinterpret_cast<const float2*>(&zt_s[j*34 + rg*2]);
            float p0 = a.x * z.x;
            float p1 = a.y * z.y;
            float4 w0 = *reinterpret_cast<const float4*>(&wc_s[j*116 + cg*8]);
            float4 w1 = *reinterpret_cast<const float4*>(&wc_s[j*116 + cg*8 + 4]);
            acc[0][0]+=p0*w0.x; acc[0][1]+=p0*w0.y; acc[0][2]+=p0*w0.z; acc[0][3]+=p0*w0.w;
            acc[0][4]+=p0*w1.x; acc[0][5]+=p0*w1.y; acc[0][6]+=p0*w1.z; acc[0][7]+=p0*w1.w;
            acc[1][0]+=p1*w0.x; acc[1][1]+=p1*w0.y; acc[1][2]+=p1*w0.z; acc[1][3]+=p1*w0.w;
            acc[1][4]+=p1*w1.x; acc[1][5]+=p1*w1.y; acc[1][6]+=p1*w1.z; acc[1][7]+=p1*w1.w;
        }
    }

    #pragma unroll
    for (int rr = 0; rr < 2; rr++) {
        int row = row0 + rg*2 + rr;
        #pragma unroll
        for (int cc = 0; cc < 8; cc++) {
            int c = cg*8 + cc;
            if (c < NCLSv)
                g_lpart[((size_t)k*ROWS + row)*NCLSv + c] = acc[rr][cc];
        }
    }
}

// ---------------- K8: combine 12 k-partials + bias -----------------------------
__global__ void k_final(const float* __restrict__ bcls, float* __restrict__ out)
{
    int idx = blockIdx.x*256 + threadIdx.x;
    if (idx >= ROWS*NCLSv) return;
    int c = idx % NCLSv;
    float v = bcls[c];
    #pragma unroll
    for (int k = 0; k < 12; k++)
        v += g_lpart[(size_t)k*ROWS*NCLSv + idx];
    out[idx] = v;
}

// ================================ launch ========================================
extern "C" void kernel_launch(void* const* d_in, const int* in_sizes, int n_in,
                              void* d_out, int out_size)
{
    const float* seq  = (const float*)d_in[0];
    const float* att  = (const float*)d_in[1];
    const int*   ms   = (const int*)  d_in[2];
    const int*   cs   = (const int*)  d_in[3];
    const float* Wh   = (const float*)d_in[4];
    const float* bh   = (const float*)d_in[5];
    const float* Wt   = (const float*)d_in[6];
    const float* bt   = (const float*)d_in[7];
    const float* Wp   = (const float*)d_in[8];
    const float* Wcls = (const float*)d_in[9];
    const float* bcls = (const float*)d_in[10];
    float* out = (float*)d_out;

    float *p_ht, *p_rs, *p_eemb, *p_uh, *p_ut, *p_vh, *p_vt, *p_wc;
    cudaGetSymbolAddress((void**)&p_ht,   g_ht);
    cudaGetSymbolAddress((void**)&p_rs,   g_rs);
    cudaGetSymbolAddress((void**)&p_eemb, g_eemb);
    cudaGetSymbolAddress((void**)&p_uh,   g_uh);
    cudaGetSymbolAddress((void**)&p_ut,   g_ut);
    cudaGetSymbolAddress((void**)&p_vh,   g_vh);
    cudaGetSymbolAddress((void**)&p_vt,   g_vt);
    cudaGetSymbolAddress((void**)&p_wc,   g_wc);

    // Wc = W_cls @ W_proj  (97 x 49152, K=768)
    k_gemm<128,8,false><<<dim3(WCN/64, 1, 1), 256>>>(
        Wcls, Wp, p_wc, NCLSv, Hv, Hv, WCN, WCN, 0, 0, 0);

    k_eatt<<<Bv*NEv*NHv, 256>>>(att, ms);
    k_gate<<<Bv*NEv, 256>>>();
    k_eemb<<<Bv*NEv, Hv>>>(seq, ms, cs);
    k_ht<<<dim3(NPAIR, Bv), 256>>>();

    // rs = ht @ seq  (batched over B via z-stride)
    k_gemm<128,8,false><<<dim3(Hv/64, (NPAIR + 127)/128, Bv), 256>>>(
        p_ht, seq, p_rs, NPAIR, Lv, Lv, Hv, Hv,
        (long long)NPAIR*Lv, (long long)Lv*Hv, (long long)NPAIR*Hv);

    // U = e_emb @ W[:, :H]^T   (48 x 768) — head/tail fused via dual-pointer stride
    k_gemm<16,1,true><<<dim3(Hv/64, 3, 2), 256>>>(
        p_eemb, Wh, p_uh, Bv*NEv, Hv, Hv, 2*Hv, Hv,
        0, (long long)(Wt - Wh), (long long)(p_ut - p_uh));

    // V = rs @ W[:, H:]^T   (1152 x 768) — head/tail fused via dual-pointer stride
    k_gemm<128,8,true><<<dim3(Hv/64, ROWS/128, 2), 256>>>(
        p_rs, Wh + Hv, p_vh, ROWS, Hv, Hv, 2*Hv, Hv,
        0, (long long)(Wt - Wh), (long long)(p_vt - p_vh));

    k_tanh<<<(ROWS*Hv + 255)/256, 256>>>(bh, bt);

    k_logits<<<dim3(ROWS/LROWS, 12), 224>>>();

    k_final<<<(ROWS*NCLSv + 255)/256, 256>>>(bcls, out);
}

// round 11
// speedup vs baseline: 6.6639x; 1.6747x over previous
#include <cuda_runtime.h>
#include <cuda_bf16.h>
#include <math.h>
#include <stdint.h>

#define Bv    2
#define Lv    1024
#define Hv    768
#define NHv   12
#define NEv   24
#define Mv    3
#define NCv   2
#define CWv   8
#define NCLSv 97
#define NPAIR (NEv*NEv)       /* 576 */
#define ROWS  (Bv*NPAIR)      /* 1152 */
#define WCN   (Hv*64)         /* 49152 */
#define KCH   16              /* K-chunks for logits split-K */

// MMA tile constants
#define TS      72            /* smem row stride in bf16 (144B: 16B-aligned, conflict-free) */
#define TILE_B  (128*TS*2)    /* 18432 B per 128x64 bf16 tile */
#define STAGE_B (4*TILE_B)    /* Ah, Al, Bh, Bl */
#define SMEMB   (2*STAGE_B)   /* double buffered = 147456 B */

__device__ __forceinline__ uint32_t smem_u32(const void* p) {
    uint32_t a;
    asm("{ .reg .u64 t; cvta.to.shared.u64 t, %1; cvt.u32.u64 %0, t; }" : "=r"(a) : "l"(p));
    return a;
}

__device__ __forceinline__ void cpasync16(uint32_t dst, const void* src) {
    asm volatile("cp.async.cg.shared.global [%0], [%1], 16;" :: "r"(dst), "l"(src) : "memory");
}
#define CP_COMMIT() asm volatile("cp.async.commit_group;" ::: "memory")
#define CP_WAIT(n)  asm volatile("cp.async.wait_group %0;" :: "n"(n) : "memory")

__device__ __forceinline__ void mma16816(float* d,
    uint32_t a0, uint32_t a1, uint32_t a2, uint32_t a3, uint32_t b0, uint32_t b1)
{
    asm volatile(
        "mma.sync.aligned.m16n8k16.row.col.f32.bf16.bf16.f32 "
        "{%0,%1,%2,%3}, {%4,%5,%6,%7}, {%8,%9}, {%0,%1,%2,%3};"
        : "+f"(d[0]), "+f"(d[1]), "+f"(d[2]), "+f"(d[3])
        : "r"(a0), "r"(a1), "r"(a2), "r"(a3), "r"(b0), "r"(b1));
}

__device__ __forceinline__ void split_bf16(float v, __nv_bfloat16& h, __nv_bfloat16& l) {
    h = __float2bfloat16(v);
    l = __float2bfloat16(v - __bfloat162float(h));
}

// ---------------- scratch (static device memory; no allocations) -------------
__device__ float g_eatt[Bv*NEv*NHv*Lv];
__device__ float g_gate[Bv*NEv*Lv];
__device__ float g_eemb[Bv*NEv*Hv];
__device__ float g_ht[(size_t)Bv*NPAIR*Lv];
__device__ float g_rs[(size_t)ROWS*Hv];
__device__ float g_uh[Bv*NEv*Hv];
__device__ float g_ut[Bv*NEv*Hv];
__device__ float g_vh[(size_t)ROWS*Hv];
__device__ float g_vt[(size_t)ROWS*Hv];
__device__ float g_zh[(size_t)ROWS*Hv];
__device__ float g_zt[(size_t)ROWS*Hv];
__device__ float g_lpart[(size_t)KCH*ROWS*NCLSv];

__device__ __align__(16) __nv_bfloat16 g_wpth[(size_t)WCN*Hv];
__device__ __align__(16) __nv_bfloat16 g_wptl[(size_t)WCN*Hv];
__device__ __align__(16) __nv_bfloat16 g_wclsh[128*Hv];
__device__ __align__(16) __nv_bfloat16 g_wclsl[128*Hv];
__device__ __align__(16) __nv_bfloat16 g_wch[(size_t)128*WCN];
__device__ __align__(16) __nv_bfloat16 g_wcl[(size_t)128*WCN];
__device__ __align__(16) __nv_bfloat16 g_blh[(size_t)ROWS*WCN];
__device__ __align__(16) __nv_bfloat16 g_bll[(size_t)ROWS*WCN];

// ---------------- K1: e_att[b,e,h,l] = mean_m attention[b,h,p_m,l] -----------
__global__ void k_eatt(const float* __restrict__ att, const int* __restrict__ ms)
{
    int bh = blockIdx.x;
    int h  = bh % NHv;
    int be = bh / NHv;
    int b  = be / NEv;
    int p0 = ms[be*Mv + 0] + 1;
    int p1 = ms[be*Mv + 1] + 1;
    int p2 = ms[be*Mv + 2] + 1;
    const float* base = att + (size_t)(b*NHv + h)*Lv*Lv;
    const float* a0 = base + (size_t)p0*Lv;
    const float* a1 = base + (size_t)p1*Lv;
    const float* a2 = base + (size_t)p2*Lv;
    float* o = g_eatt + (size_t)(be*NHv + h)*Lv;
    for (int l = threadIdx.x; l < Lv; l += blockDim.x)
        o[l] = (a0[l] + a1[l] + a2[l]) * (1.0f/3.0f);
}

// ---------------- K2: gate ----------------------------------------------------
__global__ void k_gate()
{
    int be = blockIdx.x;
    __shared__ float s[Lv];
    __shared__ float red[256];
    float part = 0.f;
    for (int l = threadIdx.x; l < Lv; l += 256) {
        float v = 0.f;
        #pragma unroll
        for (int h = 0; h < NHv; h++)
            v += g_eatt[((size_t)(be*NHv + h))*Lv + l];
        s[l] = v;
        part += v;
    }
    red[threadIdx.x] = part;
    __syncthreads();
    for (int st = 128; st > 0; st >>= 1) {
        if (threadIdx.x < st) red[threadIdx.x] += red[threadIdx.x + st];
        __syncthreads();
    }
    float inv = 1.0f / red[0];
    for (int l = threadIdx.x; l < Lv; l += 256)
        g_gate[be*Lv + l] = s[l] * inv;
}

// ---------------- K3: e_emb ----------------------------------------------------
__global__ void k_eemb(const float* __restrict__ seq, const int* __restrict__ ms,
                       const int* __restrict__ cs)
{
    int be = blockIdx.x;
    int b  = be / NEv;
    int d  = threadIdx.x;
    __shared__ int   sp[Mv];
    __shared__ int   scs[NCv];
    __shared__ float sg[NCv][CWv];
    if (threadIdx.x < Mv)  sp[threadIdx.x]  = ms[be*Mv + threadIdx.x] + 1;
    if (threadIdx.x < NCv) scs[threadIdx.x] = cs[be*NCv + threadIdx.x];
    __syncthreads();
    if (threadIdx.x < NCv*CWv) {
        int c = threadIdx.x / CWv, w = threadIdx.x % CWv;
        sg[c][w] = g_gate[be*Lv + scs[c] + w];
    }
    __syncthreads();

    float x[Mv + NCv];
    #pragma unroll
    for (int m = 0; m < Mv; m++)
        x[m] = seq[((size_t)b*Lv + sp[m])*Hv + d];
    #pragma unroll
    for (int c = 0; c < NCv; c++) {
        float acc = 0.f;
        int basel = scs[c];
        #pragma unroll
        for (int w = 0; w < CWv; w++)
            acc += sg[c][w] * seq[((size_t)b*Lv + basel + w)*Hv + d];
        x[Mv + c] = acc;
    }
    float mx = x[0];
    #pragma unroll
    for (int i = 1; i < Mv + NCv; i++) mx = fmaxf(mx, x[i]);
    float ssum = 0.f;
    #pragma unroll
    for (int i = 0; i < Mv + NCv; i++) ssum += expf(x[i] - mx);
    g_eemb[be*Hv + d] = mx + logf(ssum);
}

// ---------------- K4: ht -------------------------------------------------------
__global__ void k_ht()
{
    int ef = blockIdx.x;
    int b  = blockIdx.y;
    int e = ef / NEv, f = ef % NEv;
    __shared__ float s[Lv];
    __shared__ float red[256];
    const float* pe = g_eatt + (size_t)((b*NEv + e)*NHv)*Lv;
    const float* pf = g_eatt + (size_t)((b*NEv + f)*NHv)*Lv;
    float part = 0.f;
    for (int l = threadIdx.x; l < Lv; l += 256) {
        float v = 0.f;
        #pragma unroll
        for (int h = 0; h < NHv; h++)
            v += pe[h*Lv + l] * pf[h*Lv + l];
        v = fmaxf(v, 0.f);
        s[l] = v;
        part += v;
    }
    red[threadIdx.x] = part;
    __syncthreads();
    for (int st = 128; st > 0; st >>= 1) {
        if (threadIdx.x < st) red[threadIdx.x] += red[threadIdx.x + st];
        __syncthreads();
    }
    float inv = 1.0f / (red[0] + 1e-10f);
    float* o = g_ht + ((size_t)b*NPAIR + ef)*Lv;
    for (int l = threadIdx.x; l < Lv; l += 256)
        o[l] = s[l] * inv;
}

// ---------------- fp32 tiled GEMM (for rs / U / V) -----------------------------
template<int TM, int RT, bool BT>
__global__ void __launch_bounds__(256) k_gemm(
    const float* __restrict__ A, const float* __restrict__ Bm, float* __restrict__ C,
    int Mr, int Kd, int lda, int ldb, int ldc,
    long long sA, long long sB, long long sC)
{
    constexpr int APAD = (TM == 128) ? 136 : 20;
    A  += (long long)blockIdx.z * sA;
    Bm += (long long)blockIdx.z * sB;
    C  += (long long)blockIdx.z * sC;

    __shared__ __align__(16) float As[16*APAD];
    __shared__ __align__(16) float Bs[16*68];

    const int tid = threadIdx.x;
    const int tx = tid & 15;
    const int ty = tid >> 4;
    const int row0 = blockIdx.y * TM;
    const int col0 = blockIdx.x * 64;

    const int a_k = tid & 15;
    const int a_r = tid >> 4;

    float acc[RT][4] = {};
    float ra[TM/16], rb[4];

    auto loadA = [&](int k0) {
        #pragma unroll
        for (int t = 0; t < TM/16; t++) {
            int gr = row0 + a_r + t*16;
            ra[t] = (gr < Mr) ? A[(long long)gr*lda + (k0 + a_k)] : 0.f;
        }
    };
    auto loadB = [&](int k0) {
        if (BT) {
            #pragma unroll
            for (int t = 0; t < 4; t++)
                rb[t] = Bm[(long long)(col0 + a_r + t*16)*ldb + (k0 + a_k)];
        } else {
            #pragma unroll
            for (int t = 0; t < 4; t++)
                rb[t] = Bm[(long long)(k0 + (tid>>6) + t*4)*ldb + col0 + (tid&63)];
        }
    };
    auto storeAB = [&]() {
        #pragma unroll
        for (int t = 0; t < TM/16; t++)
            As[a_k*APAD + a_r + t*16] = ra[t];
        if (BT) {
            #pragma unroll
            for (int t = 0; t < 4; t++)
                Bs[a_k*68 + a_r + t*16] = rb[t];
        } else {
            #pragma unroll
            for (int t = 0; t < 4; t++)
                Bs[((tid>>6) + t*4)*68 + (tid&63)] = rb[t];
        }
    };

    loadA(0); loadB(0);
    for (int k0 = 0; k0 < Kd; k0 += 16) {
        storeAB();
        __syncthreads();
        if (k0 + 16 < Kd) { loadA(k0 + 16); loadB(k0 + 16); }
        #pragma unroll
        for (int kk = 0; kk < 16; kk++) {
            float av[RT];
            if constexpr (RT == 8) {
                float4 a0 = *reinterpret_cast<const float4*>(&As[kk*APAD + ty*8]);
                float4 a1 = *reinterpret_cast<const float4*>(&As[kk*APAD + ty*8 + 4]);
                av[0]=a0.x; av[1]=a0.y; av[2]=a0.z; av[3]=a0.w;
                av[4]=a1.x; av[5]=a1.y; av[6]=a1.z; av[7]=a1.w;
            } else {
                av[0] = As[kk*APAD + ty];
            }
            float4 b4 = *reinterpret_cast<const float4*>(&Bs[kk*68 + tx*4]);
            #pragma unroll
            for (int i = 0; i < RT; i++) {
                acc[i][0] += av[i]*b4.x; acc[i][1] += av[i]*b4.y;
                acc[i][2] += av[i]*b4.z; acc[i][3] += av[i]*b4.w;
            }
        }
        __syncthreads();
    }

    #pragma unroll
    for (int i = 0; i < RT; i++) {
        int gr = row0 + ty*RT + i;
        if (gr < Mr) {
            #pragma unroll
            for (int j = 0; j < 4; j++)
                C[(long long)gr*ldc + col0 + tx*4 + j] = acc[i][j];
        }
    }
}

// ---------------- K6: zh/zt = tanh(U + V + bias) -------------------------------
__global__ void k_tanh(const float* __restrict__ bh, const float* __restrict__ bt)
{
    int idx = blockIdx.x*256 + threadIdx.x;
    if (idx >= ROWS*Hv) return;
    int d  = idx % Hv;
    int r  = idx / Hv;
    int f  = r % NEv;
    int be = r / NEv;
    int b  = be / NEv;
    g_zh[idx] = tanhf(g_uh[be*Hv + d]          + g_vh[idx] + bh[d]);
    g_zt[idx] = tanhf(g_ut[(b*NEv + f)*Hv + d] + g_vt[idx] + bt[d]);
}

// ---------------- conversions ---------------------------------------------------
// Wp [768 x 49152] fp32 -> WpT hi/lo [49152 x 768] bf16 (transpose + split)
__global__ void k_wpt(const float* __restrict__ Wp)
{
    __shared__ float t[32][33];
    int n0 = blockIdx.x*32, k0 = blockIdx.y*32;
    int tx = threadIdx.x, ty = threadIdx.y;   // 32 x 8
    #pragma unroll
    for (int q = 0; q < 4; q++)
        t[ty + q*8][tx] = Wp[(size_t)(k0 + ty + q*8)*WCN + n0 + tx];
    __syncthreads();
    #pragma unroll
    for (int q = 0; q < 4; q++) {
        int n = ty + q*8;
        float v = t[tx][n];
        __nv_bfloat16 h, l; split_bf16(v, h, l);
        g_wpth[(size_t)(n0 + n)*Hv + k0 + tx] = h;
        g_wptl[(size_t)(n0 + n)*Hv + k0 + tx] = l;
    }
}

// Wcls [97 x 768] -> padded [128 x 768] hi/lo bf16
__global__ void k_wcls_conv(const float* __restrict__ Wcls)
{
    int idx = blockIdx.x*256 + threadIdx.x;
    if (idx >= 128*Hv) return;
    int r = idx / Hv, c = idx % Hv;
    float v = (r < NCLSv) ? Wcls[r*Hv + c] : 0.f;
    __nv_bfloat16 h, l; split_bf16(v, h, l);
    g_wclsh[idx] = h;
    g_wclsl[idx] = l;
}

// BL materialization: BL[r, (k*64+i)*64+j] = zh[r,k64+i]*zt[r,k64+j], hi/lo bf16
__global__ void __launch_bounds__(256) k_bl()
{
    __shared__ float zh_s[64], zt_s[64];
    int r = blockIdx.y, k = blockIdx.x, tid = threadIdx.x;
    if (tid < 64)       zh_s[tid]      = g_zh[(size_t)r*Hv + k*64 + tid];
    else if (tid < 128) zt_s[tid - 64] = g_zt[(size_t)r*Hv + k*64 + (tid - 64)];
    __syncthreads();
    int dl = tid >> 2;
    int j0 = (tid & 3) * 16;
    float a = zh_s[dl];
    uint32_t ph[8], pl[8];
    #pragma unroll
    for (int q = 0; q < 8; q++) {
        float v0 = a * zt_s[j0 + 2*q];
        float v1 = a * zt_s[j0 + 2*q + 1];
        __nv_bfloat16 h0, l0, h1, l1;
        split_bf16(v0, h0, l0); split_bf16(v1, h1, l1);
        ph[q] = (uint32_t)__bfloat16_as_ushort(h0) | ((uint32_t)__bfloat16_as_ushort(h1) << 16);
        pl[q] = (uint32_t)__bfloat16_as_ushort(l0) | ((uint32_t)__bfloat16_as_ushort(l1) << 16);
    }
    size_t base = (size_t)r*WCN + (size_t)k*4096 + dl*64 + j0;
    uint4* dh = reinterpret_cast<uint4*>(g_blh + base);
    uint4* dl4 = reinterpret_cast<uint4*>(g_bll + base);
    dh[0]  = make_uint4(ph[0], ph[1], ph[2], ph[3]);
    dh[1]  = make_uint4(ph[4], ph[5], ph[6], ph[7]);
    dl4[0] = make_uint4(pl[0], pl[1], pl[2], pl[3]);
    dl4[1] = make_uint4(pl[4], pl[5], pl[6], pl[7]);
}

// ---------------- mma.sync split-bf16 GEMM core ---------------------------------
// C[128,128] = A[128,K] * B[128,K]^T, 3-term hi/lo split, K consumed in 64-chunks.
// 256 threads = 8 warps (2 x 4); warp tile 64 x 32; m16n8k16 fragments.

__device__ __forceinline__ void issue_stage(uint32_t sb, int s,
    const __nv_bfloat16* Ah, const __nv_bfloat16* Al, int lda,
    const __nv_bfloat16* Bh, const __nv_bfloat16* Bl, int ldb)
{
    int tid = threadIdx.x;
    uint32_t st = sb + s*STAGE_B;
    #pragma unroll
    for (int t = 0; t < 4; t++) {
        int idx = tid + t*256;           // 0..1023
        int row = idx >> 3, ch = idx & 7;
        uint32_t off = row*(TS*2) + ch*16;
        const __nv_bfloat16* ga = Ah + (size_t)row*lda + ch*8;
        const __nv_bfloat16* gl = Al + (size_t)row*lda + ch*8;
        const __nv_bfloat16* gb = Bh + (size_t)row*ldb + ch*8;
        const __nv_bfloat16* gc = Bl + (size_t)row*ldb + ch*8;
        cpasync16(st +            off, ga);
        cpasync16(st +   TILE_B + off, gl);
        cpasync16(st + 2*TILE_B + off, gb);
        cpasync16(st + 3*TILE_B + off, gc);
    }
    CP_COMMIT();
}

__device__ __forceinline__ void compute_stage(const char* smem, int s,
    float acc[4][4][4], int lane, int wm, int wn)
{
    const char* base = smem + s*STAGE_B;
    #pragma unroll
    for (int ks = 0; ks < 4; ks++) {
        const int k0 = ks*16 + (lane & 3)*2;    // bf16 col index
        uint32_t bh[4][2], bl[4][2];
        #pragma unroll
        for (int nf = 0; nf < 4; nf++) {
            int n = wn*32 + nf*8 + (lane >> 2);
            const char* ph = base + 2*TILE_B + n*(TS*2) + k0*2;
            const char* pl = base + 3*TILE_B + n*(TS*2) + k0*2;
            bh[nf][0] = *(const uint32_t*)ph;
            bh[nf][1] = *(const uint32_t*)(ph + 16);
            bl[nf][0] = *(const uint32_t*)pl;
            bl[nf][1] = *(const uint32_t*)(pl + 16);
        }
        #pragma unroll
        for (int mf = 0; mf < 4; mf++) {
            int r = wm*64 + mf*16 + (lane >> 2);
            const char* pa = base + r*(TS*2) + k0*2;
            const char* pb = base + TILE_B + r*(TS*2) + k0*2;
            uint32_t ah0 = *(const uint32_t*)pa;
            uint32_t ah1 = *(const uint32_t*)(pa + TS*16);      // +8 rows
            uint32_t ah2 = *(const uint32_t*)(pa + 16);         // +8 cols
            uint32_t ah3 = *(const uint32_t*)(pa + TS*16 + 16);
            uint32_t al0 = *(const uint32_t*)pb;
            uint32_t al1 = *(const uint32_t*)(pb + TS*16);
            uint32_t al2 = *(const uint32_t*)(pb + 16);
            uint32_t al3 = *(const uint32_t*)(pb + TS*16 + 16);
            #pragma unroll
            for (int nf = 0; nf < 4; nf++) {
                mma16816(acc[mf][nf], ah0, ah1, ah2, ah3, bh[nf][0], bh[nf][1]);
                mma16816(acc[mf][nf], ah0, ah1, ah2, ah3, bl[nf][0], bl[nf][1]);
                mma16816(acc[mf][nf], al0, al1, al2, al3, bh[nf][0], bh[nf][1]);
            }
        }
    }
}

__device__ __forceinline__ void mma_pipeline(char* smem, float acc[4][4][4],
    const __nv_bfloat16* Ah, const __nv_bfloat16* Al, int lda,
    const __nv_bfloat16* Bh, const __nv_bfloat16* Bl, int ldb,
    int niter, int lane, int wm, int wn)
{
    uint32_t sb = smem_u32(smem);
    issue_stage(sb, 0, Ah, Al, lda, Bh, Bl, ldb);
    for (int it = 0; it < niter; it++) {
        if (it + 1 < niter) {
            issue_stage(sb, (it + 1) & 1,
                        Ah + (it + 1)*64, Al + (it + 1)*64, lda,
                        Bh + (it + 1)*64, Bl + (it + 1)*64, ldb);
            CP_WAIT(1);
        } else {
            CP_WAIT(0);
        }
        __syncthreads();
        compute_stage(smem, it & 1, acc, lane, wm, wn);
        __syncthreads();
    }
}

// Wc = Wcls_pad(128x768) @ WpT(49152x768)^T -> bf16 hi/lo. grid = 384.
__global__ __launch_bounds__(256, 1) void k_mma_wc()
{
    extern __shared__ char smem[];
    const int tid = threadIdx.x, lane = tid & 31, w = tid >> 5;
    const int wm = w >> 2, wn = w & 3;
    const int n0 = blockIdx.x * 128;

    float acc[4][4][4] = {};
    mma_pipeline(smem, acc,
                 g_wclsh, g_wclsl, Hv,
                 g_wpth + (size_t)n0*Hv, g_wptl + (size_t)n0*Hv, Hv,
                 Hv/64, lane, wm, wn);

    #pragma unroll
    for (int mf = 0; mf < 4; mf++) {
        int r  = wm*64 + mf*16 + (lane >> 2);
        #pragma unroll
        for (int nf = 0; nf < 4; nf++) {
            int cb = n0 + wn*32 + nf*8 + (lane & 3)*2;
            __nv_bfloat16 h0, l0, h1, l1;
            split_bf16(acc[mf][nf][0], h0, l0);
            split_bf16(acc[mf][nf][1], h1, l1);
            *reinterpret_cast<uint32_t*>(g_wch + (size_t)r*WCN + cb) =
                (uint32_t)__bfloat16_as_ushort(h0) | ((uint32_t)__bfloat16_as_ushort(h1) << 16);
            *reinterpret_cast<uint32_t*>(g_wcl + (size_t)r*WCN + cb) =
                (uint32_t)__bfloat16_as_ushort(l0) | ((uint32_t)__bfloat16_as_ushort(l1) << 16);
            split_bf16(acc[mf][nf][2], h0, l0);
            split_bf16(acc[mf][nf][3], h1, l1);
            *reinterpret_cast<uint32_t*>(g_wch + (size_t)(r + 8)*WCN + cb) =
                (uint32_t)__bfloat16_as_ushort(h0) | ((uint32_t)__bfloat16_as_ushort(h1) << 16);
            *reinterpret_cast<uint32_t*>(g_wcl + (size_t)(r + 8)*WCN + cb) =
                (uint32_t)__bfloat16_as_ushort(l0) | ((uint32_t)__bfloat16_as_ushort(l1) << 16);
        }
    }
}

// logits partials: grid (9, KCH). C[128 rows x 128 cls] over K-chunk 3072.
__global__ __launch_bounds__(256, 1) void k_mma_logits()
{
    extern __shared__ char smem[];
    const int tid = threadIdx.x, lane = tid & 31, w = tid >> 5;
    const int wm = w >> 2, wn = w & 3;
    const int row0 = blockIdx.x * 128;
    const int kc   = blockIdx.y;
    const size_t ka = (size_t)kc * (WCN / KCH);

    float acc[4][4][4] = {};
    mma_pipeline(smem, acc,
                 g_blh + (size_t)row0*WCN + ka, g_bll + (size_t)row0*WCN + ka, WCN,
                 g_wch + ka, g_wcl + ka, WCN,
                 (WCN/KCH)/64, lane, wm, wn);

    float* outk = g_lpart + (size_t)kc*ROWS*NCLSv;
    #pragma unroll
    for (int mf = 0; mf < 4; mf++) {
        int r = row0 + wm*64 + mf*16 + (lane >> 2);
        #pragma unroll
        for (int nf = 0; nf < 4; nf++) {
            int c = wn*32 + nf*8 + (lane & 3)*2;
            if (c < NCLSv)     outk[(size_t)r*NCLSv + c]           = acc[mf][nf][0];
            if (c + 1 < NCLSv) outk[(size_t)r*NCLSv + c + 1]       = acc[mf][nf][1];
            if (c < NCLSv)     outk[(size_t)(r + 8)*NCLSv + c]     = acc[mf][nf][2];
            if (c + 1 < NCLSv) outk[(size_t)(r + 8)*NCLSv + c + 1] = acc[mf][nf][3];
        }
    }
}

// ---------------- K8: combine KCH k-partials + bias ----------------------------
__global__ void k_final(const float* __restrict__ bcls, float* __restrict__ out)
{
    int idx = blockIdx.x*256 + threadIdx.x;
    if (idx >= ROWS*NCLSv) return;
    int c = idx % NCLSv;
    float v = bcls[c];
    #pragma unroll
    for (int k = 0; k < KCH; k++)
        v += g_lpart[(size_t)k*ROWS*NCLSv + idx];
    out[idx] = v;
}

// ================================ launch ========================================
extern "C" void kernel_launch(void* const* d_in, const int* in_sizes, int n_in,
                              void* d_out, int out_size)
{
    const float* seq  = (const float*)d_in[0];
    const float* att  = (const float*)d_in[1];
    const int*   ms   = (const int*)  d_in[2];
    const int*   cs   = (const int*)  d_in[3];
    const float* Wh   = (const float*)d_in[4];
    const float* bh   = (const float*)d_in[5];
    const float* Wt   = (const float*)d_in[6];
    const float* bt   = (const float*)d_in[7];
    const float* Wp   = (const float*)d_in[8];
    const float* Wcls = (const float*)d_in[9];
    const float* bcls = (const float*)d_in[10];
    float* out = (float*)d_out;

    float *p_ht, *p_rs, *p_eemb, *p_uh, *p_ut, *p_vh, *p_vt;
    cudaGetSymbolAddress((void**)&p_ht,   g_ht);
    cudaGetSymbolAddress((void**)&p_rs,   g_rs);
    cudaGetSymbolAddress((void**)&p_eemb, g_eemb);
    cudaGetSymbolAddress((void**)&p_uh,   g_uh);
    cudaGetSymbolAddress((void**)&p_ut,   g_ut);
    cudaGetSymbolAddress((void**)&p_vh,   g_vh);
    cudaGetSymbolAddress((void**)&p_vt,   g_vt);

    cudaFuncSetAttribute(k_mma_wc,     cudaFuncAttributeMaxDynamicSharedMemorySize, SMEMB);
    cudaFuncSetAttribute(k_mma_logits, cudaFuncAttributeMaxDynamicSharedMemorySize, SMEMB);

    // --- Wc path (mma.sync split-bf16) ---
    k_wpt<<<dim3(WCN/32, Hv/32), dim3(32, 8)>>>(Wp);
    k_wcls_conv<<<(128*Hv + 255)/256, 256>>>(Wcls);
    k_mma_wc<<<WCN/128, 256, SMEMB>>>();

    // --- attention path ---
    k_eatt<<<Bv*NEv*NHv, 256>>>(att, ms);
    k_gate<<<Bv*NEv, 256>>>();
    k_eemb<<<Bv*NEv, Hv>>>(seq, ms, cs);
    k_ht<<<dim3(NPAIR, Bv), 256>>>();

    // rs = ht @ seq
    k_gemm<128,8,false><<<dim3(Hv/64, (NPAIR + 127)/128, Bv), 256>>>(
        p_ht, seq, p_rs, NPAIR, Lv, Lv, Hv, Hv,
        (long long)NPAIR*Lv, (long long)Lv*Hv, (long long)NPAIR*Hv);

    // U = e_emb @ W[:, :H]^T (head/tail fused via z-stride)
    k_gemm<16,1,true><<<dim3(Hv/64, 3, 2), 256>>>(
        p_eemb, Wh, p_uh, Bv*NEv, Hv, Hv, 2*Hv, Hv,
        0, (long long)(Wt - Wh), (long long)(p_ut - p_uh));

    // V = rs @ W[:, H:]^T (head/tail fused via z-stride)
    k_gemm<128,8,true><<<dim3(Hv/64, ROWS/128, 2), 256>>>(
        p_rs, Wh + Hv, p_vh, ROWS, Hv, Hv, 2*Hv, Hv,
        0, (long long)(Wt - Wh), (long long)(p_vt - p_vh));

    k_tanh<<<(ROWS*Hv + 255)/256, 256>>>(bh, bt);

    // --- logits path (mma.sync split-bf16, split-K) ---
    k_bl<<<dim3(Hv/64, ROWS), 256>>>();
    k_mma_logits<<<dim3(ROWS/128, KCH), 256, SMEMB>>>();

    k_final<<<(ROWS*NCLSv + 255)/256, 256>>>(bcls, out);
}

// round 12
// speedup vs baseline: 8.1390x; 1.2214x over previous
#include <cuda_runtime.h>
#include <cuda_bf16.h>
#include <math.h>
#include <stdint.h>

#define Bv    2
#define Lv    1024
#define Hv    768
#define NHv   12
#define NEv   24
#define Mv    3
#define NCv   2
#define CWv   8
#define NCLSv 97
#define NPAIR (NEv*NEv)       /* 576 */
#define ROWS  (Bv*NPAIR)      /* 1152 */
#define WCN   (Hv*64)         /* 49152 */
#define KCH   16              /* K-chunks for logits split-K */

// MMA tile constants
#define TS      72            /* smem row stride in bf16 (144B) */
#define TILE_B  (128*TS*2)    /* 18432 B per 128x64 bf16 tile */
#define STAGE_B (4*TILE_B)    /* Ah, Al, Bh, Bl */
#define SMEMB   (2*STAGE_B)   /* 147456 B for k_mma_g */

// fused logits kernel smem layout
#define LB_STG  (2*TILE_B)            /* 36864: Bh+Bl per stage */
#define LA_BASE (2*LB_STG)            /* 73728 */
#define LZH_OFF (LA_BASE + 2*LB_STG)  /* 147456 */
#define LZT_OFF (LZH_OFF + 128*65*4)  /* 180736 */
#define LSMEM   (LZT_OFF + 128*66*4)  /* 214528 */

__device__ __forceinline__ uint32_t smem_u32(const void* p) {
    uint32_t a;
    asm("{ .reg .u64 t; cvta.to.shared.u64 t, %1; cvt.u32.u64 %0, t; }" : "=r"(a) : "l"(p));
    return a;
}
__device__ __forceinline__ void cpasync16(uint32_t dst, const void* src) {
    asm volatile("cp.async.cg.shared.global [%0], [%1], 16;" :: "r"(dst), "l"(src) : "memory");
}
#define CP_COMMIT() asm volatile("cp.async.commit_group;" ::: "memory")
#define CP_WAIT(n)  asm volatile("cp.async.wait_group %0;" :: "n"(n) : "memory")

__device__ __forceinline__ void mma16816(float* d,
    uint32_t a0, uint32_t a1, uint32_t a2, uint32_t a3, uint32_t b0, uint32_t b1)
{
    asm volatile(
        "mma.sync.aligned.m16n8k16.row.col.f32.bf16.bf16.f32 "
        "{%0,%1,%2,%3}, {%4,%5,%6,%7}, {%8,%9}, {%0,%1,%2,%3};"
        : "+f"(d[0]), "+f"(d[1]), "+f"(d[2]), "+f"(d[3])
        : "r"(a0), "r"(a1), "r"(a2), "r"(a3), "r"(b0), "r"(b1));
}
__device__ __forceinline__ void split_bf16(float v, __nv_bfloat16& h, __nv_bfloat16& l) {
    h = __float2bfloat16(v);
    l = __float2bfloat16(v - __bfloat162float(h));
}
__device__ __forceinline__ uint32_t pack2(__nv_bfloat16 a, __nv_bfloat16 b) {
    return (uint32_t)__bfloat16_as_ushort(a) | ((uint32_t)__bfloat16_as_ushort(b) << 16);
}

// ---------------- scratch (static device memory; no allocations) -------------
__device__ float g_eatt[Bv*NEv*NHv*Lv];
__device__ float g_gate[Bv*NEv*Lv];
__device__ float g_eemb[Bv*NEv*Hv];
__device__ float g_uh[Bv*NEv*Hv];
__device__ float g_ut[Bv*NEv*Hv];
__device__ float g_v[2*(size_t)ROWS*Hv];          /* vh | vt */
__device__ float g_zh[(size_t)ROWS*Hv];
__device__ float g_zt[(size_t)ROWS*Hv];
__device__ float g_lpart[(size_t)KCH*ROWS*NCLSv];

__device__ __align__(16) __nv_bfloat16 g_wpth[(size_t)WCN*Hv];
__device__ __align__(16) __nv_bfloat16 g_wptl[(size_t)WCN*Hv];
__device__ __align__(16) __nv_bfloat16 g_wclsh[128*Hv];
__device__ __align__(16) __nv_bfloat16 g_wclsl[128*Hv];
__device__ __align__(16) __nv_bfloat16 g_wch[(size_t)128*WCN];
__device__ __align__(16) __nv_bfloat16 g_wcl[(size_t)128*WCN];
__device__ __align__(16) __nv_bfloat16 g_hth[(size_t)Bv*NPAIR*Lv];
__device__ __align__(16) __nv_bfloat16 g_htl[(size_t)Bv*NPAIR*Lv];
__device__ __align__(16) __nv_bfloat16 g_sqh[(size_t)Bv*Hv*Lv];
__device__ __align__(16) __nv_bfloat16 g_sql[(size_t)Bv*Hv*Lv];
__device__ __align__(16) __nv_bfloat16 g_rsh[(size_t)ROWS*Hv];
__device__ __align__(16) __nv_bfloat16 g_rsl[(size_t)ROWS*Hv];
__device__ __align__(16) __nv_bfloat16 g_whxh[2*(size_t)Hv*Hv];
__device__ __align__(16) __nv_bfloat16 g_whxl[2*(size_t)Hv*Hv];

// ---------------- K1: e_att[b,e,h,l] = mean_m attention[b,h,p_m,l] -----------
__global__ void k_eatt(const float* __restrict__ att, const int* __restrict__ ms)
{
    int bh = blockIdx.x;
    int h  = bh % NHv;
    int be = bh / NHv;
    int b  = be / NEv;
    int p0 = ms[be*Mv + 0] + 1;
    int p1 = ms[be*Mv + 1] + 1;
    int p2 = ms[be*Mv + 2] + 1;
    const float* base = att + (size_t)(b*NHv + h)*Lv*Lv;
    const float* a0 = base + (size_t)p0*Lv;
    const float* a1 = base + (size_t)p1*Lv;
    const float* a2 = base + (size_t)p2*Lv;
    float* o = g_eatt + (size_t)(be*NHv + h)*Lv;
    for (int l = threadIdx.x; l < Lv; l += blockDim.x)
        o[l] = (a0[l] + a1[l] + a2[l]) * (1.0f/3.0f);
}

// ---------------- K2: gate ----------------------------------------------------
__global__ void k_gate()
{
    int be = blockIdx.x;
    __shared__ float s[Lv];
    __shared__ float red[256];
    float part = 0.f;
    for (int l = threadIdx.x; l < Lv; l += 256) {
        float v = 0.f;
        #pragma unroll
        for (int h = 0; h < NHv; h++)
            v += g_eatt[((size_t)(be*NHv + h))*Lv + l];
        s[l] = v;
        part += v;
    }
    red[threadIdx.x] = part;
    __syncthreads();
    for (int st = 128; st > 0; st >>= 1) {
        if (threadIdx.x < st) red[threadIdx.x] += red[threadIdx.x + st];
        __syncthreads();
    }
    float inv = 1.0f / red[0];
    for (int l = threadIdx.x; l < Lv; l += 256)
        g_gate[be*Lv + l] = s[l] * inv;
}

// ---------------- K3: e_emb ----------------------------------------------------
__global__ void k_eemb(const float* __restrict__ seq, const int* __restrict__ ms,
                       const int* __restrict__ cs)
{
    int be = blockIdx.x;
    int b  = be / NEv;
    int d  = threadIdx.x;
    __shared__ int   sp[Mv];
    __shared__ int   scs[NCv];
    __shared__ float sg[NCv][CWv];
    if (threadIdx.x < Mv)  sp[threadIdx.x]  = ms[be*Mv + threadIdx.x] + 1;
    if (threadIdx.x < NCv) scs[threadIdx.x] = cs[be*NCv + threadIdx.x];
    __syncthreads();
    if (threadIdx.x < NCv*CWv) {
        int c = threadIdx.x / CWv, w = threadIdx.x % CWv;
        sg[c][w] = g_gate[be*Lv + scs[c] + w];
    }
    __syncthreads();

    float x[Mv + NCv];
    #pragma unroll
    for (int m = 0; m < Mv; m++)
        x[m] = seq[((size_t)b*Lv + sp[m])*Hv + d];
    #pragma unroll
    for (int c = 0; c < NCv; c++) {
        float acc = 0.f;
        int basel = scs[c];
        #pragma unroll
        for (int w = 0; w < CWv; w++)
            acc += sg[c][w] * seq[((size_t)b*Lv + basel + w)*Hv + d];
        x[Mv + c] = acc;
    }
    float mx = x[0];
    #pragma unroll
    for (int i = 1; i < Mv + NCv; i++) mx = fmaxf(mx, x[i]);
    float ssum = 0.f;
    #pragma unroll
    for (int i = 0; i < Mv + NCv; i++) ssum += expf(x[i] - mx);
    g_eemb[be*Hv + d] = mx + logf(ssum);
}

// ---------------- K4: ht (emits split-bf16 directly) ---------------------------
__global__ void k_ht()
{
    int ef = blockIdx.x;
    int b  = blockIdx.y;
    int e = ef / NEv, f = ef % NEv;
    __shared__ float s[Lv];
    __shared__ float red[256];
    const float* pe = g_eatt + (size_t)((b*NEv + e)*NHv)*Lv;
    const float* pf = g_eatt + (size_t)((b*NEv + f)*NHv)*Lv;
    float part = 0.f;
    for (int l = threadIdx.x; l < Lv; l += 256) {
        float v = 0.f;
        #pragma unroll
        for (int h = 0; h < NHv; h++)
            v += pe[h*Lv + l] * pf[h*Lv + l];
        v = fmaxf(v, 0.f);
        s[l] = v;
        part += v;
    }
    red[threadIdx.x] = part;
    __syncthreads();
    for (int st = 128; st > 0; st >>= 1) {
        if (threadIdx.x < st) red[threadIdx.x] += red[threadIdx.x + st];
        __syncthreads();
    }
    float inv = 1.0f / (red[0] + 1e-10f);
    size_t off = ((size_t)b*NPAIR + ef)*Lv;
    for (int l = threadIdx.x; l < Lv; l += 256) {
        __nv_bfloat16 h, lo; split_bf16(s[l]*inv, h, lo);
        g_hth[off + l] = h;
        g_htl[off + l] = lo;
    }
}

// ---------------- fp32 tiled GEMM (for U only) ----------------------------------
template<int TM, int RT, bool BT>
__global__ void __launch_bounds__(256) k_gemm(
    const float* __restrict__ A, const float* __restrict__ Bm, float* __restrict__ C,
    int Mr, int Kd, int lda, int ldb, int ldc,
    long long sA, long long sB, long long sC)
{
    constexpr int APAD = (TM == 128) ? 136 : 20;
    A  += (long long)blockIdx.z * sA;
    Bm += (long long)blockIdx.z * sB;
    C  += (long long)blockIdx.z * sC;

    __shared__ __align__(16) float As[16*APAD];
    __shared__ __align__(16) float Bs[16*68];

    const int tid = threadIdx.x;
    const int tx = tid & 15;
    const int ty = tid >> 4;
    const int row0 = blockIdx.y * TM;
    const int col0 = blockIdx.x * 64;

    const int a_k = tid & 15;
    const int a_r = tid >> 4;

    float acc[RT][4] = {};
    float ra[TM/16], rb[4];

    auto loadA = [&](int k0) {
        #pragma unroll
        for (int t = 0; t < TM/16; t++) {
            int gr = row0 + a_r + t*16;
            ra[t] = (gr < Mr) ? A[(long long)gr*lda + (k0 + a_k)] : 0.f;
        }
    };
    auto loadB = [&](int k0) {
        if (BT) {
            #pragma unroll
            for (int t = 0; t < 4; t++)
                rb[t] = Bm[(long long)(col0 + a_r + t*16)*ldb + (k0 + a_k)];
        } else {
            #pragma unroll
            for (int t = 0; t < 4; t++)
                rb[t] = Bm[(long long)(k0 + (tid>>6) + t*4)*ldb + col0 + (tid&63)];
        }
    };
    auto storeAB = [&]() {
        #pragma unroll
        for (int t = 0; t < TM/16; t++)
            As[a_k*APAD + a_r + t*16] = ra[t];
        if (BT) {
            #pragma unroll
            for (int t = 0; t < 4; t++)
                Bs[a_k*68 + a_r + t*16] = rb[t];
        } else {
            #pragma unroll
            for (int t = 0; t < 4; t++)
                Bs[((tid>>6) + t*4)*68 + (tid&63)] = rb[t];
        }
    };

    loadA(0); loadB(0);
    for (int k0 = 0; k0 < Kd; k0 += 16) {
        storeAB();
        __syncthreads();
        if (k0 + 16 < Kd) { loadA(k0 + 16); loadB(k0 + 16); }
        #pragma unroll
        for (int kk = 0; kk < 16; kk++) {
            float av[RT];
            if constexpr (RT == 8) {
                float4 a0 = *reinterpret_cast<const float4*>(&As[kk*APAD + ty*8]);
                float4 a1 = *reinterpret_cast<const float4*>(&As[kk*APAD + ty*8 + 4]);
                av[0]=a0.x; av[1]=a0.y; av[2]=a0.z; av[3]=a0.w;
                av[4]=a1.x; av[5]=a1.y; av[6]=a1.z; av[7]=a1.w;
            } else {
                av[0] = As[kk*APAD + ty];
            }
            float4 b4 = *reinterpret_cast<const float4*>(&Bs[kk*68 + tx*4]);
            #pragma unroll
            for (int i = 0; i < RT; i++) {
                acc[i][0] += av[i]*b4.x; acc[i][1] += av[i]*b4.y;
                acc[i][2] += av[i]*b4.z; acc[i][3] += av[i]*b4.w;
            }
        }
        __syncthreads();
    }

    #pragma unroll
    for (int i = 0; i < RT; i++) {
        int gr = row0 + ty*RT + i;
        if (gr < Mr) {
            #pragma unroll
            for (int j = 0; j < 4; j++)
                C[(long long)gr*ldc + col0 + tx*4 + j] = acc[i][j];
        }
    }
}

// ---------------- K6: zh/zt = tanh(U + V + bias) -------------------------------
__global__ void k_tanh(const float* __restrict__ bh, const float* __restrict__ bt)
{
    int idx = blockIdx.x*256 + threadIdx.x;
    if (idx >= ROWS*Hv) return;
    int d  = idx % Hv;
    int r  = idx / Hv;
    int f  = r % NEv;
    int be = r / NEv;
    int b  = be / NEv;
    g_zh[idx] = tanhf(g_uh[be*Hv + d]          + g_v[idx]                    + bh[d]);
    g_zt[idx] = tanhf(g_ut[(b*NEv + f)*Hv + d] + g_v[(size_t)ROWS*Hv + idx]  + bt[d]);
}

// ---------------- conversions ---------------------------------------------------
// Wp [768 x 49152] fp32 -> WpT hi/lo [49152 x 768]
__global__ void k_wpt(const float* __restrict__ Wp)
{
    __shared__ float t[32][33];
    int n0 = blockIdx.x*32, k0 = blockIdx.y*32;
    int tx = threadIdx.x, ty = threadIdx.y;   // 32 x 8
    #pragma unroll
    for (int q = 0; q < 4; q++)
        t[ty + q*8][tx] = Wp[(size_t)(k0 + ty + q*8)*WCN + n0 + tx];
    __syncthreads();
    #pragma unroll
    for (int q = 0; q < 4; q++) {
        int n = ty + q*8;
        float v = t[tx][n];
        __nv_bfloat16 h, l; split_bf16(v, h, l);
        g_wpth[(size_t)(n0 + n)*Hv + k0 + tx] = h;
        g_wptl[(size_t)(n0 + n)*Hv + k0 + tx] = l;
    }
}

// seq [b, l, d] fp32 -> seqT hi/lo [b, d, l]
__global__ void k_seqt(const float* __restrict__ seq)
{
    __shared__ float t[32][33];
    int l0 = blockIdx.x*32, d0 = blockIdx.y*32, b = blockIdx.z;
    int tx = threadIdx.x, ty = threadIdx.y;   // 32 x 8
    #pragma unroll
    for (int q = 0; q < 4; q++)
        t[ty + q*8][tx] = seq[((size_t)b*Lv + l0 + ty + q*8)*Hv + d0 + tx];
    __syncthreads();
    #pragma unroll
    for (int q = 0; q < 4; q++) {
        int d = ty + q*8;
        float v = t[tx][d];
        __nv_bfloat16 h, l; split_bf16(v, h, l);
        g_sqh[((size_t)b*Hv + d0 + d)*Lv + l0 + tx] = h;
        g_sql[((size_t)b*Hv + d0 + d)*Lv + l0 + tx] = l;
    }
}

// Wcls [97 x 768] -> padded [128 x 768] hi/lo
__global__ void k_wcls_conv(const float* __restrict__ Wcls)
{
    int idx = blockIdx.x*256 + threadIdx.x;
    if (idx >= 128*Hv) return;
    int r = idx / Hv, c = idx % Hv;
    float v = (r < NCLSv) ? Wcls[r*Hv + c] : 0.f;
    __nv_bfloat16 h, l; split_bf16(v, h, l);
    g_wclsh[idx] = h;
    g_wclsl[idx] = l;
}

// W_head/W_tail cols [H, H:2H] -> hi/lo [2][768][768]
__global__ void k_whx(const float* __restrict__ Wh, const float* __restrict__ Wt)
{
    int idx = blockIdx.x*256 + threadIdx.x;
    if (idx >= 2*Hv*Hv) return;
    int z = idx / (Hv*Hv);
    int rem = idx - z*Hv*Hv;
    int d = rem / Hv, k = rem % Hv;
    const float* W = z ? Wt : Wh;
    float v = W[(size_t)d*(2*Hv) + Hv + k];
    __nv_bfloat16 h, l; split_bf16(v, h, l);
    g_whxh[idx] = h;
    g_whxl[idx] = l;
}

// ---------------- mma.sync split-bf16 core ---------------------------------------
// pA -> Ah tile (Al at +TILE_B); pB -> Bh tile (Bl at +TILE_B). 8 warps, 64x32 warp tile.
__device__ __forceinline__ void compute_core(const char* pA, const char* pB,
    float acc[4][4][4], int lane, int wm, int wn)
{
    #pragma unroll
    for (int ks = 0; ks < 4; ks++) {
        const int k0 = ks*16 + (lane & 3)*2;
        uint32_t bh[4][2], bl[4][2];
        #pragma unroll
        for (int nf = 0; nf < 4; nf++) {
            int n = wn*32 + nf*8 + (lane >> 2);
            const char* ph = pB + n*(TS*2) + k0*2;
            const char* pl = ph + TILE_B;
            bh[nf][0] = *(const uint32_t*)ph;
            bh[nf][1] = *(const uint32_t*)(ph + 16);
            bl[nf][0] = *(const uint32_t*)pl;
            bl[nf][1] = *(const uint32_t*)(pl + 16);
        }
        #pragma unroll
        for (int mf = 0; mf < 4; mf++) {
            int r = wm*64 + mf*16 + (lane >> 2);
            const char* pa = pA + r*(TS*2) + k0*2;
            const char* pb = pa + TILE_B;
            uint32_t ah0 = *(const uint32_t*)pa;
            uint32_t ah1 = *(const uint32_t*)(pa + TS*16);
            uint32_t ah2 = *(const uint32_t*)(pa + 16);
            uint32_t ah3 = *(const uint32_t*)(pa + TS*16 + 16);
            uint32_t al0 = *(const uint32_t*)pb;
            uint32_t al1 = *(const uint32_t*)(pb + TS*16);
            uint32_t al2 = *(const uint32_t*)(pb + 16);
            uint32_t al3 = *(const uint32_t*)(pb + TS*16 + 16);
            #pragma unroll
            for (int nf = 0; nf < 4; nf++) {
                mma16816(acc[mf][nf], ah0, ah1, ah2, ah3, bh[nf][0], bh[nf][1]);
                mma16816(acc[mf][nf], ah0, ah1, ah2, ah3, bl[nf][0], bl[nf][1]);
                mma16816(acc[mf][nf], al0, al1, al2, al3, bh[nf][0], bh[nf][1]);
            }
        }
    }
}

// ---------------- generic split-bf16 GEMM: C = A @ B^T ---------------------------
// A [M x K] row-major hi/lo (rows clamped to Mr), B [N x K] row-major hi/lo.
// grid: x over N/128, y over ceil(M/128), z batch. OUT: 0 = fp32 C, 1 = split-bf16.
template<int OUT>
__global__ __launch_bounds__(256, 1) void k_mma_g(
    const __nv_bfloat16* __restrict__ Ah, const __nv_bfloat16* __restrict__ Al, int lda, long long sA,
    const __nv_bfloat16* __restrict__ Bh, const __nv_bfloat16* __restrict__ Bl, int ldb, long long sB,
    float* __restrict__ Cf, __nv_bfloat16* __restrict__ Ch, __nv_bfloat16* __restrict__ Cl,
    int ldc, long long sC, int Mr, int niter)
{
    extern __shared__ char smem[];
    const int tid = threadIdx.x, lane = tid & 31, w = tid >> 5;
    const int wm = w >> 2, wn = w & 3;
    const int row0 = blockIdx.y * 128;
    const int n0   = blockIdx.x * 128;

    Ah += (long long)blockIdx.z * sA;  Al += (long long)blockIdx.z * sA;
    Bh += (long long)blockIdx.z * sB + (size_t)n0*ldb;
    Bl += (long long)blockIdx.z * sB + (size_t)n0*ldb;
    const long long coff = (long long)blockIdx.z * sC;

    uint32_t sb = smem_u32(smem);

    auto issue = [&](int s, int it) {
        uint32_t st = sb + s*STAGE_B;
        const __nv_bfloat16* ah = Ah + it*64;
        const __nv_bfloat16* al = Al + it*64;
        const __nv_bfloat16* bh = Bh + it*64;
        const __nv_bfloat16* bl = Bl + it*64;
        #pragma unroll
        for (int t = 0; t < 4; t++) {
            int idx = tid + t*256;
            int row = idx >> 3, ch = idx & 7;
            uint32_t off = row*(TS*2) + ch*16;
            int ar = row0 + row; if (ar >= Mr) ar = Mr - 1;
            cpasync16(st +            off, ah + (size_t)ar*lda + ch*8);
            cpasync16(st +   TILE_B + off, al + (size_t)ar*lda + ch*8);
            cpasync16(st + 2*TILE_B + off, bh + (size_t)row*ldb + ch*8);
            cpasync16(st + 3*TILE_B + off, bl + (size_t)row*ldb + ch*8);
        }
        CP_COMMIT();
    };

    float acc[4][4][4] = {};
    issue(0, 0);
    for (int it = 0; it < niter; it++) {
        if (it + 1 < niter) { issue((it + 1) & 1, it + 1); CP_WAIT(1); }
        else                { CP_WAIT(0); }
        __syncthreads();
        const char* base = smem + (it & 1)*STAGE_B;
        compute_core(base, base + 2*TILE_B, acc, lane, wm, wn);
        __syncthreads();
    }

    #pragma unroll
    for (int mf = 0; mf < 4; mf++) {
        int r = row0 + wm*64 + mf*16 + (lane >> 2);
        #pragma unroll
        for (int nf = 0; nf < 4; nf++) {
            int cb = n0 + wn*32 + nf*8 + (lane & 3)*2;
            if (OUT == 0) {
                if (r < Mr) {
                    Cf[coff + (long long)r*ldc + cb]     = acc[mf][nf][0];
                    Cf[coff + (long long)r*ldc + cb + 1] = acc[mf][nf][1];
                }
                if (r + 8 < Mr) {
                    Cf[coff + (long long)(r + 8)*ldc + cb]     = acc[mf][nf][2];
                    Cf[coff + (long long)(r + 8)*ldc + cb + 1] = acc[mf][nf][3];
                }
            } else {
                __nv_bfloat16 h0, l0, h1, l1;
                if (r < Mr) {
                    split_bf16(acc[mf][nf][0], h0, l0);
                    split_bf16(acc[mf][nf][1], h1, l1);
                    *reinterpret_cast<uint32_t*>(Ch + coff + (long long)r*ldc + cb) = pack2(h0, h1);
                    *reinterpret_cast<uint32_t*>(Cl + coff + (long long)r*ldc + cb) = pack2(l0, l1);
                }
                if (r + 8 < Mr) {
                    split_bf16(acc[mf][nf][2], h0, l0);
                    split_bf16(acc[mf][nf][3], h1, l1);
                    *reinterpret_cast<uint32_t*>(Ch + coff + (long long)(r + 8)*ldc + cb) = pack2(h0, h1);
                    *reinterpret_cast<uint32_t*>(Cl + coff + (long long)(r + 8)*ldc + cb) = pack2(l0, l1);
                }
            }
        }
    }
}

// ---------------- fused logits kernel ---------------------------------------------
// grid (ROWS/128 = 9, KCH = 16). Each block: 128 rows x 128 classes over 48 K-chunks.
// A tiles generated in smem from zh/zt (rank-1 products), B = Wc hi/lo via cp.async.
__global__ __launch_bounds__(256, 1) void k_logits_f()
{
    extern __shared__ char smem[];
    uint32_t sb = smem_u32(smem);
    float* zhs = (float*)(smem + LZH_OFF);   // [128][65]
    float* zts = (float*)(smem + LZT_OFF);   // [128][66]
    const int tid = threadIdx.x, lane = tid & 31, w = tid >> 5;
    const int wm = w >> 2, wn = w & 3;
    const int row0 = blockIdx.x * 128;
    const int c0   = blockIdx.y * 48;        // chunk index in [0, 768)

    auto issueB = [&](int s, int c) {
        uint32_t st = sb + s*LB_STG;
        const __nv_bfloat16* bh = g_wch + (size_t)c*64;
        const __nv_bfloat16* bl = g_wcl + (size_t)c*64;
        #pragma unroll
        for (int t = 0; t < 4; t++) {
            int idx = tid + t*256;
            int row = idx >> 3, ch = idx & 7;
            uint32_t off = row*(TS*2) + ch*16;
            cpasync16(st +          off, bh + (size_t)row*WCN + ch*8);
            cpasync16(st + TILE_B + off, bl + (size_t)row*WCN + ch*8);
        }
        CP_COMMIT();
    };

    float acc[4][4][4] = {};
    issueB(0, c0);
    int kcur = -1;
    for (int it = 0; it < 48; it++) {
        int c = c0 + it, s = it & 1;
        if (it + 1 < 48) { issueB(s ^ 1, c + 1); CP_WAIT(1); }
        else             { CP_WAIT(0); }
        int k = c >> 6;
        if (k != kcur) {
            for (int idx = tid; idx < 8192; idx += 256) {
                int r = idx >> 6, cc = idx & 63;
                zhs[r*65 + cc] = g_zh[(size_t)(row0 + r)*Hv + k*64 + cc];
                zts[r*66 + cc] = g_zt[(size_t)(row0 + r)*Hv + k*64 + cc];
            }
            kcur = k;
            __syncthreads();
        }
        // generate A tile: A[r, j] = zh[r, k*64+i] * zt[r, k*64+j], i = c & 63
        {
            int i  = c & 63;
            int r  = tid >> 1;
            int j0 = (tid & 1) << 5;
            float a = zhs[r*65 + i];
            char* pA = smem + LA_BASE + s*LB_STG + r*(TS*2);
            #pragma unroll
            for (int j = 0; j < 32; j += 2) {
                float v0 = a * zts[r*66 + j0 + j];
                float v1 = a * zts[r*66 + j0 + j + 1];
                __nv_bfloat16 h0, l0, h1, l1;
                split_bf16(v0, h0, l0); split_bf16(v1, h1, l1);
                *(uint32_t*)(pA +          (j0 + j)*2) = pack2(h0, h1);
                *(uint32_t*)(pA + TILE_B + (j0 + j)*2) = pack2(l0, l1);
            }
        }
        __syncthreads();
        compute_core(smem + LA_BASE + s*LB_STG, smem + s*LB_STG, acc, lane, wm, wn);
        __syncthreads();
    }

    float* outk = g_lpart + (size_t)blockIdx.y*ROWS*NCLSv;
    #pragma unroll
    for (int mf = 0; mf < 4; mf++) {
        int r = row0 + wm*64 + mf*16 + (lane >> 2);
        #pragma unroll
        for (int nf = 0; nf < 4; nf++) {
            int cc = wn*32 + nf*8 + (lane & 3)*2;
            if (cc < NCLSv)     outk[(size_t)r*NCLSv + cc]           = acc[mf][nf][0];
            if (cc + 1 < NCLSv) outk[(size_t)r*NCLSv + cc + 1]       = acc[mf][nf][1];
            if (cc < NCLSv)     outk[(size_t)(r + 8)*NCLSv + cc]     = acc[mf][nf][2];
            if (cc + 1 < NCLSv) outk[(size_t)(r + 8)*NCLSv + cc + 1] = acc[mf][nf][3];
        }
    }
}

// ---------------- K8: combine KCH k-partials + bias ----------------------------
__global__ void k_final(const float* __restrict__ bcls, float* __restrict__ out)
{
    int idx = blockIdx.x*256 + threadIdx.x;
    if (idx >= ROWS*NCLSv) return;
    int c = idx % NCLSv;
    float v = bcls[c];
    #pragma unroll
    for (int k = 0; k < KCH; k++)
        v += g_lpart[(size_t)k*ROWS*NCLSv + idx];
    out[idx] = v;
}

// ================================ launch ========================================
extern "C" void kernel_launch(void* const* d_in, const int* in_sizes, int n_in,
                              void* d_out, int out_size)
{
    const float* seq  = (const float*)d_in[0];
    const float* att  = (const float*)d_in[1];
    const int*   ms   = (const int*)  d_in[2];
    const int*   cs   = (const int*)  d_in[3];
    const float* Wh   = (const float*)d_in[4];
    const float* bh   = (const float*)d_in[5];
    const float* Wt   = (const float*)d_in[6];
    const float* bt   = (const float*)d_in[7];
    const float* Wp   = (const float*)d_in[8];
    const float* Wcls = (const float*)d_in[9];
    const float* bcls = (const float*)d_in[10];
    float* out = (float*)d_out;

    float *p_eemb, *p_uh, *p_ut, *p_v;
    __nv_bfloat16 *p_wpth, *p_wptl, *p_wclsh, *p_wclsl, *p_wch, *p_wcl;
    __nv_bfloat16 *p_hth, *p_htl, *p_sqh, *p_sql, *p_rsh, *p_rsl, *p_whxh, *p_whxl;
    cudaGetSymbolAddress((void**)&p_eemb,  g_eemb);
    cudaGetSymbolAddress((void**)&p_uh,    g_uh);
    cudaGetSymbolAddress((void**)&p_ut,    g_ut);
    cudaGetSymbolAddress((void**)&p_v,     g_v);
    cudaGetSymbolAddress((void**)&p_wpth,  g_wpth);
    cudaGetSymbolAddress((void**)&p_wptl,  g_wptl);
    cudaGetSymbolAddress((void**)&p_wclsh, g_wclsh);
    cudaGetSymbolAddress((void**)&p_wclsl, g_wclsl);
    cudaGetSymbolAddress((void**)&p_wch,   g_wch);
    cudaGetSymbolAddress((void**)&p_wcl,   g_wcl);
    cudaGetSymbolAddress((void**)&p_hth,   g_hth);
    cudaGetSymbolAddress((void**)&p_htl,   g_htl);
    cudaGetSymbolAddress((void**)&p_sqh,   g_sqh);
    cudaGetSymbolAddress((void**)&p_sql,   g_sql);
    cudaGetSymbolAddress((void**)&p_rsh,   g_rsh);
    cudaGetSymbolAddress((void**)&p_rsl,   g_rsl);
    cudaGetSymbolAddress((void**)&p_whxh,  g_whxh);
    cudaGetSymbolAddress((void**)&p_whxl,  g_whxl);

    cudaFuncSetAttribute(k_mma_g<0>, cudaFuncAttributeMaxDynamicSharedMemorySize, SMEMB);
    cudaFuncSetAttribute(k_mma_g<1>, cudaFuncAttributeMaxDynamicSharedMemorySize, SMEMB);
    cudaFuncSetAttribute(k_logits_f, cudaFuncAttributeMaxDynamicSharedMemorySize, LSMEM);

    // --- weight conversions ---
    k_wpt<<<dim3(WCN/32, Hv/32), dim3(32, 8)>>>(Wp);
    k_wcls_conv<<<(128*Hv + 255)/256, 256>>>(Wcls);
    k_whx<<<(2*Hv*Hv + 255)/256, 256>>>(Wh, Wt);
    k_seqt<<<dim3(Lv/32, Hv/32, Bv), dim3(32, 8)>>>(seq);

    // Wc = Wcls_pad @ WpT^T  -> split bf16   [128 x 49152]
    k_mma_g<1><<<dim3(WCN/128, 1, 1), 256, SMEMB>>>(
        p_wclsh, p_wclsl, Hv, 0, p_wpth, p_wptl, Hv, 0,
        nullptr, p_wch, p_wcl, WCN, 0, 128, Hv/64);

    // --- attention path ---
    k_eatt<<<Bv*NEv*NHv, 256>>>(att, ms);
    k_gate<<<Bv*NEv, 256>>>();
    k_eemb<<<Bv*NEv, Hv>>>(seq, ms, cs);
    k_ht<<<dim3(NPAIR, Bv), 256>>>();

    // rs = ht @ seqT^T  -> split bf16  (per batch: 576 x 768, K=1024)
    k_mma_g<1><<<dim3(Hv/128, 5, Bv), 256, SMEMB>>>(
        p_hth, p_htl, Lv, (long long)NPAIR*Lv,
        p_sqh, p_sql, Lv, (long long)Hv*Lv,
        nullptr, p_rsh, p_rsl, Hv, (long long)NPAIR*Hv, NPAIR, Lv/64);

    // U = e_emb @ W[:, :H]^T  (fp32, tiny; head/tail via z-stride)
    k_gemm<16,1,true><<<dim3(Hv/64, 3, 2), 256>>>(
        p_eemb, Wh, p_uh, Bv*NEv, Hv, Hv, 2*Hv, Hv,
        0, (long long)(Wt - Wh), (long long)(p_ut - p_uh));

    // V = rs @ Whx^T  -> fp32  (head/tail via z-stride)
    k_mma_g<0><<<dim3(Hv/128, ROWS/128, 2), 256, SMEMB>>>(
        p_rsh, p_rsl, Hv, 0,
        p_whxh, p_whxl, Hv, (long long)Hv*Hv,
        p_v, nullptr, nullptr, Hv, (long long)ROWS*Hv, ROWS, Hv/64);

    k_tanh<<<(ROWS*Hv + 255)/256, 256>>>(bh, bt);

    // --- fused logits (A generated in-kernel, split-K over 16 chunks) ---
    k_logits_f<<<dim3(ROWS/128, KCH), 256, LSMEM>>>();

    k_final<<<(ROWS*NCLSv + 255)/256, 256>>>(bcls, out);
}

// round 14
// speedup vs baseline: 8.3285x; 1.0233x over previous
#include <cuda_runtime.h>
#include <cuda_bf16.h>
#include <math.h>
#include <stdint.h>

#define Bv    2
#define Lv    1024
#define Hv    768
#define NHv   12
#define NEv   24
#define Mv    3
#define NCv   2
#define CWv   8
#define NCLSv 97
#define NPAIR (NEv*NEv)       /* 576 */
#define ROWS  (Bv*NPAIR)      /* 1152 */
#define WCN   (Hv*64)         /* 49152 */
#define KCH   16              /* K-chunks for logits split-K */

// MMA tile constants
#define TS      72            /* smem row stride in bf16 (144B) */
#define TILE_B  (128*TS*2)    /* 18432 B per 128x64 bf16 tile */
#define STAGE_B (4*TILE_B)    /* Ah, Al, Bh, Bl */
#define SMEMB   (2*STAGE_B)   /* 147456 B */
// fp32 B staging (for in-kernel transpose+split of row-major fp32 weights)
#define FST_OFF (2*STAGE_B)            /* 147456 */
#define FST_STG (64*132*4)             /* 33792 B: [64 k][132 n] fp32 */
#define SMEM_T  (FST_OFF + 2*FST_STG)  /* 215040 */

// fused logits kernel smem layout
#define LB_STG  (2*TILE_B)            /* 36864: Bh+Bl per stage */
#define LA_BASE (2*LB_STG)            /* 73728 */
#define LZH_OFF (LA_BASE + 2*LB_STG)  /* 147456 */
#define LZT_OFF (LZH_OFF + 128*65*4)  /* 180736 */
#define LSMEM   (LZT_OFF + 128*66*4)  /* 214528 */

__device__ __forceinline__ uint32_t smem_u32(const void* p) {
    uint32_t a;
    asm("{ .reg .u64 t; cvta.to.shared.u64 t, %1; cvt.u32.u64 %0, t; }" : "=r"(a) : "l"(p));
    return a;
}
__device__ __forceinline__ void cpasync16(uint32_t dst, const void* src) {
    asm volatile("cp.async.cg.shared.global [%0], [%1], 16;" :: "r"(dst), "l"(src) : "memory");
}
#define CP_COMMIT() asm volatile("cp.async.commit_group;" ::: "memory")
#define CP_WAIT(n)  asm volatile("cp.async.wait_group %0;" :: "n"(n) : "memory")

__device__ __forceinline__ void mma16816(float* d,
    uint32_t a0, uint32_t a1, uint32_t a2, uint32_t a3, uint32_t b0, uint32_t b1)
{
    asm volatile(
        "mma.sync.aligned.m16n8k16.row.col.f32.bf16.bf16.f32 "
        "{%0,%1,%2,%3}, {%4,%5,%6,%7}, {%8,%9}, {%0,%1,%2,%3};"
        : "+f"(d[0]), "+f"(d[1]), "+f"(d[2]), "+f"(d[3])
        : "r"(a0), "r"(a1), "r"(a2), "r"(a3), "r"(b0), "r"(b1));
}
__device__ __forceinline__ void split_bf16(float v, __nv_bfloat16& h, __nv_bfloat16& l) {
    h = __float2bfloat16(v);
    l = __float2bfloat16(v - __bfloat162float(h));
}
__device__ __forceinline__ uint32_t pack2(__nv_bfloat16 a, __nv_bfloat16 b) {
    return (uint32_t)__bfloat16_as_ushort(a) | ((uint32_t)__bfloat16_as_ushort(b) << 16);
}

// ---------------- scratch (static device memory; no allocations) -------------
__device__ float g_eatt[Bv*NEv*NHv*Lv];
__device__ float g_gate[Bv*NEv*Lv];
__device__ float g_eemb[Bv*NEv*Hv];
__device__ float g_uh[Bv*NEv*Hv];
__device__ float g_ut[Bv*NEv*Hv];
__device__ float g_zh[(size_t)ROWS*Hv];
__device__ float g_zt[(size_t)ROWS*Hv];
__device__ float g_lpart[(size_t)KCH*ROWS*NCLSv];

__device__ __align__(16) __nv_bfloat16 g_wclsh[128*Hv];
__device__ __align__(16) __nv_bfloat16 g_wclsl[128*Hv];
__device__ __align__(16) __nv_bfloat16 g_wch[(size_t)128*WCN];
__device__ __align__(16) __nv_bfloat16 g_wcl[(size_t)128*WCN];
__device__ __align__(16) __nv_bfloat16 g_hth[(size_t)Bv*NPAIR*Lv];
__device__ __align__(16) __nv_bfloat16 g_htl[(size_t)Bv*NPAIR*Lv];
__device__ __align__(16) __nv_bfloat16 g_rsh[(size_t)ROWS*Hv];
__device__ __align__(16) __nv_bfloat16 g_rsl[(size_t)ROWS*Hv];
__device__ __align__(16) __nv_bfloat16 g_whxh[2*(size_t)Hv*Hv];
__device__ __align__(16) __nv_bfloat16 g_whxl[2*(size_t)Hv*Hv];

// ---------------- K1: e_att ----------------------------------------------------
__global__ void k_eatt(const float* __restrict__ att, const int* __restrict__ ms)
{
    int bh = blockIdx.x;
    int h  = bh % NHv;
    int be = bh / NHv;
    int b  = be / NEv;
    int p0 = ms[be*Mv + 0] + 1;
    int p1 = ms[be*Mv + 1] + 1;
    int p2 = ms[be*Mv + 2] + 1;
    const float* base = att + (size_t)(b*NHv + h)*Lv*Lv;
    const float* a0 = base + (size_t)p0*Lv;
    const float* a1 = base + (size_t)p1*Lv;
    const float* a2 = base + (size_t)p2*Lv;
    float* o = g_eatt + (size_t)(be*NHv + h)*Lv;
    for (int l = threadIdx.x; l < Lv; l += blockDim.x)
        o[l] = (a0[l] + a1[l] + a2[l]) * (1.0f/3.0f);
}

// ---------------- K2: gate ----------------------------------------------------
__global__ void k_gate()
{
    int be = blockIdx.x;
    __shared__ float s[Lv];
    __shared__ float red[256];
    float part = 0.f;
    for (int l = threadIdx.x; l < Lv; l += 256) {
        float v = 0.f;
        #pragma unroll
        for (int h = 0; h < NHv; h++)
            v += g_eatt[((size_t)(be*NHv + h))*Lv + l];
        s[l] = v;
        part += v;
    }
    red[threadIdx.x] = part;
    __syncthreads();
    for (int st = 128; st > 0; st >>= 1) {
        if (threadIdx.x < st) red[threadIdx.x] += red[threadIdx.x + st];
        __syncthreads();
    }
    float inv = 1.0f / red[0];
    for (int l = threadIdx.x; l < Lv; l += 256)
        g_gate[be*Lv + l] = s[l] * inv;
}

// ---------------- K3: e_emb ----------------------------------------------------
__global__ void k_eemb(const float* __restrict__ seq, const int* __restrict__ ms,
                       const int* __restrict__ cs)
{
    int be = blockIdx.x;
    int b  = be / NEv;
    int d  = threadIdx.x;
    __shared__ int   sp[Mv];
    __shared__ int   scs[NCv];
    __shared__ float sg[NCv][CWv];
    if (threadIdx.x < Mv)  sp[threadIdx.x]  = ms[be*Mv + threadIdx.x] + 1;
    if (threadIdx.x < NCv) scs[threadIdx.x] = cs[be*NCv + threadIdx.x];
    __syncthreads();
    if (threadIdx.x < NCv*CWv) {
        int c = threadIdx.x / CWv, w = threadIdx.x % CWv;
        sg[c][w] = g_gate[be*Lv + scs[c] + w];
    }
    __syncthreads();

    float x[Mv + NCv];
    #pragma unroll
    for (int m = 0; m < Mv; m++)
        x[m] = seq[((size_t)b*Lv + sp[m])*Hv + d];
    #pragma unroll
    for (int c = 0; c < NCv; c++) {
        float acc = 0.f;
        int basel = scs[c];
        #pragma unroll
        for (int w = 0; w < CWv; w++)
            acc += sg[c][w] * seq[((size_t)b*Lv + basel + w)*Hv + d];
        x[Mv + c] = acc;
    }
    float mx = x[0];
    #pragma unroll
    for (int i = 1; i < Mv + NCv; i++) mx = fmaxf(mx, x[i]);
    float ssum = 0.f;
    #pragma unroll
    for (int i = 0; i < Mv + NCv; i++) ssum += expf(x[i] - mx);
    g_eemb[be*Hv + d] = mx + logf(ssum);
}

// ---------------- K4: ht (emits split-bf16 directly) ---------------------------
__global__ void k_ht()
{
    int ef = blockIdx.x;
    int b  = blockIdx.y;
    int e = ef / NEv, f = ef % NEv;
    __shared__ float s[Lv];
    __shared__ float red[256];
    const float* pe = g_eatt + (size_t)((b*NEv + e)*NHv)*Lv;
    const float* pf = g_eatt + (size_t)((b*NEv + f)*NHv)*Lv;
    float part = 0.f;
    for (int l = threadIdx.x; l < Lv; l += 256) {
        float v = 0.f;
        #pragma unroll
        for (int h = 0; h < NHv; h++)
            v += pe[h*Lv + l] * pf[h*Lv + l];
        v = fmaxf(v, 0.f);
        s[l] = v;
        part += v;
    }
    red[threadIdx.x] = part;
    __syncthreads();
    for (int st = 128; st > 0; st >>= 1) {
        if (threadIdx.x < st) red[threadIdx.x] += red[threadIdx.x + st];
        __syncthreads();
    }
    float inv = 1.0f / (red[0] + 1e-10f);
    size_t off = ((size_t)b*NPAIR + ef)*Lv;
    for (int l = threadIdx.x; l < Lv; l += 256) {
        __nv_bfloat16 h, lo; split_bf16(s[l]*inv, h, lo);
        g_hth[off + l] = h;
        g_htl[off + l] = lo;
    }
}

// ---------------- fp32 tiled GEMM (for U only) ----------------------------------
template<int TM, int RT, bool BT>
__global__ void __launch_bounds__(256) k_gemm(
    const float* __restrict__ A, const float* __restrict__ Bm, float* __restrict__ C,
    int Mr, int Kd, int lda, int ldb, int ldc,
    long long sA, long long sB, long long sC)
{
    constexpr int APAD = (TM == 128) ? 136 : 20;
    A  += (long long)blockIdx.z * sA;
    Bm += (long long)blockIdx.z * sB;
    C  += (long long)blockIdx.z * sC;

    __shared__ __align__(16) float As[16*APAD];
    __shared__ __align__(16) float Bs[16*68];

    const int tid = threadIdx.x;
    const int tx = tid & 15;
    const int ty = tid >> 4;
    const int row0 = blockIdx.y * TM;
    const int col0 = blockIdx.x * 64;

    const int a_k = tid & 15;
    const int a_r = tid >> 4;

    float acc[RT][4] = {};
    float ra[TM/16], rb[4];

    auto loadA = [&](int k0) {
        #pragma unroll
        for (int t = 0; t < TM/16; t++) {
            int gr = row0 + a_r + t*16;
            ra[t] = (gr < Mr) ? A[(long long)gr*lda + (k0 + a_k)] : 0.f;
        }
    };
    auto loadB = [&](int k0) {
        if (BT) {
            #pragma unroll
            for (int t = 0; t < 4; t++)
                rb[t] = Bm[(long long)(col0 + a_r + t*16)*ldb + (k0 + a_k)];
        } else {
            #pragma unroll
            for (int t = 0; t < 4; t++)
                rb[t] = Bm[(long long)(k0 + (tid>>6) + t*4)*ldb + col0 + (tid&63)];
        }
    };
    auto storeAB = [&]() {
        #pragma unroll
        for (int t = 0; t < TM/16; t++)
            As[a_k*APAD + a_r + t*16] = ra[t];
        if (BT) {
            #pragma unroll
            for (int t = 0; t < 4; t++)
                Bs[a_k*68 + a_r + t*16] = rb[t];
        } else {
            #pragma unroll
            for (int t = 0; t < 4; t++)
                Bs[((tid>>6) + t*4)*68 + (tid&63)] = rb[t];
        }
    };

    loadA(0); loadB(0);
    for (int k0 = 0; k0 < Kd; k0 += 16) {
        storeAB();
        __syncthreads();
        if (k0 + 16 < Kd) { loadA(k0 + 16); loadB(k0 + 16); }
        #pragma unroll
        for (int kk = 0; kk < 16; kk++) {
            float av[RT];
            if constexpr (RT == 8) {
                float4 a0 = *reinterpret_cast<const float4*>(&As[kk*APAD + ty*8]);
                float4 a1 = *reinterpret_cast<const float4*>(&As[kk*APAD + ty*8 + 4]);
                av[0]=a0.x; av[1]=a0.y; av[2]=a0.z; av[3]=a0.w;
                av[4]=a1.x; av[5]=a1.y; av[6]=a1.z; av[7]=a1.w;
            } else {
                av[0] = As[kk*APAD + ty];
            }
            float4 b4 = *reinterpret_cast<const float4*>(&Bs[kk*68 + tx*4]);
            #pragma unroll
            for (int i = 0; i < RT; i++) {
                acc[i][0] += av[i]*b4.x; acc[i][1] += av[i]*b4.y;
                acc[i][2] += av[i]*b4.z; acc[i][3] += av[i]*b4.w;
            }
        }
        __syncthreads();
    }

    #pragma unroll
    for (int i = 0; i < RT; i++) {
        int gr = row0 + ty*RT + i;
        if (gr < Mr) {
            #pragma unroll
            for (int j = 0; j < 4; j++)
                C[(long long)gr*ldc + col0 + tx*4 + j] = acc[i][j];
        }
    }
}

// ---------------- conversions (small weights only) -------------------------------
// Wcls [97 x 768] -> padded [128 x 768] hi/lo
__global__ void k_wcls_conv(const float* __restrict__ Wcls)
{
    int idx = blockIdx.x*256 + threadIdx.x;
    if (idx >= 128*Hv) return;
    int r = idx / Hv, c = idx % Hv;
    float v = (r < NCLSv) ? Wcls[r*Hv + c] : 0.f;
    __nv_bfloat16 h, l; split_bf16(v, h, l);
    g_wclsh[idx] = h;
    g_wclsl[idx] = l;
}

// W_head/W_tail cols [H, H:2H] -> hi/lo [2][768][768]
__global__ void k_whx(const float* __restrict__ Wh, const float* __restrict__ Wt)
{
    int idx = blockIdx.x*256 + threadIdx.x;
    if (idx >= 2*Hv*Hv) return;
    int z = idx / (Hv*Hv);
    int rem = idx - z*Hv*Hv;
    int d = rem / Hv, k = rem % Hv;
    const float* W = z ? Wt : Wh;
    float v = W[(size_t)d*(2*Hv) + Hv + k];
    __nv_bfloat16 h, l; split_bf16(v, h, l);
    g_whxh[idx] = h;
    g_whxl[idx] = l;
}

// ---------------- mma.sync split-bf16 core ---------------------------------------
__device__ __forceinline__ void compute_core(const char* pA, const char* pB,
    float acc[4][4][4], int lane, int wm, int wn)
{
    #pragma unroll
    for (int ks = 0; ks < 4; ks++) {
        const int k0 = ks*16 + (lane & 3)*2;
        uint32_t bh[4][2], bl[4][2];
        #pragma unroll
        for (int nf = 0; nf < 4; nf++) {
            int n = wn*32 + nf*8 + (lane >> 2);
            const char* ph = pB + n*(TS*2) + k0*2;
            const char* pl = ph + TILE_B;
            bh[nf][0] = *(const uint32_t*)ph;
            bh[nf][1] = *(const uint32_t*)(ph + 16);
            bl[nf][0] = *(const uint32_t*)pl;
            bl[nf][1] = *(const uint32_t*)(pl + 16);
        }
        #pragma unroll
        for (int mf = 0; mf < 4; mf++) {
            int r = wm*64 + mf*16 + (lane >> 2);
            const char* pa = pA + r*(TS*2) + k0*2;
            const char* pb = pa + TILE_B;
            uint32_t ah0 = *(const uint32_t*)pa;
            uint32_t ah1 = *(const uint32_t*)(pa + TS*16);
            uint32_t ah2 = *(const uint32_t*)(pa + 16);
            uint32_t ah3 = *(const uint32_t*)(pa + TS*16 + 16);
            uint32_t al0 = *(const uint32_t*)pb;
            uint32_t al1 = *(const uint32_t*)(pb + TS*16);
            uint32_t al2 = *(const uint32_t*)(pb + 16);
            uint32_t al3 = *(const uint32_t*)(pb + TS*16 + 16);
            #pragma unroll
            for (int nf = 0; nf < 4; nf++) {
                mma16816(acc[mf][nf], ah0, ah1, ah2, ah3, bh[nf][0], bh[nf][1]);
                mma16816(acc[mf][nf], ah0, ah1, ah2, ah3, bl[nf][0], bl[nf][1]);
                mma16816(acc[mf][nf], al0, al1, al2, al3, bh[nf][0], bh[nf][1]);
            }
        }
    }
}

// ---------------- unified split-bf16 GEMM: C = A @ B^T ----------------------------
// A [M x K] presplit hi/lo, row-clamped to Mr.
// BSRC=0: B [N x K] presplit hi/lo (ldb, z-stride sB).
// BSRC=1: B[n,k] = Wf[k, n] with Wf fp32 row-major [K x ldw] (z-stride sW);
//         transpose+split done in-kernel via fp32 smem staging.
// OUT=1: C -> split bf16 (Ch/Cl). OUT=2: Z = tanh(acc + U + bias), z selects h/t.
template<int BSRC, int OUT>
__global__ __launch_bounds__(256, 1) void k_mma_u(
    const __nv_bfloat16* __restrict__ Ah, const __nv_bfloat16* __restrict__ Al,
    int lda, long long sA,
    const __nv_bfloat16* __restrict__ Bh, const __nv_bfloat16* __restrict__ Bl,
    int ldb, long long sB,
    const float* __restrict__ Wf, int ldw, long long sW,
    __nv_bfloat16* __restrict__ Ch, __nv_bfloat16* __restrict__ Cl, int ldc, long long sC,
    float* __restrict__ Z0, float* __restrict__ Z1,
    const float* __restrict__ U0, const float* __restrict__ U1,
    const float* __restrict__ bias0, const float* __restrict__ bias1,
    int Mr, int niter)
{
    extern __shared__ char smem[];
    const int tid = threadIdx.x, lane = tid & 31, w = tid >> 5;
    const int wm = w >> 2, wn = w & 3;
    const int row0 = blockIdx.y * 128;
    const int n0   = blockIdx.x * 128;

    Ah += (long long)blockIdx.z * sA;
    Al += (long long)blockIdx.z * sA;
    const __nv_bfloat16* Bph = nullptr;
    const __nv_bfloat16* Bpl = nullptr;
    const float* Wfb = nullptr;
    if constexpr (BSRC == 0) {
        Bph = Bh + (long long)blockIdx.z*sB + (size_t)n0*ldb;
        Bpl = Bl + (long long)blockIdx.z*sB + (size_t)n0*ldb;
    } else {
        Wfb = Wf + (long long)blockIdx.z*sW + n0;
    }

    uint32_t sb = smem_u32(smem);

    auto issue = [&](int s, int it) {
        uint32_t st = sb + s*STAGE_B;
        const __nv_bfloat16* ah = Ah + it*64;
        const __nv_bfloat16* al = Al + it*64;
        #pragma unroll
        for (int t = 0; t < 4; t++) {
            int idx = tid + t*256;
            int row = idx >> 3, ch = idx & 7;
            uint32_t off = row*(TS*2) + ch*16;
            int ar = row0 + row; if (ar >= Mr) ar = Mr - 1;
            cpasync16(st +          off, ah + (size_t)ar*lda + ch*8);
            cpasync16(st + TILE_B + off, al + (size_t)ar*lda + ch*8);
        }
        if constexpr (BSRC == 0) {
            const __nv_bfloat16* bh = Bph + it*64;
            const __nv_bfloat16* bl = Bpl + it*64;
            #pragma unroll
            for (int t = 0; t < 4; t++) {
                int idx = tid + t*256;
                int row = idx >> 3, ch = idx & 7;
                uint32_t off = row*(TS*2) + ch*16;
                cpasync16(st + 2*TILE_B + off, bh + (size_t)row*ldb + ch*8);
                cpasync16(st + 3*TILE_B + off, bl + (size_t)row*ldb + ch*8);
            }
        } else {
            const float* wrow = Wfb + (size_t)(it*64)*ldw;
            uint32_t fst = sb + FST_OFF + s*FST_STG;
            #pragma unroll
            for (int t = 0; t < 8; t++) {
                int idx = tid + t*256;        // 0..2047 -> [64 rows][32 chunks]
                int row = idx >> 5, ch = idx & 31;
                cpasync16(fst + row*528 + ch*16, wrow + (size_t)row*ldw + ch*4);
            }
        }
        CP_COMMIT();
    };

    auto convertB = [&](int s) {
        const float* f = (const float*)(smem + FST_OFF + s*FST_STG);
        char* bt_ = smem + s*STAGE_B + 2*TILE_B;
        int n  = tid >> 1;
        int kb = (tid & 1) * 32;
        const float* fp = f + n;
        char* ph = bt_ + (n*TS + kb)*2;
        char* pl = ph + TILE_B;
        #pragma unroll
        for (int j = 0; j < 32; j += 2) {
            float v0 = fp[(kb + j)*132];
            float v1 = fp[(kb + j + 1)*132];
            __nv_bfloat16 h0, l0, h1, l1;
            split_bf16(v0, h0, l0); split_bf16(v1, h1, l1);
            *(uint32_t*)(ph + j*2) = pack2(h0, h1);
            *(uint32_t*)(pl + j*2) = pack2(l0, l1);
        }
    };

    float acc[4][4][4] = {};
    issue(0, 0);
    for (int it = 0; it < niter; it++) {
        int s = it & 1;
        if (it + 1 < niter) { issue(s ^ 1, it + 1); CP_WAIT(1); }
        else                { CP_WAIT(0); }
        __syncthreads();
        if constexpr (BSRC == 1) { convertB(s); __syncthreads(); }
        const char* base = smem + s*STAGE_B;
        compute_core(base, base + 2*TILE_B, acc, lane, wm, wn);
        __syncthreads();
    }

    if constexpr (OUT == 1) {
        const long long coff = (long long)blockIdx.z * sC;
        #pragma unroll
        for (int mf = 0; mf < 4; mf++) {
            int r = row0 + wm*64 + mf*16 + (lane >> 2);
            #pragma unroll
            for (int nf = 0; nf < 4; nf++) {
                int cb = n0 + wn*32 + nf*8 + (lane & 3)*2;
                __nv_bfloat16 h0, l0, h1, l1;
                if (r < Mr) {
                    split_bf16(acc[mf][nf][0], h0, l0);
                    split_bf16(acc[mf][nf][1], h1, l1);
                    *reinterpret_cast<uint32_t*>(Ch + coff + (long long)r*ldc + cb) = pack2(h0, h1);
                    *reinterpret_cast<uint32_t*>(Cl + coff + (long long)r*ldc + cb) = pack2(l0, l1);
                }
                if (r + 8 < Mr) {
                    split_bf16(acc[mf][nf][2], h0, l0);
                    split_bf16(acc[mf][nf][3], h1, l1);
                    *reinterpret_cast<uint32_t*>(Ch + coff + (long long)(r + 8)*ldc + cb) = pack2(h0, h1);
                    *reinterpret_cast<uint32_t*>(Cl + coff + (long long)(r + 8)*ldc + cb) = pack2(l0, l1);
                }
            }
        }
    } else {   // OUT == 2: Z = tanh(acc + U + bias)
        float* Z        = blockIdx.z ? Z1 : Z0;
        const float* U  = blockIdx.z ? U1 : U0;
        const float* bs = blockIdx.z ? bias1 : bias0;
        #pragma unroll
        for (int mf = 0; mf < 4; mf++) {
            int r = row0 + wm*64 + mf*16 + (lane >> 2);
            #pragma unroll
            for (int nf = 0; nf < 4; nf++) {
                int cb = n0 + wn*32 + nf*8 + (lane & 3)*2;
                float b0 = bs[cb], b1 = bs[cb + 1];
                if (r < Mr) {
                    int u = blockIdx.z == 0 ? (r / NEv) : ((r / NPAIR)*NEv + (r % NEv));
                    Z[(size_t)r*Hv + cb]     = tanhf(acc[mf][nf][0] + U[u*Hv + cb]     + b0);
                    Z[(size_t)r*Hv + cb + 1] = tanhf(acc[mf][nf][1] + U[u*Hv + cb + 1] + b1);
                }
                int r8 = r + 8;
                if (r8 < Mr) {
                    int u = blockIdx.z == 0 ? (r8 / NEv) : ((r8 / NPAIR)*NEv + (r8 % NEv));
                    Z[(size_t)r8*Hv + cb]     = tanhf(acc[mf][nf][2] + U[u*Hv + cb]     + b0);
                    Z[(size_t)r8*Hv + cb + 1] = tanhf(acc[mf][nf][3] + U[u*Hv + cb + 1] + b1);
                }
            }
        }
    }
}

// ---------------- fused logits kernel ---------------------------------------------
__global__ __launch_bounds__(256, 1) void k_logits_f()
{
    extern __shared__ char smem[];
    uint32_t sb = smem_u32(smem);
    float* zhs = (float*)(smem + LZH_OFF);   // [128][65]
    float* zts = (float*)(smem + LZT_OFF);   // [128][66]
    const int tid = threadIdx.x, lane = tid & 31, w = tid >> 5;
    const int wm = w >> 2, wn = w & 3;
    const int row0 = blockIdx.x * 128;
    const int c0   = blockIdx.y * 48;

    auto issueB = [&](int s, int c) {
        uint32_t st = sb + s*LB_STG;
        const __nv_bfloat16* bh = g_wch + (size_t)c*64;
        const __nv_bfloat16* bl = g_wcl + (size_t)c*64;
        #pragma unroll
        for (int t = 0; t < 4; t++) {
            int idx = tid + t*256;
            int row = idx >> 3, ch = idx & 7;
            uint32_t off = row*(TS*2) + ch*16;
            cpasync16(st +          off, bh + (size_t)row*WCN + ch*8);
            cpasync16(st + TILE_B + off, bl + (size_t)row*WCN + ch*8);
        }
        CP_COMMIT();
    };

    float acc[4][4][4] = {};
    issueB(0, c0);
    int kcur = -1;
    for (int it = 0; it < 48; it++) {
        int c = c0 + it, s = it & 1;
        if (it + 1 < 48) { issueB(s ^ 1, c + 1); CP_WAIT(1); }
        else             { CP_WAIT(0); }
        int k = c >> 6;
        if (k != kcur) {
            for (int idx = tid; idx < 8192; idx += 256) {
                int r = idx >> 6, cc = idx & 63;
                zhs[r*65 + cc] = g_zh[(size_t)(row0 + r)*Hv + k*64 + cc];
                zts[r*66 + cc] = g_zt[(size_t)(row0 + r)*Hv + k*64 + cc];
            }
            kcur = k;
            __syncthreads();
        }
        {
            int i  = c & 63;
            int r  = tid >> 1;
            int j0 = (tid & 1) << 5;
            float a = zhs[r*65 + i];
            char* pA = smem + LA_BASE + s*LB_STG + r*(TS*2);
            #pragma unroll
            for (int j = 0; j < 32; j += 2) {
                float v0 = a * zts[r*66 + j0 + j];
                float v1 = a * zts[r*66 + j0 + j + 1];
                __nv_bfloat16 h0, l0, h1, l1;
                split_bf16(v0, h0, l0); split_bf16(v1, h1, l1);
                *(uint32_t*)(pA +          (j0 + j)*2) = pack2(h0, h1);
                *(uint32_t*)(pA + TILE_B + (j0 + j)*2) = pack2(l0, l1);
            }
        }
        __syncthreads();
        compute_core(smem + LA_BASE + s*LB_STG, smem + s*LB_STG, acc, lane, wm, wn);
        __syncthreads();
    }

    float* outk = g_lpart + (size_t)blockIdx.y*ROWS*NCLSv;
    #pragma unroll
    for (int mf = 0; mf < 4; mf++) {
        int r = row0 + wm*64 + mf*16 + (lane >> 2);
        #pragma unroll
        for (int nf = 0; nf < 4; nf++) {
            int cc = wn*32 + nf*8 + (lane & 3)*2;
            if (cc < NCLSv)     outk[(size_t)r*NCLSv + cc]           = acc[mf][nf][0];
            if (cc + 1 < NCLSv) outk[(size_t)r*NCLSv + cc + 1]       = acc[mf][nf][1];
            if (cc < NCLSv)     outk[(size_t)(r + 8)*NCLSv + cc]     = acc[mf][nf][2];
            if (cc + 1 < NCLSv) outk[(size_t)(r + 8)*NCLSv + cc + 1] = acc[mf][nf][3];
        }
    }
}

// ---------------- K8: combine KCH k-partials + bias ----------------------------
__global__ void k_final(const float* __restrict__ bcls, float* __restrict__ out)
{
    int idx = blockIdx.x*256 + threadIdx.x;
    if (idx >= ROWS*NCLSv) return;
    int c = idx % NCLSv;
    float v = bcls[c];
    #pragma unroll
    for (int k = 0; k < KCH; k++)
        v += g_lpart[(size_t)k*ROWS*NCLSv + idx];
    out[idx] = v;
}

// ================================ launch ========================================
extern "C" void kernel_launch(void* const* d_in, const int* in_sizes, int n_in,
                              void* d_out, int out_size)
{
    const float* seq  = (const float*)d_in[0];
    const float* att  = (const float*)d_in[1];
    const int*   ms   = (const int*)  d_in[2];
    const int*   cs   = (const int*)  d_in[3];
    const float* Wh   = (const float*)d_in[4];
    const float* bh   = (const float*)d_in[5];
    const float* Wt   = (const float*)d_in[6];
    const float* bt   = (const float*)d_in[7];
    const float* Wp   = (const float*)d_in[8];
    const float* Wcls = (const float*)d_in[9];
    const float* bcls = (const float*)d_in[10];
    float* out = (float*)d_out;

    float *p_eemb, *p_uh, *p_ut, *p_zh, *p_zt;
    __nv_bfloat16 *p_wclsh, *p_wclsl, *p_wch, *p_wcl;
    __nv_bfloat16 *p_hth, *p_htl, *p_rsh, *p_rsl, *p_whxh, *p_whxl;
    cudaGetSymbolAddress((void**)&p_eemb,  g_eemb);
    cudaGetSymbolAddress((void**)&p_uh,    g_uh);
    cudaGetSymbolAddress((void**)&p_ut,    g_ut);
    cudaGetSymbolAddress((void**)&p_zh,    g_zh);
    cudaGetSymbolAddress((void**)&p_zt,    g_zt);
    cudaGetSymbolAddress((void**)&p_wclsh, g_wclsh);
    cudaGetSymbolAddress((void**)&p_wclsl, g_wclsl);
    cudaGetSymbolAddress((void**)&p_wch,   g_wch);
    cudaGetSymbolAddress((void**)&p_wcl,   g_wcl);
    cudaGetSymbolAddress((void**)&p_hth,   g_hth);
    cudaGetSymbolAddress((void**)&p_htl,   g_htl);
    cudaGetSymbolAddress((void**)&p_rsh,   g_rsh);
    cudaGetSymbolAddress((void**)&p_rsl,   g_rsl);
    cudaGetSymbolAddress((void**)&p_whxh,  g_whxh);
    cudaGetSymbolAddress((void**)&p_whxl,  g_whxl);

    cudaFuncSetAttribute(k_mma_u<1,1>, cudaFuncAttributeMaxDynamicSharedMemorySize, SMEM_T);
    cudaFuncSetAttribute(k_mma_u<0,2>, cudaFuncAttributeMaxDynamicSharedMemorySize, SMEMB);
    cudaFuncSetAttribute(k_logits_f,   cudaFuncAttributeMaxDynamicSharedMemorySize, LSMEM);

    // --- small weight conversions ---
    k_wcls_conv<<<(128*Hv + 255)/256, 256>>>(Wcls);
    k_whx<<<(2*Hv*Hv + 255)/256, 256>>>(Wh, Wt);

    // Wc = Wcls_pad @ Wp  -> split bf16 [128 x 49152]; Wp read fp32 + transposed in-kernel
    k_mma_u<1,1><<<dim3(WCN/128, 1, 1), 256, SMEM_T>>>(
        p_wclsh, p_wclsl, Hv, 0,
        nullptr, nullptr, 0, 0,
        Wp, WCN, 0,
        p_wch, p_wcl, WCN, 0,
        nullptr, nullptr, nullptr, nullptr, nullptr, nullptr,
        128, Hv/64);

    // --- attention path ---
    k_eatt<<<Bv*NEv*NHv, 256>>>(att, ms);
    k_gate<<<Bv*NEv, 256>>>();
    k_eemb<<<Bv*NEv, Hv>>>(seq, ms, cs);
    k_ht<<<dim3(NPAIR, Bv), 256>>>();

    // rs = ht @ seq^T -> split bf16 (per batch: 576 x 768, K=1024); seq read fp32 direct
    k_mma_u<1,1><<<dim3(Hv/128, 5, Bv), 256, SMEM_T>>>(
        p_hth, p_htl, Lv, (long long)NPAIR*Lv,
        nullptr, nullptr, 0, 0,
        seq, Hv, (long long)Lv*Hv,
        p_rsh, p_rsl, Hv, (long long)NPAIR*Hv,
        nullptr, nullptr, nullptr, nullptr, nullptr, nullptr,
        NPAIR, Lv/64);

    // U = e_emb @ W[:, :H]^T  (fp32, tiny; head/tail via z-stride)
    k_gemm<16,1,true><<<dim3(Hv/64, 3, 2), 256>>>(
        p_eemb, Wh, p_uh, Bv*NEv, Hv, Hv, 2*Hv, Hv,
        0, (long long)(Wt - Wh), (long long)(p_ut - p_uh));

    // zh/zt = tanh(rs @ Whx^T + U + bias)  (head/tail via z)
    k_mma_u<0,2><<<dim3(Hv/128, ROWS/128, 2), 256, SMEMB>>>(
        p_rsh, p_rsl, Hv, 0,
        p_whxh, p_whxl, Hv, (long long)Hv*Hv,
        nullptr, 0, 0,
        nullptr, nullptr, 0, 0,
        p_zh, p_zt, p_uh, p_ut, bh, bt,
        ROWS, Hv/64);

    // --- fused logits (A generated in-kernel, split-K over 16 chunks) ---
    k_logits_f<<<dim3(ROWS/128, KCH), 256, LSMEM>>>();

    k_final<<<(ROWS*NCLSv + 255)/256, 256>>>(bcls, out);
}

// round 15
// speedup vs baseline: 9.2020x; 1.1049x over previous
#include <cuda_runtime.h>
#include <cuda_bf16.h>
#include <math.h>
#include <stdint.h>

#define Bv    2
#define Lv    1024
#define Hv    768
#define NHv   12
#define NEv   24
#define Mv    3
#define NCv   2
#define CWv   8
#define NCLSv 97
#define NPAIR (NEv*NEv)       /* 576 */
#define ROWS  (Bv*NPAIR)      /* 1152 */
#define WCN   (Hv*64)         /* 49152 */
#define KCH   16              /* K-chunks for logits split-K */

// MMA tile constants
#define TS      72            /* smem row stride in bf16 (144B) */
#define TILE_B  (128*TS*2)    /* 18432 B per 128x64 bf16 tile */
#define STAGE_B (4*TILE_B)    /* Ah, Al, Bh, Bl */
#define SMEMB   (2*STAGE_B)   /* 147456 B */
// fp32 B staging (for in-kernel transpose+split of row-major fp32 weights)
#define FST_OFF (2*STAGE_B)            /* 147456 */
#define FST_STG (64*132*4)             /* 33792 B: [64 k][132 n] fp32 */
#define SMEM_T  (FST_OFF + 2*FST_STG)  /* 215040 */

// fused logits kernel smem layout
#define LB_STG  (2*TILE_B)            /* 36864: Bh+Bl per stage */
#define LA_BASE (2*LB_STG)            /* 73728 */
#define LZH_OFF (LA_BASE + 2*LB_STG)  /* 147456 */
#define LZT_OFF (LZH_OFF + 128*65*4)  /* 180736 */
#define LSMEM   (LZT_OFF + 128*66*4)  /* 214528 */

__device__ __forceinline__ uint32_t smem_u32(const void* p) {
    uint32_t a;
    asm("{ .reg .u64 t; cvta.to.shared.u64 t, %1; cvt.u32.u64 %0, t; }" : "=r"(a) : "l"(p));
    return a;
}
__device__ __forceinline__ void cpasync16(uint32_t dst, const void* src) {
    asm volatile("cp.async.cg.shared.global [%0], [%1], 16;" :: "r"(dst), "l"(src) : "memory");
}
#define CP_COMMIT() asm volatile("cp.async.commit_group;" ::: "memory")
#define CP_WAIT(n)  asm volatile("cp.async.wait_group %0;" :: "n"(n) : "memory")

__device__ __forceinline__ void mma16816(float* d,
    uint32_t a0, uint32_t a1, uint32_t a2, uint32_t a3, uint32_t b0, uint32_t b1)
{
    asm volatile(
        "mma.sync.aligned.m16n8k16.row.col.f32.bf16.bf16.f32 "
        "{%0,%1,%2,%3}, {%4,%5,%6,%7}, {%8,%9}, {%0,%1,%2,%3};"
        : "+f"(d[0]), "+f"(d[1]), "+f"(d[2]), "+f"(d[3])
        : "r"(a0), "r"(a1), "r"(a2), "r"(a3), "r"(b0), "r"(b1));
}
__device__ __forceinline__ void ldsm4(uint32_t& r0, uint32_t& r1, uint32_t& r2, uint32_t& r3,
                                      uint32_t addr)
{
    asm volatile("ldmatrix.sync.aligned.m8n8.x4.shared.b16 {%0,%1,%2,%3}, [%4];"
        : "=r"(r0), "=r"(r1), "=r"(r2), "=r"(r3) : "r"(addr));
}
__device__ __forceinline__ void split_bf16(float v, __nv_bfloat16& h, __nv_bfloat16& l) {
    h = __float2bfloat16(v);
    l = __float2bfloat16(v - __bfloat162float(h));
}
__device__ __forceinline__ uint32_t pack2(__nv_bfloat16 a, __nv_bfloat16 b) {
    return (uint32_t)__bfloat16_as_ushort(a) | ((uint32_t)__bfloat16_as_ushort(b) << 16);
}

// ---------------- scratch (static device memory; no allocations) -------------
__device__ float g_eatt[Bv*NEv*NHv*Lv];
__device__ float g_gate[Bv*NEv*Lv];
__device__ float g_eemb[Bv*NEv*Hv];
__device__ float g_uh[Bv*NEv*Hv];
__device__ float g_ut[Bv*NEv*Hv];
__device__ float g_zh[(size_t)ROWS*Hv];
__device__ float g_zt[(size_t)ROWS*Hv];
__device__ float g_lpart[(size_t)KCH*ROWS*NCLSv];

__device__ __align__(16) __nv_bfloat16 g_wclsh[128*Hv];
__device__ __align__(16) __nv_bfloat16 g_wclsl[128*Hv];
__device__ __align__(16) __nv_bfloat16 g_wch[(size_t)128*WCN];
__device__ __align__(16) __nv_bfloat16 g_wcl[(size_t)128*WCN];
__device__ __align__(16) __nv_bfloat16 g_hth[(size_t)Bv*NPAIR*Lv];
__device__ __align__(16) __nv_bfloat16 g_htl[(size_t)Bv*NPAIR*Lv];
__device__ __align__(16) __nv_bfloat16 g_rsh[(size_t)ROWS*Hv];
__device__ __align__(16) __nv_bfloat16 g_rsl[(size_t)ROWS*Hv];
__device__ __align__(16) __nv_bfloat16 g_whxh[2*(size_t)Hv*Hv];
__device__ __align__(16) __nv_bfloat16 g_whxl[2*(size_t)Hv*Hv];

// ---------------- K1: e_att ----------------------------------------------------
__global__ void k_eatt(const float* __restrict__ att, const int* __restrict__ ms)
{
    int bh = blockIdx.x;
    int h  = bh % NHv;
    int be = bh / NHv;
    int b  = be / NEv;
    int p0 = ms[be*Mv + 0] + 1;
    int p1 = ms[be*Mv + 1] + 1;
    int p2 = ms[be*Mv + 2] + 1;
    const float* base = att + (size_t)(b*NHv + h)*Lv*Lv;
    const float* a0 = base + (size_t)p0*Lv;
    const float* a1 = base + (size_t)p1*Lv;
    const float* a2 = base + (size_t)p2*Lv;
    float* o = g_eatt + (size_t)(be*NHv + h)*Lv;
    for (int l = threadIdx.x; l < Lv; l += blockDim.x)
        o[l] = (a0[l] + a1[l] + a2[l]) * (1.0f/3.0f);
}

// ---------------- K2: gate ----------------------------------------------------
__global__ void k_gate()
{
    int be = blockIdx.x;
    __shared__ float s[Lv];
    __shared__ float red[256];
    float part = 0.f;
    for (int l = threadIdx.x; l < Lv; l += 256) {
        float v = 0.f;
        #pragma unroll
        for (int h = 0; h < NHv; h++)
            v += g_eatt[((size_t)(be*NHv + h))*Lv + l];
        s[l] = v;
        part += v;
    }
    red[threadIdx.x] = part;
    __syncthreads();
    for (int st = 128; st > 0; st >>= 1) {
        if (threadIdx.x < st) red[threadIdx.x] += red[threadIdx.x + st];
        __syncthreads();
    }
    float inv = 1.0f / red[0];
    for (int l = threadIdx.x; l < Lv; l += 256)
        g_gate[be*Lv + l] = s[l] * inv;
}

// ---------------- K3: e_emb ----------------------------------------------------
__global__ void k_eemb(const float* __restrict__ seq, const int* __restrict__ ms,
                       const int* __restrict__ cs)
{
    int be = blockIdx.x;
    int b  = be / NEv;
    int d  = threadIdx.x;
    __shared__ int   sp[Mv];
    __shared__ int   scs[NCv];
    __shared__ float sg[NCv][CWv];
    if (threadIdx.x < Mv)  sp[threadIdx.x]  = ms[be*Mv + threadIdx.x] + 1;
    if (threadIdx.x < NCv) scs[threadIdx.x] = cs[be*NCv + threadIdx.x];
    __syncthreads();
    if (threadIdx.x < NCv*CWv) {
        int c = threadIdx.x / CWv, w = threadIdx.x % CWv;
        sg[c][w] = g_gate[be*Lv + scs[c] + w];
    }
    __syncthreads();

    float x[Mv + NCv];
    #pragma unroll
    for (int m = 0; m < Mv; m++)
        x[m] = seq[((size_t)b*Lv + sp[m])*Hv + d];
    #pragma unroll
    for (int c = 0; c < NCv; c++) {
        float acc = 0.f;
        int basel = scs[c];
        #pragma unroll
        for (int w = 0; w < CWv; w++)
            acc += sg[c][w] * seq[((size_t)b*Lv + basel + w)*Hv + d];
        x[Mv + c] = acc;
    }
    float mx = x[0];
    #pragma unroll
    for (int i = 1; i < Mv + NCv; i++) mx = fmaxf(mx, x[i]);
    float ssum = 0.f;
    #pragma unroll
    for (int i = 0; i < Mv + NCv; i++) ssum += expf(x[i] - mx);
    g_eemb[be*Hv + d] = mx + logf(ssum);
}

// ---------------- K4: ht (emits split-bf16 directly) ---------------------------
__global__ void k_ht()
{
    int ef = blockIdx.x;
    int b  = blockIdx.y;
    int e = ef / NEv, f = ef % NEv;
    __shared__ float s[Lv];
    __shared__ float red[256];
    const float* pe = g_eatt + (size_t)((b*NEv + e)*NHv)*Lv;
    const float* pf = g_eatt + (size_t)((b*NEv + f)*NHv)*Lv;
    float part = 0.f;
    for (int l = threadIdx.x; l < Lv; l += 256) {
        float v = 0.f;
        #pragma unroll
        for (int h = 0; h < NHv; h++)
            v += pe[h*Lv + l] * pf[h*Lv + l];
        v = fmaxf(v, 0.f);
        s[l] = v;
        part += v;
    }
    red[threadIdx.x] = part;
    __syncthreads();
    for (int st = 128; st > 0; st >>= 1) {
        if (threadIdx.x < st) red[threadIdx.x] += red[threadIdx.x + st];
        __syncthreads();
    }
    float inv = 1.0f / (red[0] + 1e-10f);
    size_t off = ((size_t)b*NPAIR + ef)*Lv;
    for (int l = threadIdx.x; l < Lv; l += 256) {
        __nv_bfloat16 h, lo; split_bf16(s[l]*inv, h, lo);
        g_hth[off + l] = h;
        g_htl[off + l] = lo;
    }
}

// ---------------- fp32 tiled GEMM (for U only) ----------------------------------
template<int TM, int RT, bool BT>
__global__ void __launch_bounds__(256) k_gemm(
    const float* __restrict__ A, const float* __restrict__ Bm, float* __restrict__ C,
    int Mr, int Kd, int lda, int ldb, int ldc,
    long long sA, long long sB, long long sC)
{
    constexpr int APAD = (TM == 128) ? 136 : 20;
    A  += (long long)blockIdx.z * sA;
    Bm += (long long)blockIdx.z * sB;
    C  += (long long)blockIdx.z * sC;

    __shared__ __align__(16) float As[16*APAD];
    __shared__ __align__(16) float Bs[16*68];

    const int tid = threadIdx.x;
    const int tx = tid & 15;
    const int ty = tid >> 4;
    const int row0 = blockIdx.y * TM;
    const int col0 = blockIdx.x * 64;

    const int a_k = tid & 15;
    const int a_r = tid >> 4;

    float acc[RT][4] = {};
    float ra[TM/16], rb[4];

    auto loadA = [&](int k0) {
        #pragma unroll
        for (int t = 0; t < TM/16; t++) {
            int gr = row0 + a_r + t*16;
            ra[t] = (gr < Mr) ? A[(long long)gr*lda + (k0 + a_k)] : 0.f;
        }
    };
    auto loadB = [&](int k0) {
        if (BT) {
            #pragma unroll
            for (int t = 0; t < 4; t++)
                rb[t] = Bm[(long long)(col0 + a_r + t*16)*ldb + (k0 + a_k)];
        } else {
            #pragma unroll
            for (int t = 0; t < 4; t++)
                rb[t] = Bm[(long long)(k0 + (tid>>6) + t*4)*ldb + col0 + (tid&63)];
        }
    };
    auto storeAB = [&]() {
        #pragma unroll
        for (int t = 0; t < TM/16; t++)
            As[a_k*APAD + a_r + t*16] = ra[t];
        if (BT) {
            #pragma unroll
            for (int t = 0; t < 4; t++)
                Bs[a_k*68 + a_r + t*16] = rb[t];
        } else {
            #pragma unroll
            for (int t = 0; t < 4; t++)
                Bs[((tid>>6) + t*4)*68 + (tid&63)] = rb[t];
        }
    };

    loadA(0); loadB(0);
    for (int k0 = 0; k0 < Kd; k0 += 16) {
        storeAB();
        __syncthreads();
        if (k0 + 16 < Kd) { loadA(k0 + 16); loadB(k0 + 16); }
        #pragma unroll
        for (int kk = 0; kk < 16; kk++) {
            float av[RT];
            if constexpr (RT == 8) {
                float4 a0 = *reinterpret_cast<const float4*>(&As[kk*APAD + ty*8]);
                float4 a1 = *reinterpret_cast<const float4*>(&As[kk*APAD + ty*8 + 4]);
                av[0]=a0.x; av[1]=a0.y; av[2]=a0.z; av[3]=a0.w;
                av[4]=a1.x; av[5]=a1.y; av[6]=a1.z; av[7]=a1.w;
            } else {
                av[0] = As[kk*APAD + ty];
            }
            float4 b4 = *reinterpret_cast<const float4*>(&Bs[kk*68 + tx*4]);
            #pragma unroll
            for (int i = 0; i < RT; i++) {
                acc[i][0] += av[i]*b4.x; acc[i][1] += av[i]*b4.y;
                acc[i][2] += av[i]*b4.z; acc[i][3] += av[i]*b4.w;
            }
        }
        __syncthreads();
    }

    #pragma unroll
    for (int i = 0; i < RT; i++) {
        int gr = row0 + ty*RT + i;
        if (gr < Mr) {
            #pragma unroll
            for (int j = 0; j < 4; j++)
                C[(long long)gr*ldc + col0 + tx*4 + j] = acc[i][j];
        }
    }
}

// ---------------- conversions (small weights only) -------------------------------
__global__ void k_wcls_conv(const float* __restrict__ Wcls)
{
    int idx = blockIdx.x*256 + threadIdx.x;
    if (idx >= 128*Hv) return;
    int r = idx / Hv, c = idx % Hv;
    float v = (r < NCLSv) ? Wcls[r*Hv + c] : 0.f;
    __nv_bfloat16 h, l; split_bf16(v, h, l);
    g_wclsh[idx] = h;
    g_wclsl[idx] = l;
}

__global__ void k_whx(const float* __restrict__ Wh, const float* __restrict__ Wt)
{
    int idx = blockIdx.x*256 + threadIdx.x;
    if (idx >= 2*Hv*Hv) return;
    int z = idx / (Hv*Hv);
    int rem = idx - z*Hv*Hv;
    int d = rem / Hv, k = rem % Hv;
    const float* W = z ? Wt : Wh;
    float v = W[(size_t)d*(2*Hv) + Hv + k];
    __nv_bfloat16 h, l; split_bf16(v, h, l);
    g_whxh[idx] = h;
    g_whxl[idx] = l;
}

// ---------------- mma.sync split-bf16 core (ldmatrix edition) --------------------
// pA/pB: uint32 smem addresses of the hi tiles (lo at +TILE_B). Layout: row-major,
// TS(=72) bf16 stride. TS*2 = 144B stride -> conflict-free LDSM (banks 4r mod 32).
__device__ __forceinline__ void compute_core(uint32_t pA, uint32_t pB,
    float acc[4][4][4], int lane, int wm, int wn)
{
    const int la = lane & 15;               // A row offset
    const int ka = (lane >> 4) * 8;         // A col offset
    const int lb = (lane & 7) + ((lane >> 4) & 1) * 8;  // B row offset
    const int kb = ((lane >> 3) & 1) * 8;               // B col offset

    #pragma unroll
    for (int ks = 0; ks < 4; ks++) {
        const int k0 = ks*16;
        uint32_t bh[4][2], bl[4][2];
        #pragma unroll
        for (int p = 0; p < 2; p++) {
            int n0 = wn*32 + p*16;
            uint32_t addr = pB + ((n0 + lb)*TS + k0 + kb)*2;
            ldsm4(bh[2*p][0], bh[2*p][1], bh[2*p+1][0], bh[2*p+1][1], addr);
            ldsm4(bl[2*p][0], bl[2*p][1], bl[2*p+1][0], bl[2*p+1][1], addr + TILE_B);
        }
        #pragma unroll
        for (int mf = 0; mf < 4; mf++) {
            int r0 = wm*64 + mf*16;
            uint32_t addr = pA + ((r0 + la)*TS + k0 + ka)*2;
            uint32_t ah0, ah1, ah2, ah3, al0, al1, al2, al3;
            ldsm4(ah0, ah1, ah2, ah3, addr);
            ldsm4(al0, al1, al2, al3, addr + TILE_B);
            #pragma unroll
            for (int nf = 0; nf < 4; nf++) {
                mma16816(acc[mf][nf], ah0, ah1, ah2, ah3, bh[nf][0], bh[nf][1]);
                mma16816(acc[mf][nf], ah0, ah1, ah2, ah3, bl[nf][0], bl[nf][1]);
                mma16816(acc[mf][nf], al0, al1, al2, al3, bh[nf][0], bh[nf][1]);
            }
        }
    }
}

// ---------------- unified split-bf16 GEMM: C = A @ B^T ----------------------------
template<int BSRC, int OUT>
__global__ __launch_bounds__(256, 1) void k_mma_u(
    const __nv_bfloat16* __restrict__ Ah, const __nv_bfloat16* __restrict__ Al,
    int lda, long long sA,
    const __nv_bfloat16* __restrict__ Bh, const __nv_bfloat16* __restrict__ Bl,
    int ldb, long long sB,
    const float* __restrict__ Wf, int ldw, long long sW,
    __nv_bfloat16* __restrict__ Ch, __nv_bfloat16* __restrict__ Cl, int ldc, long long sC,
    float* __restrict__ Z0, float* __restrict__ Z1,
    const float* __restrict__ U0, const float* __restrict__ U1,
    const float* __restrict__ bias0, const float* __restrict__ bias1,
    int Mr, int niter)
{
    extern __shared__ char smem[];
    const int tid = threadIdx.x, lane = tid & 31, w = tid >> 5;
    const int wm = w >> 2, wn = w & 3;
    const int row0 = blockIdx.y * 128;
    const int n0   = blockIdx.x * 128;

    Ah += (long long)blockIdx.z * sA;
    Al += (long long)blockIdx.z * sA;
    const __nv_bfloat16* Bph = nullptr;
    const __nv_bfloat16* Bpl = nullptr;
    const float* Wfb = nullptr;
    if constexpr (BSRC == 0) {
        Bph = Bh + (long long)blockIdx.z*sB + (size_t)n0*ldb;
        Bpl = Bl + (long long)blockIdx.z*sB + (size_t)n0*ldb;
    } else {
        Wfb = Wf + (long long)blockIdx.z*sW + n0;
    }

    uint32_t sb = smem_u32(smem);

    auto issue = [&](int s, int it) {
        uint32_t st = sb + s*STAGE_B;
        const __nv_bfloat16* ah = Ah + it*64;
        const __nv_bfloat16* al = Al + it*64;
        #pragma unroll
        for (int t = 0; t < 4; t++) {
            int idx = tid + t*256;
            int row = idx >> 3, ch = idx & 7;
            uint32_t off = row*(TS*2) + ch*16;
            int ar = row0 + row; if (ar >= Mr) ar = Mr - 1;
            cpasync16(st +          off, ah + (size_t)ar*lda + ch*8);
            cpasync16(st + TILE_B + off, al + (size_t)ar*lda + ch*8);
        }
        if constexpr (BSRC == 0) {
            const __nv_bfloat16* bh = Bph + it*64;
            const __nv_bfloat16* bl = Bpl + it*64;
            #pragma unroll
            for (int t = 0; t < 4; t++) {
                int idx = tid + t*256;
                int row = idx >> 3, ch = idx & 7;
                uint32_t off = row*(TS*2) + ch*16;
                cpasync16(st + 2*TILE_B + off, bh + (size_t)row*ldb + ch*8);
                cpasync16(st + 3*TILE_B + off, bl + (size_t)row*ldb + ch*8);
            }
        } else {
            const float* wrow = Wfb + (size_t)(it*64)*ldw;
            uint32_t fst = sb + FST_OFF + s*FST_STG;
            #pragma unroll
            for (int t = 0; t < 8; t++) {
                int idx = tid + t*256;
                int row = idx >> 5, ch = idx & 31;
                cpasync16(fst + row*528 + ch*16, wrow + (size_t)row*ldw + ch*4);
            }
        }
        CP_COMMIT();
    };

    auto convertB = [&](int s) {
        const float* f = (const float*)(smem + FST_OFF + s*FST_STG);
        char* bt_ = smem + s*STAGE_B + 2*TILE_B;
        int n  = tid >> 1;
        int kb = (tid & 1) * 32;
        const float* fp = f + n;
        char* ph = bt_ + (n*TS + kb)*2;
        char* pl = ph + TILE_B;
        #pragma unroll
        for (int j = 0; j < 32; j += 2) {
            float v0 = fp[(kb + j)*132];
            float v1 = fp[(kb + j + 1)*132];
            __nv_bfloat16 h0, l0, h1, l1;
            split_bf16(v0, h0, l0); split_bf16(v1, h1, l1);
            *(uint32_t*)(ph + j*2) = pack2(h0, h1);
            *(uint32_t*)(pl + j*2) = pack2(l0, l1);
        }
    };

    float acc[4][4][4] = {};
    issue(0, 0);
    for (int it = 0; it < niter; it++) {
        int s = it & 1;
        if (it + 1 < niter) { issue(s ^ 1, it + 1); CP_WAIT(1); }
        else                { CP_WAIT(0); }
        __syncthreads();
        if constexpr (BSRC == 1) { convertB(s); __syncthreads(); }
        uint32_t base = sb + s*STAGE_B;
        compute_core(base, base + 2*TILE_B, acc, lane, wm, wn);
        __syncthreads();
    }

    if constexpr (OUT == 1) {
        const long long coff = (long long)blockIdx.z * sC;
        #pragma unroll
        for (int mf = 0; mf < 4; mf++) {
            int r = row0 + wm*64 + mf*16 + (lane >> 2);
            #pragma unroll
            for (int nf = 0; nf < 4; nf++) {
                int cb = n0 + wn*32 + nf*8 + (lane & 3)*2;
                __nv_bfloat16 h0, l0, h1, l1;
                if (r < Mr) {
                    split_bf16(acc[mf][nf][0], h0, l0);
                    split_bf16(acc[mf][nf][1], h1, l1);
                    *reinterpret_cast<uint32_t*>(Ch + coff + (long long)r*ldc + cb) = pack2(h0, h1);
                    *reinterpret_cast<uint32_t*>(Cl + coff + (long long)r*ldc + cb) = pack2(l0, l1);
                }
                if (r + 8 < Mr) {
                    split_bf16(acc[mf][nf][2], h0, l0);
                    split_bf16(acc[mf][nf][3], h1, l1);
                    *reinterpret_cast<uint32_t*>(Ch + coff + (long long)(r + 8)*ldc + cb) = pack2(h0, h1);
                    *reinterpret_cast<uint32_t*>(Cl + coff + (long long)(r + 8)*ldc + cb) = pack2(l0, l1);
                }
            }
        }
    } else {   // OUT == 2: Z = tanh(acc + U + bias)
        float* Z        = blockIdx.z ? Z1 : Z0;
        const float* U  = blockIdx.z ? U1 : U0;
        const float* bs = blockIdx.z ? bias1 : bias0;
        #pragma unroll
        for (int mf = 0; mf < 4; mf++) {
            int r = row0 + wm*64 + mf*16 + (lane >> 2);
            #pragma unroll
            for (int nf = 0; nf < 4; nf++) {
                int cb = n0 + wn*32 + nf*8 + (lane & 3)*2;
                float b0 = bs[cb], b1 = bs[cb + 1];
                if (r < Mr) {
                    int u = blockIdx.z == 0 ? (r / NEv) : ((r / NPAIR)*NEv + (r % NEv));
                    Z[(size_t)r*Hv + cb]     = tanhf(acc[mf][nf][0] + U[u*Hv + cb]     + b0);
                    Z[(size_t)r*Hv + cb + 1] = tanhf(acc[mf][nf][1] + U[u*Hv + cb + 1] + b1);
                }
                int r8 = r + 8;
                if (r8 < Mr) {
                    int u = blockIdx.z == 0 ? (r8 / NEv) : ((r8 / NPAIR)*NEv + (r8 % NEv));
                    Z[(size_t)r8*Hv + cb]     = tanhf(acc[mf][nf][2] + U[u*Hv + cb]     + b0);
                    Z[(size_t)r8*Hv + cb + 1] = tanhf(acc[mf][nf][3] + U[u*Hv + cb + 1] + b1);
                }
            }
        }
    }
}

// ---------------- fused logits kernel ---------------------------------------------
__global__ __launch_bounds__(256, 1) void k_logits_f()
{
    extern __shared__ char smem[];
    uint32_t sb = smem_u32(smem);
    float* zhs = (float*)(smem + LZH_OFF);   // [128][65]
    float* zts = (float*)(smem + LZT_OFF);   // [128][66]
    const int tid = threadIdx.x, lane = tid & 31, w = tid >> 5;
    const int wm = w >> 2, wn = w & 3;
    const int row0 = blockIdx.x * 128;
    const int c0   = blockIdx.y * 48;

    auto issueB = [&](int s, int c) {
        uint32_t st = sb + s*LB_STG;
        const __nv_bfloat16* bh = g_wch + (size_t)c*64;
        const __nv_bfloat16* bl = g_wcl + (size_t)c*64;
        #pragma unroll
        for (int t = 0; t < 4; t++) {
            int idx = tid + t*256;
            int row = idx >> 3, ch = idx & 7;
            uint32_t off = row*(TS*2) + ch*16;
            cpasync16(st +          off, bh + (size_t)row*WCN + ch*8);
            cpasync16(st + TILE_B + off, bl + (size_t)row*WCN + ch*8);
        }
        CP_COMMIT();
    };

    float acc[4][4][4] = {};
    issueB(0, c0);
    int kcur = -1;
    for (int it = 0; it < 48; it++) {
        int c = c0 + it, s = it & 1;
        if (it + 1 < 48) { issueB(s ^ 1, c + 1); CP_WAIT(1); }
        else             { CP_WAIT(0); }
        int k = c >> 6;
        if (k != kcur) {
            for (int idx = tid; idx < 8192; idx += 256) {
                int r = idx >> 6, cc = idx & 63;
                zhs[r*65 + cc] = g_zh[(size_t)(row0 + r)*Hv + k*64 + cc];
                zts[r*66 + cc] = g_zt[(size_t)(row0 + r)*Hv + k*64 + cc];
            }
            kcur = k;
            __syncthreads();
        }
        {
            int i  = c & 63;
            int r  = tid >> 1;
            int j0 = (tid & 1) << 5;
            float a = zhs[r*65 + i];
            char* pA = smem + LA_BASE + s*LB_STG + r*(TS*2);
            #pragma unroll
            for (int j = 0; j < 32; j += 2) {
                float v0 = a * zts[r*66 + j0 + j];
                float v1 = a * zts[r*66 + j0 + j + 1];
                __nv_bfloat16 h0, l0, h1, l1;
                split_bf16(v0, h0, l0); split_bf16(v1, h1, l1);
                *(uint32_t*)(pA +          (j0 + j)*2) = pack2(h0, h1);
                *(uint32_t*)(pA + TILE_B + (j0 + j)*2) = pack2(l0, l1);
            }
        }
        __syncthreads();
        compute_core(sb + LA_BASE + s*LB_STG, sb + s*LB_STG, acc, lane, wm, wn);
        __syncthreads();
    }

    float* outk = g_lpart + (size_t)blockIdx.y*ROWS*NCLSv;
    #pragma unroll
    for (int mf = 0; mf < 4; mf++) {
        int r = row0 + wm*64 + mf*16 + (lane >> 2);
        #pragma unroll
        for (int nf = 0; nf < 4; nf++) {
            int cc = wn*32 + nf*8 + (lane & 3)*2;
            if (cc < NCLSv)     outk[(size_t)r*NCLSv + cc]           = acc[mf][nf][0];
            if (cc + 1 < NCLSv) outk[(size_t)r*NCLSv + cc + 1]       = acc[mf][nf][1];
            if (cc < NCLSv)     outk[(size_t)(r + 8)*NCLSv + cc]     = acc[mf][nf][2];
            if (cc + 1 < NCLSv) outk[(size_t)(r + 8)*NCLSv + cc + 1] = acc[mf][nf][3];
        }
    }
}

// ---------------- K8: combine KCH k-partials + bias ----------------------------
__global__ void k_final(const float* __restrict__ bcls, float* __restrict__ out)
{
    int idx = blockIdx.x*256 + threadIdx.x;
    if (idx >= ROWS*NCLSv) return;
    int c = idx % NCLSv;
    float v = bcls[c];
    #pragma unroll
    for (int k = 0; k < KCH; k++)
        v += g_lpart[(size_t)k*ROWS*NCLSv + idx];
    out[idx] = v;
}

// ================================ launch ========================================
extern "C" void kernel_launch(void* const* d_in, const int* in_sizes, int n_in,
                              void* d_out, int out_size)
{
    const float* seq  = (const float*)d_in[0];
    const float* att  = (const float*)d_in[1];
    const int*   ms   = (const int*)  d_in[2];
    const int*   cs   = (const int*)  d_in[3];
    const float* Wh   = (const float*)d_in[4];
    const float* bh   = (const float*)d_in[5];
    const float* Wt   = (const float*)d_in[6];
    const float* bt   = (const float*)d_in[7];
    const float* Wp   = (const float*)d_in[8];
    const float* Wcls = (const float*)d_in[9];
    const float* bcls = (const float*)d_in[10];
    float* out = (float*)d_out;

    float *p_eemb, *p_uh, *p_ut, *p_zh, *p_zt;
    __nv_bfloat16 *p_wclsh, *p_wclsl, *p_wch, *p_wcl;
    __nv_bfloat16 *p_hth, *p_htl, *p_rsh, *p_rsl, *p_whxh, *p_whxl;
    cudaGetSymbolAddress((void**)&p_eemb,  g_eemb);
    cudaGetSymbolAddress((void**)&p_uh,    g_uh);
    cudaGetSymbolAddress((void**)&p_ut,    g_ut);
    cudaGetSymbolAddress((void**)&p_zh,    g_zh);
    cudaGetSymbolAddress((void**)&p_zt,    g_zt);
    cudaGetSymbolAddress((void**)&p_wclsh, g_wclsh);
    cudaGetSymbolAddress((void**)&p_wclsl, g_wclsl);
    cudaGetSymbolAddress((void**)&p_wch,   g_wch);
    cudaGetSymbolAddress((void**)&p_wcl,   g_wcl);
    cudaGetSymbolAddress((void**)&p_hth,   g_hth);
    cudaGetSymbolAddress((void**)&p_htl,   g_htl);
    cudaGetSymbolAddress((void**)&p_rsh,   g_rsh);
    cudaGetSymbolAddress((void**)&p_rsl,   g_rsl);
    cudaGetSymbolAddress((void**)&p_whxh,  g_whxh);
    cudaGetSymbolAddress((void**)&p_whxl,  g_whxl);

    cudaFuncSetAttribute(k_mma_u<1,1>, cudaFuncAttributeMaxDynamicSharedMemorySize, SMEM_T);
    cudaFuncSetAttribute(k_mma_u<0,2>, cudaFuncAttributeMaxDynamicSharedMemorySize, SMEMB);
    cudaFuncSetAttribute(k_logits_f,   cudaFuncAttributeMaxDynamicSharedMemorySize, LSMEM);

    // Aux stream + fork/join events, created once on the (uncaptured) correctness
    // call; reused verbatim inside capture. Work per call is identical.
    static cudaStream_t s_aux = nullptr;
    static cudaEvent_t  e_fork = nullptr, e_join = nullptr;
    if (s_aux == nullptr) {
        cudaStreamCreateWithFlags(&s_aux, cudaStreamNonBlocking);
        cudaEventCreateWithFlags(&e_fork, cudaEventDisableTiming);
        cudaEventCreateWithFlags(&e_join, cudaEventDisableTiming);
    }

    // ---- fork: Wc path on aux stream (independent until k_logits_f) ----
    cudaEventRecord(e_fork, 0);
    cudaStreamWaitEvent(s_aux, e_fork, 0);

    k_wcls_conv<<<(128*Hv + 255)/256, 256, 0, s_aux>>>(Wcls);
    // Wc = Wcls_pad @ Wp  -> split bf16 [128 x 49152]; Wp read fp32 + transposed in-kernel
    k_mma_u<1,1><<<dim3(WCN/128, 1, 1), 256, SMEM_T, s_aux>>>(
        p_wclsh, p_wclsl, Hv, 0,
        nullptr, nullptr, 0, 0,
        Wp, WCN, 0,
        p_wch, p_wcl, WCN, 0,
        nullptr, nullptr, nullptr, nullptr, nullptr, nullptr,
        128, Hv/64);
    cudaEventRecord(e_join, s_aux);

    // ---- main stream: attention path ----
    k_whx<<<(2*Hv*Hv + 255)/256, 256>>>(Wh, Wt);
    k_eatt<<<Bv*NEv*NHv, 256>>>(att, ms);
    k_gate<<<Bv*NEv, 256>>>();
    k_eemb<<<Bv*NEv, Hv>>>(seq, ms, cs);
    k_ht<<<dim3(NPAIR, Bv), 256>>>();

    // rs = ht @ seq^T -> split bf16 (per batch: 576 x 768, K=1024); seq read fp32 direct
    k_mma_u<1,1><<<dim3(Hv/128, 5, Bv), 256, SMEM_T>>>(
        p_hth, p_htl, Lv, (long long)NPAIR*Lv,
        nullptr, nullptr, 0, 0,
        seq, Hv, (long long)Lv*Hv,
        p_rsh, p_rsl, Hv, (long long)NPAIR*Hv,
        nullptr, nullptr, nullptr, nullptr, nullptr, nullptr,
        NPAIR, Lv/64);

    // U = e_emb @ W[:, :H]^T  (fp32, tiny; head/tail via z-stride)
    k_gemm<16,1,true><<<dim3(Hv/64, 3, 2), 256>>>(
        p_eemb, Wh, p_uh, Bv*NEv, Hv, Hv, 2*Hv, Hv,
        0, (long long)(Wt - Wh), (long long)(p_ut - p_uh));

    // zh/zt = tanh(rs @ Whx^T + U + bias)  (head/tail via z)
    k_mma_u<0,2><<<dim3(Hv/128, ROWS/128, 2), 256, SMEMB>>>(
        p_rsh, p_rsl, Hv, 0,
        p_whxh, p_whxl, Hv, (long long)Hv*Hv,
        nullptr, 0, 0,
        nullptr, nullptr, 0, 0,
        p_zh, p_zt, p_uh, p_ut, bh, bt,
        ROWS, Hv/64);

    // ---- join: logits needs Wc ----
    cudaStreamWaitEvent(0, e_join, 0);

    // fused logits (A generated in-kernel, split-K over 16 chunks)
    k_logits_f<<<dim3(ROWS/128, KCH), 256, LSMEM>>>();

    k_final<<<(ROWS*NCLSv + 255)/256, 256>>>(bcls, out);
}

// round 16
// speedup vs baseline: 9.2490x; 1.0051x over previous
#include <cuda_runtime.h>
#include <cuda_bf16.h>
#include <math.h>
#include <stdint.h>

#define Bv    2
#define Lv    1024
#define Hv    768
#define NHv   12
#define NEv   24
#define Mv    3
#define NCv   2
#define CWv   8
#define NCLSv 97
#define NPAIR (NEv*NEv)       /* 576 */
#define ROWS  (Bv*NPAIR)      /* 1152 */
#define WCN   (Hv*64)         /* 49152 */
#define KCH   16              /* K-chunks for logits split-K */

// MMA tile constants
#define TS      72            /* smem row stride in bf16 (144B) */
#define TILE_B  (128*TS*2)    /* 18432 B per 128x64 bf16 tile */
#define STAGE_B (4*TILE_B)    /* Ah, Al, Bh, Bl */
#define SMEMB   (2*STAGE_B)   /* 147456 B */
// fp32 B staging (for in-kernel transpose+split of row-major fp32 weights)
#define FST_OFF (2*STAGE_B)            /* 147456 */
#define FST_STG (64*132*4)             /* 33792 B: [64 k][132 n] fp32 */
#define SMEM_T  (FST_OFF + 2*FST_STG)  /* 215040 */

// fused logits kernel smem layout
#define LB_STG  (2*TILE_B)            /* 36864: Bh+Bl per stage */
#define LA_BASE (2*LB_STG)            /* 73728 */
#define LZH_OFF (LA_BASE + 2*LB_STG)  /* 147456 */
#define LZT_OFF (LZH_OFF + 128*65*4)  /* 180736 */
#define LSMEM   (LZT_OFF + 128*66*4)  /* 214528 */

__device__ __forceinline__ uint32_t smem_u32(const void* p) {
    uint32_t a;
    asm("{ .reg .u64 t; cvta.to.shared.u64 t, %1; cvt.u32.u64 %0, t; }" : "=r"(a) : "l"(p));
    return a;
}
__device__ __forceinline__ void cpasync16(uint32_t dst, const void* src) {
    asm volatile("cp.async.cg.shared.global [%0], [%1], 16;" :: "r"(dst), "l"(src) : "memory");
}
#define CP_COMMIT() asm volatile("cp.async.commit_group;" ::: "memory")
#define CP_WAIT(n)  asm volatile("cp.async.wait_group %0;" :: "n"(n) : "memory")

__device__ __forceinline__ void mma16816(float* d,
    uint32_t a0, uint32_t a1, uint32_t a2, uint32_t a3, uint32_t b0, uint32_t b1)
{
    asm volatile(
        "mma.sync.aligned.m16n8k16.row.col.f32.bf16.bf16.f32 "
        "{%0,%1,%2,%3}, {%4,%5,%6,%7}, {%8,%9}, {%0,%1,%2,%3};"
        : "+f"(d[0]), "+f"(d[1]), "+f"(d[2]), "+f"(d[3])
        : "r"(a0), "r"(a1), "r"(a2), "r"(a3), "r"(b0), "r"(b1));
}
__device__ __forceinline__ void ldsm4(uint32_t& r0, uint32_t& r1, uint32_t& r2, uint32_t& r3,
                                      uint32_t addr)
{
    asm volatile("ldmatrix.sync.aligned.m8n8.x4.shared.b16 {%0,%1,%2,%3}, [%4];"
        : "=r"(r0), "=r"(r1), "=r"(r2), "=r"(r3) : "r"(addr));
}
__device__ __forceinline__ void split_bf16(float v, __nv_bfloat16& h, __nv_bfloat16& l) {
    h = __float2bfloat16(v);
    l = __float2bfloat16(v - __bfloat162float(h));
}
__device__ __forceinline__ uint32_t pack2(__nv_bfloat16 a, __nv_bfloat16 b) {
    return (uint32_t)__bfloat16_as_ushort(a) | ((uint32_t)__bfloat16_as_ushort(b) << 16);
}

// ---------------- scratch (static device memory; no allocations) -------------
__device__ float g_eatt[Bv*NEv*NHv*Lv];
__device__ float g_gate[Bv*NEv*Lv];
__device__ float g_eemb[Bv*NEv*Hv];
__device__ float g_uh[Bv*NEv*Hv];
__device__ float g_ut[Bv*NEv*Hv];
__device__ float g_zh[(size_t)ROWS*Hv];
__device__ float g_zt[(size_t)ROWS*Hv];
__device__ float g_lpart[(size_t)KCH*ROWS*NCLSv];

__device__ __align__(16) __nv_bfloat16 g_wclsh[128*Hv];
__device__ __align__(16) __nv_bfloat16 g_wclsl[128*Hv];
__device__ __align__(16) __nv_bfloat16 g_wch[(size_t)128*WCN];
__device__ __align__(16) __nv_bfloat16 g_wcl[(size_t)128*WCN];
__device__ __align__(16) __nv_bfloat16 g_hth[(size_t)Bv*NPAIR*Lv];
__device__ __align__(16) __nv_bfloat16 g_htl[(size_t)Bv*NPAIR*Lv];
__device__ __align__(16) __nv_bfloat16 g_rsh[(size_t)ROWS*Hv];
__device__ __align__(16) __nv_bfloat16 g_rsl[(size_t)ROWS*Hv];
__device__ __align__(16) __nv_bfloat16 g_whxh[2*(size_t)Hv*Hv];
__device__ __align__(16) __nv_bfloat16 g_whxl[2*(size_t)Hv*Hv];

// ---------------- K1: e_att ----------------------------------------------------
__global__ void k_eatt(const float* __restrict__ att, const int* __restrict__ ms)
{
    int bh = blockIdx.x;
    int h  = bh % NHv;
    int be = bh / NHv;
    int b  = be / NEv;
    int p0 = ms[be*Mv + 0] + 1;
    int p1 = ms[be*Mv + 1] + 1;
    int p2 = ms[be*Mv + 2] + 1;
    const float* base = att + (size_t)(b*NHv + h)*Lv*Lv;
    const float* a0 = base + (size_t)p0*Lv;
    const float* a1 = base + (size_t)p1*Lv;
    const float* a2 = base + (size_t)p2*Lv;
    float* o = g_eatt + (size_t)(be*NHv + h)*Lv;
    for (int l = threadIdx.x; l < Lv; l += blockDim.x)
        o[l] = (a0[l] + a1[l] + a2[l]) * (1.0f/3.0f);
}

// ---------------- K2: gate ----------------------------------------------------
__global__ void k_gate()
{
    int be = blockIdx.x;
    __shared__ float s[Lv];
    __shared__ float red[256];
    float part = 0.f;
    for (int l = threadIdx.x; l < Lv; l += 256) {
        float v = 0.f;
        #pragma unroll
        for (int h = 0; h < NHv; h++)
            v += g_eatt[((size_t)(be*NHv + h))*Lv + l];
        s[l] = v;
        part += v;
    }
    red[threadIdx.x] = part;
    __syncthreads();
    for (int st = 128; st > 0; st >>= 1) {
        if (threadIdx.x < st) red[threadIdx.x] += red[threadIdx.x + st];
        __syncthreads();
    }
    float inv = 1.0f / red[0];
    for (int l = threadIdx.x; l < Lv; l += 256)
        g_gate[be*Lv + l] = s[l] * inv;
}

// ---------------- K3: e_emb ----------------------------------------------------
__global__ void k_eemb(const float* __restrict__ seq, const int* __restrict__ ms,
                       const int* __restrict__ cs)
{
    int be = blockIdx.x;
    int b  = be / NEv;
    int d  = threadIdx.x;
    __shared__ int   sp[Mv];
    __shared__ int   scs[NCv];
    __shared__ float sg[NCv][CWv];
    if (threadIdx.x < Mv)  sp[threadIdx.x]  = ms[be*Mv + threadIdx.x] + 1;
    if (threadIdx.x < NCv) scs[threadIdx.x] = cs[be*NCv + threadIdx.x];
    __syncthreads();
    if (threadIdx.x < NCv*CWv) {
        int c = threadIdx.x / CWv, w = threadIdx.x % CWv;
        sg[c][w] = g_gate[be*Lv + scs[c] + w];
    }
    __syncthreads();

    float x[Mv + NCv];
    #pragma unroll
    for (int m = 0; m < Mv; m++)
        x[m] = seq[((size_t)b*Lv + sp[m])*Hv + d];
    #pragma unroll
    for (int c = 0; c < NCv; c++) {
        float acc = 0.f;
        int basel = scs[c];
        #pragma unroll
        for (int w = 0; w < CWv; w++)
            acc += sg[c][w] * seq[((size_t)b*Lv + basel + w)*Hv + d];
        x[Mv + c] = acc;
    }
    float mx = x[0];
    #pragma unroll
    for (int i = 1; i < Mv + NCv; i++) mx = fmaxf(mx, x[i]);
    float ssum = 0.f;
    #pragma unroll
    for (int i = 0; i < Mv + NCv; i++) ssum += expf(x[i] - mx);
    g_eemb[be*Hv + d] = mx + logf(ssum);
}

// ---------------- K4: ht (emits split-bf16 directly) ---------------------------
__global__ void k_ht()
{
    int ef = blockIdx.x;
    int b  = blockIdx.y;
    int e = ef / NEv, f = ef % NEv;
    __shared__ float s[Lv];
    __shared__ float red[256];
    const float* pe = g_eatt + (size_t)((b*NEv + e)*NHv)*Lv;
    const float* pf = g_eatt + (size_t)((b*NEv + f)*NHv)*Lv;
    float part = 0.f;
    for (int l = threadIdx.x; l < Lv; l += 256) {
        float v = 0.f;
        #pragma unroll
        for (int h = 0; h < NHv; h++)
            v += pe[h*Lv + l] * pf[h*Lv + l];
        v = fmaxf(v, 0.f);
        s[l] = v;
        part += v;
    }
    red[threadIdx.x] = part;
    __syncthreads();
    for (int st = 128; st > 0; st >>= 1) {
        if (threadIdx.x < st) red[threadIdx.x] += red[threadIdx.x + st];
        __syncthreads();
    }
    float inv = 1.0f / (red[0] + 1e-10f);
    size_t off = ((size_t)b*NPAIR + ef)*Lv;
    for (int l = threadIdx.x; l < Lv; l += 256) {
        __nv_bfloat16 h, lo; split_bf16(s[l]*inv, h, lo);
        g_hth[off + l] = h;
        g_htl[off + l] = lo;
    }
}

// ---------------- fp32 tiled GEMM (for U only) ----------------------------------
template<int TM, int RT, bool BT>
__global__ void __launch_bounds__(256) k_gemm(
    const float* __restrict__ A, const float* __restrict__ Bm, float* __restrict__ C,
    int Mr, int Kd, int lda, int ldb, int ldc,
    long long sA, long long sB, long long sC)
{
    constexpr int APAD = (TM == 128) ? 136 : 20;
    A  += (long long)blockIdx.z * sA;
    Bm += (long long)blockIdx.z * sB;
    C  += (long long)blockIdx.z * sC;

    __shared__ __align__(16) float As[16*APAD];
    __shared__ __align__(16) float Bs[16*68];

    const int tid = threadIdx.x;
    const int tx = tid & 15;
    const int ty = tid >> 4;
    const int row0 = blockIdx.y * TM;
    const int col0 = blockIdx.x * 64;

    const int a_k = tid & 15;
    const int a_r = tid >> 4;

    float acc[RT][4] = {};
    float ra[TM/16], rb[4];

    auto loadA = [&](int k0) {
        #pragma unroll
        for (int t = 0; t < TM/16; t++) {
            int gr = row0 + a_r + t*16;
            ra[t] = (gr < Mr) ? A[(long long)gr*lda + (k0 + a_k)] : 0.f;
        }
    };
    auto loadB = [&](int k0) {
        if (BT) {
            #pragma unroll
            for (int t = 0; t < 4; t++)
                rb[t] = Bm[(long long)(col0 + a_r + t*16)*ldb + (k0 + a_k)];
        } else {
            #pragma unroll
            for (int t = 0; t < 4; t++)
                rb[t] = Bm[(long long)(k0 + (tid>>6) + t*4)*ldb + col0 + (tid&63)];
        }
    };
    auto storeAB = [&]() {
        #pragma unroll
        for (int t = 0; t < TM/16; t++)
            As[a_k*APAD + a_r + t*16] = ra[t];
        if (BT) {
            #pragma unroll
            for (int t = 0; t < 4; t++)
                Bs[a_k*68 + a_r + t*16] = rb[t];
        } else {
            #pragma unroll
            for (int t = 0; t < 4; t++)
                Bs[((tid>>6) + t*4)*68 + (tid&63)] = rb[t];
        }
    };

    loadA(0); loadB(0);
    for (int k0 = 0; k0 < Kd; k0 += 16) {
        storeAB();
        __syncthreads();
        if (k0 + 16 < Kd) { loadA(k0 + 16); loadB(k0 + 16); }
        #pragma unroll
        for (int kk = 0; kk < 16; kk++) {
            float av[RT];
            if constexpr (RT == 8) {
                float4 a0 = *reinterpret_cast<const float4*>(&As[kk*APAD + ty*8]);
                float4 a1 = *reinterpret_cast<const float4*>(&As[kk*APAD + ty*8 + 4]);
                av[0]=a0.x; av[1]=a0.y; av[2]=a0.z; av[3]=a0.w;
                av[4]=a1.x; av[5]=a1.y; av[6]=a1.z; av[7]=a1.w;
            } else {
                av[0] = As[kk*APAD + ty];
            }
            float4 b4 = *reinterpret_cast<const float4*>(&Bs[kk*68 + tx*4]);
            #pragma unroll
            for (int i = 0; i < RT; i++) {
                acc[i][0] += av[i]*b4.x; acc[i][1] += av[i]*b4.y;
                acc[i][2] += av[i]*b4.z; acc[i][3] += av[i]*b4.w;
            }
        }
        __syncthreads();
    }

    #pragma unroll
    for (int i = 0; i < RT; i++) {
        int gr = row0 + ty*RT + i;
        if (gr < Mr) {
            #pragma unroll
            for (int j = 0; j < 4; j++)
                C[(long long)gr*ldc + col0 + tx*4 + j] = acc[i][j];
        }
    }
}

// ---------------- conversions (small weights only) -------------------------------
__global__ void k_wcls_conv(const float* __restrict__ Wcls)
{
    int idx = blockIdx.x*256 + threadIdx.x;
    if (idx >= 128*Hv) return;
    int r = idx / Hv, c = idx % Hv;
    float v = (r < NCLSv) ? Wcls[r*Hv + c] : 0.f;
    __nv_bfloat16 h, l; split_bf16(v, h, l);
    g_wclsh[idx] = h;
    g_wclsl[idx] = l;
}

__global__ void k_whx(const float* __restrict__ Wh, const float* __restrict__ Wt)
{
    int idx = blockIdx.x*256 + threadIdx.x;
    if (idx >= 2*Hv*Hv) return;
    int z = idx / (Hv*Hv);
    int rem = idx - z*Hv*Hv;
    int d = rem / Hv, k = rem % Hv;
    const float* W = z ? Wt : Wh;
    float v = W[(size_t)d*(2*Hv) + Hv + k];
    __nv_bfloat16 h, l; split_bf16(v, h, l);
    g_whxh[idx] = h;
    g_whxl[idx] = l;
}

// ---------------- mma.sync split-bf16 core (ldmatrix edition) --------------------
// pA/pB: uint32 smem addresses of the hi tiles (lo at +TILE_B). Layout: row-major,
// TS(=72) bf16 stride. TS*2 = 144B stride -> conflict-free LDSM (banks 4r mod 32).
__device__ __forceinline__ void compute_core(uint32_t pA, uint32_t pB,
    float acc[4][4][4], int lane, int wm, int wn)
{
    const int la = lane & 15;               // A row offset
    const int ka = (lane >> 4) * 8;         // A col offset
    const int lb = (lane & 7) + ((lane >> 4) & 1) * 8;  // B row offset
    const int kb = ((lane >> 3) & 1) * 8;               // B col offset

    #pragma unroll
    for (int ks = 0; ks < 4; ks++) {
        const int k0 = ks*16;
        uint32_t bh[4][2], bl[4][2];
        #pragma unroll
        for (int p = 0; p < 2; p++) {
            int n0 = wn*32 + p*16;
            uint32_t addr = pB + ((n0 + lb)*TS + k0 + kb)*2;
            ldsm4(bh[2*p][0], bh[2*p][1], bh[2*p+1][0], bh[2*p+1][1], addr);
            ldsm4(bl[2*p][0], bl[2*p][1], bl[2*p+1][0], bl[2*p+1][1], addr + TILE_B);
        }
        #pragma unroll
        for (int mf = 0; mf < 4; mf++) {
            int r0 = wm*64 + mf*16;
            uint32_t addr = pA + ((r0 + la)*TS + k0 + ka)*2;
            uint32_t ah0, ah1, ah2, ah3, al0, al1, al2, al3;
            ldsm4(ah0, ah1, ah2, ah3, addr);
            ldsm4(al0, al1, al2, al3, addr + TILE_B);
            #pragma unroll
            for (int nf = 0; nf < 4; nf++) {
                mma16816(acc[mf][nf], ah0, ah1, ah2, ah3, bh[nf][0], bh[nf][1]);
                mma16816(acc[mf][nf], ah0, ah1, ah2, ah3, bl[nf][0], bl[nf][1]);
                mma16816(acc[mf][nf], al0, al1, al2, al3, bh[nf][0], bh[nf][1]);
            }
        }
    }
}

// ---------------- unified split-bf16 GEMM: C = A @ B^T ----------------------------
template<int BSRC, int OUT>
__global__ __launch_bounds__(256, 1) void k_mma_u(
    const __nv_bfloat16* __restrict__ Ah, const __nv_bfloat16* __restrict__ Al,
    int lda, long long sA,
    const __nv_bfloat16* __restrict__ Bh, const __nv_bfloat16* __restrict__ Bl,
    int ldb, long long sB,
    const float* __restrict__ Wf, int ldw, long long sW,
    __nv_bfloat16* __restrict__ Ch, __nv_bfloat16* __restrict__ Cl, int ldc, long long sC,
    float* __restrict__ Z0, float* __restrict__ Z1,
    const float* __restrict__ U0, const float* __restrict__ U1,
    const float* __restrict__ bias0, const float* __restrict__ bias1,
    int Mr, int niter)
{
    extern __shared__ char smem[];
    const int tid = threadIdx.x, lane = tid & 31, w = tid >> 5;
    const int wm = w >> 2, wn = w & 3;
    const int row0 = blockIdx.y * 128;
    const int n0   = blockIdx.x * 128;

    Ah += (long long)blockIdx.z * sA;
    Al += (long long)blockIdx.z * sA;
    const __nv_bfloat16* Bph = nullptr;
    const __nv_bfloat16* Bpl = nullptr;
    const float* Wfb = nullptr;
    if constexpr (BSRC == 0) {
        Bph = Bh + (long long)blockIdx.z*sB + (size_t)n0*ldb;
        Bpl = Bl + (long long)blockIdx.z*sB + (size_t)n0*ldb;
    } else {
        Wfb = Wf + (long long)blockIdx.z*sW + n0;
    }

    uint32_t sb = smem_u32(smem);

    auto issue = [&](int s, int it) {
        uint32_t st = sb + s*STAGE_B;
        const __nv_bfloat16* ah = Ah + it*64;
        const __nv_bfloat16* al = Al + it*64;
        #pragma unroll
        for (int t = 0; t < 4; t++) {
            int idx = tid + t*256;
            int row = idx >> 3, ch = idx & 7;
            uint32_t off = row*(TS*2) + ch*16;
            int ar = row0 + row; if (ar >= Mr) ar = Mr - 1;
            cpasync16(st +          off, ah + (size_t)ar*lda + ch*8);
            cpasync16(st + TILE_B + off, al + (size_t)ar*lda + ch*8);
        }
        if constexpr (BSRC == 0) {
            const __nv_bfloat16* bh = Bph + it*64;
            const __nv_bfloat16* bl = Bpl + it*64;
            #pragma unroll
            for (int t = 0; t < 4; t++) {
                int idx = tid + t*256;
                int row = idx >> 3, ch = idx & 7;
                uint32_t off = row*(TS*2) + ch*16;
                cpasync16(st + 2*TILE_B + off, bh + (size_t)row*ldb + ch*8);
                cpasync16(st + 3*TILE_B + off, bl + (size_t)row*ldb + ch*8);
            }
        } else {
            const float* wrow = Wfb + (size_t)(it*64)*ldw;
            uint32_t fst = sb + FST_OFF + s*FST_STG;
            #pragma unroll
            for (int t = 0; t < 8; t++) {
                int idx = tid + t*256;
                int row = idx >> 5, ch = idx & 31;
                cpasync16(fst + row*528 + ch*16, wrow + (size_t)row*ldw + ch*4);
            }
        }
        CP_COMMIT();
    };

    auto convertB = [&](int s) {
        const float* f = (const float*)(smem + FST_OFF + s*FST_STG);
        char* bt_ = smem + s*STAGE_B + 2*TILE_B;
        int n  = tid >> 1;
        int kb = (tid & 1) * 32;
        const float* fp = f + n;
        char* ph = bt_ + (n*TS + kb)*2;
        char* pl = ph + TILE_B;
        #pragma unroll
        for (int j = 0; j < 32; j += 2) {
            float v0 = fp[(kb + j)*132];
            float v1 = fp[(kb + j + 1)*132];
            __nv_bfloat16 h0, l0, h1, l1;
            split_bf16(v0, h0, l0); split_bf16(v1, h1, l1);
            *(uint32_t*)(ph + j*2) = pack2(h0, h1);
            *(uint32_t*)(pl + j*2) = pack2(l0, l1);
        }
    };

    float acc[4][4][4] = {};
    issue(0, 0);
    for (int it = 0; it < niter; it++) {
        int s = it & 1;
        if (it + 1 < niter) { issue(s ^ 1, it + 1); CP_WAIT(1); }
        else                { CP_WAIT(0); }
        __syncthreads();
        if constexpr (BSRC == 1) { convertB(s); __syncthreads(); }
        uint32_t base = sb + s*STAGE_B;
        compute_core(base, base + 2*TILE_B, acc, lane, wm, wn);
        __syncthreads();
    }

    if constexpr (OUT == 1) {
        const long long coff = (long long)blockIdx.z * sC;
        #pragma unroll
        for (int mf = 0; mf < 4; mf++) {
            int r = row0 + wm*64 + mf*16 + (lane >> 2);
            #pragma unroll
            for (int nf = 0; nf < 4; nf++) {
                int cb = n0 + wn*32 + nf*8 + (lane & 3)*2;
                __nv_bfloat16 h0, l0, h1, l1;
                if (r < Mr) {
                    split_bf16(acc[mf][nf][0], h0, l0);
                    split_bf16(acc[mf][nf][1], h1, l1);
                    *reinterpret_cast<uint32_t*>(Ch + coff + (long long)r*ldc + cb) = pack2(h0, h1);
                    *reinterpret_cast<uint32_t*>(Cl + coff + (long long)r*ldc + cb) = pack2(l0, l1);
                }
                if (r + 8 < Mr) {
                    split_bf16(acc[mf][nf][2], h0, l0);
                    split_bf16(acc[mf][nf][3], h1, l1);
                    *reinterpret_cast<uint32_t*>(Ch + coff + (long long)(r + 8)*ldc + cb) = pack2(h0, h1);
                    *reinterpret_cast<uint32_t*>(Cl + coff + (long long)(r + 8)*ldc + cb) = pack2(l0, l1);
                }
            }
        }
    } else {   // OUT == 2: Z = tanh(acc + U + bias)
        float* Z        = blockIdx.z ? Z1 : Z0;
        const float* U  = blockIdx.z ? U1 : U0;
        const float* bs = blockIdx.z ? bias1 : bias0;
        #pragma unroll
        for (int mf = 0; mf < 4; mf++) {
            int r = row0 + wm*64 + mf*16 + (lane >> 2);
            #pragma unroll
            for (int nf = 0; nf < 4; nf++) {
                int cb = n0 + wn*32 + nf*8 + (lane & 3)*2;
                float b0 = bs[cb], b1 = bs[cb + 1];
                if (r < Mr) {
                    int u = blockIdx.z == 0 ? (r / NEv) : ((r / NPAIR)*NEv + (r % NEv));
                    Z[(size_t)r*Hv + cb]     = tanhf(acc[mf][nf][0] + U[u*Hv + cb]     + b0);
                    Z[(size_t)r*Hv + cb + 1] = tanhf(acc[mf][nf][1] + U[u*Hv + cb + 1] + b1);
                }
                int r8 = r + 8;
                if (r8 < Mr) {
                    int u = blockIdx.z == 0 ? (r8 / NEv) : ((r8 / NPAIR)*NEv + (r8 % NEv));
                    Z[(size_t)r8*Hv + cb]     = tanhf(acc[mf][nf][2] + U[u*Hv + cb]     + b0);
                    Z[(size_t)r8*Hv + cb + 1] = tanhf(acc[mf][nf][3] + U[u*Hv + cb + 1] + b1);
                }
            }
        }
    }
}

// ---------------- fused logits kernel ---------------------------------------------
__global__ __launch_bounds__(256, 1) void k_logits_f()
{
    extern __shared__ char smem[];
    uint32_t sb = smem_u32(smem);
    float* zhs = (float*)(smem + LZH_OFF);   // [128][65]
    float* zts = (float*)(smem + LZT_OFF);   // [128][66]
    const int tid = threadIdx.x, lane = tid & 31, w = tid >> 5;
    const int wm = w >> 2, wn = w & 3;
    const int row0 = blockIdx.x * 128;
    const int c0   = blockIdx.y * 48;

    auto issueB = [&](int s, int c) {
        uint32_t st = sb + s*LB_STG;
        const __nv_bfloat16* bh = g_wch + (size_t)c*64;
        const __nv_bfloat16* bl = g_wcl + (size_t)c*64;
        #pragma unroll
        for (int t = 0; t < 4; t++) {
            int idx = tid + t*256;
            int row = idx >> 3, ch = idx & 7;
            uint32_t off = row*(TS*2) + ch*16;
            cpasync16(st +          off, bh + (size_t)row*WCN + ch*8);
            cpasync16(st + TILE_B + off, bl + (size_t)row*WCN + ch*8);
        }
        CP_COMMIT();
    };

    float acc[4][4][4] = {};
    issueB(0, c0);
    int kcur = -1;
    for (int it = 0; it < 48; it++) {
        int c = c0 + it, s = it & 1;
        if (it + 1 < 48) { issueB(s ^ 1, c + 1); CP_WAIT(1); }
        else             { CP_WAIT(0); }
        int k = c >> 6;
        if (k != kcur) {
            for (int idx = tid; idx < 8192; idx += 256) {
                int r = idx >> 6, cc = idx & 63;
                zhs[r*65 + cc] = g_zh[(size_t)(row0 + r)*Hv + k*64 + cc];
                zts[r*66 + cc] = g_zt[(size_t)(row0 + r)*Hv + k*64 + cc];
            }
            kcur = k;
            __syncthreads();
        }
        {
            int i  = c & 63;
            int r  = tid >> 1;
            int j0 = (tid & 1) << 5;
            float a = zhs[r*65 + i];
            char* pA = smem + LA_BASE + s*LB_STG + r*(TS*2);
            #pragma unroll
            for (int j = 0; j < 32; j += 2) {
                float v0 = a * zts[r*66 + j0 + j];
                float v1 = a * zts[r*66 + j0 + j + 1];
                __nv_bfloat16 h0, l0, h1, l1;
                split_bf16(v0, h0, l0); split_bf16(v1, h1, l1);
                *(uint32_t*)(pA +          (j0 + j)*2) = pack2(h0, h1);
                *(uint32_t*)(pA + TILE_B + (j0 + j)*2) = pack2(l0, l1);
            }
        }
        __syncthreads();
        compute_core(sb + LA_BASE + s*LB_STG, sb + s*LB_STG, acc, lane, wm, wn);
        __syncthreads();
    }

    float* outk = g_lpart + (size_t)blockIdx.y*ROWS*NCLSv;
    #pragma unroll
    for (int mf = 0; mf < 4; mf++) {
        int r = row0 + wm*64 + mf*16 + (lane >> 2);
        #pragma unroll
        for (int nf = 0; nf < 4; nf++) {
            int cc = wn*32 + nf*8 + (lane & 3)*2;
            if (cc < NCLSv)     outk[(size_t)r*NCLSv + cc]           = acc[mf][nf][0];
            if (cc + 1 < NCLSv) outk[(size_t)r*NCLSv + cc + 1]       = acc[mf][nf][1];
            if (cc < NCLSv)     outk[(size_t)(r + 8)*NCLSv + cc]     = acc[mf][nf][2];
            if (cc + 1 < NCLSv) outk[(size_t)(r + 8)*NCLSv + cc + 1] = acc[mf][nf][3];
        }
    }
}

// ---------------- K8: combine KCH k-partials + bias ----------------------------
__global__ void k_final(const float* __restrict__ bcls, float* __restrict__ out)
{
    int idx = blockIdx.x*256 + threadIdx.x;
    if (idx >= ROWS*NCLSv) return;
    int c = idx % NCLSv;
    float v = bcls[c];
    #pragma unroll
    for (int k = 0; k < KCH; k++)
        v += g_lpart[(size_t)k*ROWS*NCLSv + idx];
    out[idx] = v;
}

// ================================ launch ========================================
extern "C" void kernel_launch(void* const* d_in, const int* in_sizes, int n_in,
                              void* d_out, int out_size)
{
    const float* seq  = (const float*)d_in[0];
    const float* att  = (const float*)d_in[1];
    const int*   ms   = (const int*)  d_in[2];
    const int*   cs   = (const int*)  d_in[3];
    const float* Wh   = (const float*)d_in[4];
    const float* bh   = (const float*)d_in[5];
    const float* Wt   = (const float*)d_in[6];
    const float* bt   = (const float*)d_in[7];
    const float* Wp   = (const float*)d_in[8];
    const float* Wcls = (const float*)d_in[9];
    const float* bcls = (const float*)d_in[10];
    float* out = (float*)d_out;

    float *p_eemb, *p_uh, *p_ut, *p_zh, *p_zt;
    __nv_bfloat16 *p_wclsh, *p_wclsl, *p_wch, *p_wcl;
    __nv_bfloat16 *p_hth, *p_htl, *p_rsh, *p_rsl, *p_whxh, *p_whxl;
    cudaGetSymbolAddress((void**)&p_eemb,  g_eemb);
    cudaGetSymbolAddress((void**)&p_uh,    g_uh);
    cudaGetSymbolAddress((void**)&p_ut,    g_ut);
    cudaGetSymbolAddress((void**)&p_zh,    g_zh);
    cudaGetSymbolAddress((void**)&p_zt,    g_zt);
    cudaGetSymbolAddress((void**)&p_wclsh, g_wclsh);
    cudaGetSymbolAddress((void**)&p_wclsl, g_wclsl);
    cudaGetSymbolAddress((void**)&p_wch,   g_wch);
    cudaGetSymbolAddress((void**)&p_wcl,   g_wcl);
    cudaGetSymbolAddress((void**)&p_hth,   g_hth);
    cudaGetSymbolAddress((void**)&p_htl,   g_htl);
    cudaGetSymbolAddress((void**)&p_rsh,   g_rsh);
    cudaGetSymbolAddress((void**)&p_rsl,   g_rsl);
    cudaGetSymbolAddress((void**)&p_whxh,  g_whxh);
    cudaGetSymbolAddress((void**)&p_whxl,  g_whxl);

    cudaFuncSetAttribute(k_mma_u<1,1>, cudaFuncAttributeMaxDynamicSharedMemorySize, SMEM_T);
    cudaFuncSetAttribute(k_mma_u<0,2>, cudaFuncAttributeMaxDynamicSharedMemorySize, SMEMB);
    cudaFuncSetAttribute(k_logits_f,   cudaFuncAttributeMaxDynamicSharedMemorySize, LSMEM);

    // Aux stream + fork/join events, created once on the (uncaptured) correctness
    // call; reused verbatim inside capture. Work per call is identical.
    static cudaStream_t s_aux = nullptr;
    static cudaEvent_t  e_fork = nullptr, e_join = nullptr;
    if (s_aux == nullptr) {
        cudaStreamCreateWithFlags(&s_aux, cudaStreamNonBlocking);
        cudaEventCreateWithFlags(&e_fork, cudaEventDisableTiming);
        cudaEventCreateWithFlags(&e_join, cudaEventDisableTiming);
    }

    // ---- fork: Wc path on aux stream (independent until k_logits_f) ----
    cudaEventRecord(e_fork, 0);
    cudaStreamWaitEvent(s_aux, e_fork, 0);

    k_wcls_conv<<<(128*Hv + 255)/256, 256, 0, s_aux>>>(Wcls);
    // Wc = Wcls_pad @ Wp  -> split bf16 [128 x 49152]; Wp read fp32 + transposed in-kernel
    k_mma_u<1,1><<<dim3(WCN/128, 1, 1), 256, SMEM_T, s_aux>>>(
        p_wclsh, p_wclsl, Hv, 0,
        nullptr, nullptr, 0, 0,
        Wp, WCN, 0,
        p_wch, p_wcl, WCN, 0,
        nullptr, nullptr, nullptr, nullptr, nullptr, nullptr,
        128, Hv/64);
    cudaEventRecord(e_join, s_aux);

    // ---- main stream: attention path ----
    k_whx<<<(2*Hv*Hv + 255)/256, 256>>>(Wh, Wt);
    k_eatt<<<Bv*NEv*NHv, 256>>>(att, ms);
    k_gate<<<Bv*NEv, 256>>>();
    k_eemb<<<Bv*NEv, Hv>>>(seq, ms, cs);
    k_ht<<<dim3(NPAIR, Bv), 256>>>();

    // rs = ht @ seq^T -> split bf16 (per batch: 576 x 768, K=1024); seq read fp32 direct
    k_mma_u<1,1><<<dim3(Hv/128, 5, Bv), 256, SMEM_T>>>(
        p_hth, p_htl, Lv, (long long)NPAIR*Lv,
        nullptr, nullptr, 0, 0,
        seq, Hv, (long long)Lv*Hv,
        p_rsh, p_rsl, Hv, (long long)NPAIR*Hv,
        nullptr, nullptr, nullptr, nullptr, nullptr, nullptr,
        NPAIR, Lv/64);

    // U = e_emb @ W[:, :H]^T  (fp32, tiny; head/tail via z-stride)
    k_gemm<16,1,true><<<dim3(Hv/64, 3, 2), 256>>>(
        p_eemb, Wh, p_uh, Bv*NEv, Hv, Hv, 2*Hv, Hv,
        0, (long long)(Wt - Wh), (long long)(p_ut - p_uh));

    // zh/zt = tanh(rs @ Whx^T + U + bias)  (head/tail via z)
    k_mma_u<0,2><<<dim3(Hv/128, ROWS/128, 2), 256, SMEMB>>>(
        p_rsh, p_rsl, Hv, 0,
        p_whxh, p_whxl, Hv, (long long)Hv*Hv,
        nullptr, 0, 0,
        nullptr, nullptr, 0, 0,
        p_zh, p_zt, p_uh, p_ut, bh, bt,
        ROWS, Hv/64);

    // ---- join: logits needs Wc ----
    cudaStreamWaitEvent(0, e_join, 0);

    // fused logits (A generated in-kernel, split-K over 16 chunks)
    k_logits_f<<<dim3(ROWS/128, KCH), 256, LSMEM>>>();

    k_final<<<(ROWS*NCLSv + 255)/256, 256>>>(bcls, out);
}